// round 7
// baseline (speedup 1.0000x reference)
#include <cuda_runtime.h>
#include <cuda_bf16.h>
#include <mma.h>
#include <cstdint>
#include <cstddef>

using namespace nvcuda;

// ===================== scratch (no allocations allowed) =====================
#define MAX_EDGES 2000000
#define MAX_NODES 100000
#define SLACK 128

__device__ __align__(128) __nv_bfloat16 g_rpH[(size_t)(MAX_EDGES + SLACK) * 16];
__device__ __align__(128) __nv_bfloat16 g_rpL[(size_t)(MAX_EDGES + SLACK) * 16];
__device__ __align__(128) __nv_bfloat16 g_Xh[(size_t)(MAX_EDGES + SLACK) * 160];
__device__ __align__(128) __nv_bfloat16 g_Xl[(size_t)(MAX_EDGES + SLACK) * 160];
__device__ __align__(128) __nv_bfloat16 g_Yh[(size_t)(MAX_EDGES + SLACK) * 160];
__device__ __align__(128) __nv_bfloat16 g_Yl[(size_t)(MAX_EDGES + SLACK) * 160];
__device__ float g_eprime[(size_t)MAX_NODES * 64];
__device__ __align__(128) __nv_bfloat16 g_wstage[262144];

// ===================== cp.async helpers ======================================
__device__ __forceinline__ uint32_t smem_u32(const void* p) {
    uint32_t a;
    asm("{ .reg .u64 t; cvta.to.shared.u64 t, %1; cvt.u32.u64 %0, t; }" : "=r"(a) : "l"(p));
    return a;
}
__device__ __forceinline__ void cpa16(uint32_t dst, const void* src) {
    asm volatile("cp.async.cg.shared.global [%0], [%1], 16;" :: "r"(dst), "l"(src));
}
#define CP_COMMIT() asm volatile("cp.async.commit_group;" ::: "memory")
#define CP_WAIT1()  asm volatile("cp.async.wait_group 1;" ::: "memory")

// ===================== weight prep: pad + bias-fold + hi/lo split ===========
__global__ void prep_w(const float* __restrict__ W, const float* __restrict__ bias,
                       int din, int dout, int KD, int WSTR, int bias_row,
                       __nv_bfloat16* __restrict__ dst)
{
    int idx = blockIdx.x * blockDim.x + threadIdx.x;
    int tot = KD * WSTR;
    if (idx >= tot) return;
    int k = idx / WSTR, n = idx % WSTR;
    float v = 0.f;
    if (n < dout) {
        if (k < din) v = W[(size_t)k * dout + n];
        else if (k == bias_row) v = bias[n];
    }
    __nv_bfloat16 h = __float2bfloat16(v);
    __nv_bfloat16 l = __float2bfloat16(v - __bfloat162float(h));
    dst[idx] = h;
    dst[tot + idx] = l;
}

// ===================== gather: R'[M,16] bf16 hi/lo (col13 = 1 for bias) =====
__global__ void gather_kernel(const float* __restrict__ x,
                              const float* __restrict__ ofx,
                              const int* __restrict__ src,
                              const int* __restrict__ tgt,
                              const float* __restrict__ t,
                              __nv_bfloat16* __restrict__ oh,
                              __nv_bfloat16* __restrict__ ol, int M)
{
    int e = blockIdx.x * blockDim.x + threadIdx.x;
    if (e >= M) return;
    int s = src[e], g = tgt[e];
    float v[16];
    float4 xs = *(const float4*)(x + (size_t)4 * s);
    float2 os = *(const float2*)(ofx + (size_t)2 * s);
    float4 xt = *(const float4*)(x + (size_t)4 * g);
    float2 ot = *(const float2*)(ofx + (size_t)2 * g);
    v[0]=xs.x; v[1]=xs.y; v[2]=xs.z; v[3]=xs.w; v[4]=os.x; v[5]=os.y;
    v[6]=xt.x; v[7]=xt.y; v[8]=xt.z; v[9]=xt.w; v[10]=ot.x; v[11]=ot.y;
    v[12]=t[0]; v[13]=1.0f; v[14]=0.f; v[15]=0.f;
    uint32_t wh[8], wl[8];
#pragma unroll
    for (int i = 0; i < 8; i++) {
        __nv_bfloat16 h0 = __float2bfloat16(v[2*i]);
        __nv_bfloat16 h1 = __float2bfloat16(v[2*i+1]);
        __nv_bfloat16 l0 = __float2bfloat16(v[2*i]   - __bfloat162float(h0));
        __nv_bfloat16 l1 = __float2bfloat16(v[2*i+1] - __bfloat162float(h1));
        wh[i] = (uint32_t)__bfloat16_as_ushort(h0) | ((uint32_t)__bfloat16_as_ushort(h1) << 16);
        wl[i] = (uint32_t)__bfloat16_as_ushort(l0) | ((uint32_t)__bfloat16_as_ushort(l1) << 16);
    }
    uint4* ph = (uint4*)(oh + (size_t)e * 16);
    uint4* pl = (uint4*)(ol + (size_t)e * 16);
    ph[0] = make_uint4(wh[0], wh[1], wh[2], wh[3]);
    ph[1] = make_uint4(wh[4], wh[5], wh[6], wh[7]);
    pl[0] = make_uint4(wl[0], wl[1], wl[2], wl[3]);
    pl[1] = make_uint4(wl[4], wl[5], wl[6], wl[7]);
}

__global__ void zero_kernel(float* __restrict__ p, int n)
{
    int i = blockIdx.x * blockDim.x + threadIdx.x;
    if (i < n) p[i] = 0.f;
}

// ===================== fused wmma layer ======================================
// B fragments register-resident; A tiles (64 rows) double-buffered via cp.async.
// Per warp: 2 m-sub-tiles interleaved x 3 split-term accumulators = 6
// independent HMMA chains (latency hiding).
// OUTMODE 0: relu -> bf16 hi/lo planes (width ND), col onecol forced to 1.0
// OUTMODE 1: fused segment-sum: atomicAdd cols<50 into ep[tgt[row]*64 + col]
template <int KT, int ND, int WN, int WM, int OUTMODE>
__global__ __launch_bounds__(32 * WN * WM, 1)
void fused_layer(const __nv_bfloat16* __restrict__ inH,
                 const __nv_bfloat16* __restrict__ inL,
                 const __nv_bfloat16* __restrict__ wimg,
                 __nv_bfloat16* __restrict__ outH,
                 __nv_bfloat16* __restrict__ outL,
                 const int* __restrict__ tgt,
                 float* __restrict__ ep,
                 int M, int onecol)
{
    constexpr int THREADS = 32 * WN * WM;
    constexpr int KD = KT * 16;
    constexpr int ASTR = KD + 8;
    constexpr int WSTR = ND + 8;
    constexpr int WPLANE = KD * WSTR;
    constexpr int ABUF_ELE = 2 * 64 * ASTR;
    constexpr int CPR = KD / 8;
    constexpr int NCHUNK = 64 * CPR * 2;

    extern __shared__ unsigned char smem[];
    __nv_bfloat16* Wh = (__nv_bfloat16*)smem;
    __nv_bfloat16* Wl = Wh + WPLANE;
    __nv_bfloat16* A0 = Wl + WPLANE;
    float* scr = (float*)(A0 + 2 * ABUF_ELE);

    const int tid = threadIdx.x;
    const int wid = tid >> 5;
    const int lane = tid & 31;
    const int warp_n = wid % WN;
    const int warp_m = wid / WN;
    const uint32_t a_u32 = smem_u32(A0);

    {   // weights -> smem
        const uint4* s4 = (const uint4*)wimg;
        uint4* d4 = (uint4*)smem;
        for (int i = tid; i < (2 * WPLANE * 2) / 16; i += THREADS) d4[i] = s4[i];
    }
    __syncthreads();

    // hoist B fragments into registers
    wmma::fragment<wmma::matrix_b, 16, 16, 16, __nv_bfloat16, wmma::row_major> bH[KT], bL[KT];
#pragma unroll
    for (int k0 = 0; k0 < KT; k0++) {
        wmma::load_matrix_sync(bH[k0], Wh + (k0 * 16) * WSTR + warp_n * 16, WSTR);
        wmma::load_matrix_sync(bL[k0], Wl + (k0 * 16) * WSTR + warp_n * 16, WSTR);
    }

    const int ntiles = (M + 63) >> 6;
    float* scrw = scr + wid * 256;

    auto stage = [&](int b, int tile) {
        const int row0 = tile << 6;
        const uint32_t abase = a_u32 + b * (ABUF_ELE * 2);
        for (int i = tid; i < NCHUNK; i += THREADS) {
            int plane = i / (64 * CPR);
            int rem = i - plane * (64 * CPR);
            int row = rem / CPR, ch = rem - row * CPR;
            int rsrc = row0 + row; if (rsrc >= M) rsrc = M - 1;
            const __nv_bfloat16* s = (plane ? inL : inH) + (size_t)rsrc * KD + ch * 8;
            cpa16(abase + plane * (64 * ASTR * 2) + (row * ASTR + ch * 8) * 2, s);
        }
        CP_COMMIT();
    };

    int tile = blockIdx.x;
    if (tile < ntiles) stage(0, tile); else CP_COMMIT();
    int buf = 0;

    for (; tile < ntiles; tile += gridDim.x) {
        const int nxt = tile + gridDim.x;
        stage(buf ^ 1, nxt < ntiles ? nxt : tile);
        CP_WAIT1();
        __syncthreads();

        const __nv_bfloat16* Ah = A0 + buf * ABUF_ELE;
        const __nv_bfloat16* Al = Ah + 64 * ASTR;
        const size_t row0 = (size_t)tile << 6;

        // sub-pairs: sp=0 -> subs {0,1}, sp=1 -> subs {2,3}
        for (int sp = warp_m; sp < 2; sp += WM) {
            const int sub0 = sp * 2;
            wmma::fragment<wmma::accumulator, 16, 16, 16, float> aA0, aB0, aC0, aA1, aB1, aC1;
            wmma::fill_fragment(aA0, 0.f); wmma::fill_fragment(aB0, 0.f); wmma::fill_fragment(aC0, 0.f);
            wmma::fill_fragment(aA1, 0.f); wmma::fill_fragment(aB1, 0.f); wmma::fill_fragment(aC1, 0.f);
#pragma unroll
            for (int k0 = 0; k0 < KT; k0++) {
                wmma::fragment<wmma::matrix_a, 16, 16, 16, __nv_bfloat16, wmma::row_major> a0H, a0L, a1H, a1L;
                wmma::load_matrix_sync(a0H, Ah + (sub0 * 16) * ASTR + k0 * 16, ASTR);
                wmma::load_matrix_sync(a0L, Al + (sub0 * 16) * ASTR + k0 * 16, ASTR);
                wmma::load_matrix_sync(a1H, Ah + ((sub0 + 1) * 16) * ASTR + k0 * 16, ASTR);
                wmma::load_matrix_sync(a1L, Al + ((sub0 + 1) * 16) * ASTR + k0 * 16, ASTR);
                wmma::mma_sync(aA0, a0H, bH[k0], aA0);
                wmma::mma_sync(aA1, a1H, bH[k0], aA1);
                wmma::mma_sync(aB0, a0H, bL[k0], aB0);
                wmma::mma_sync(aB1, a1H, bL[k0], aB1);
                wmma::mma_sync(aC0, a0L, bH[k0], aC0);
                wmma::mma_sync(aC1, a1L, bH[k0], aC1);
            }
#pragma unroll
            for (int e = 0; e < aA0.num_elements; e++) {
                aA0.x[e] += aB0.x[e] + aC0.x[e];
                aA1.x[e] += aB1.x[e] + aC1.x[e];
            }

#pragma unroll
            for (int which = 0; which < 2; which++) {
                const int sub = sub0 + which;
                wmma::store_matrix_sync(scrw, which ? aA1 : aA0, 16, wmma::mem_row_major);
                __syncwarp();

                const int r = lane >> 1, c0 = (lane & 1) * 8;
                const float* s = scrw + r * 16 + c0;
                const int gc0 = warp_n * 16 + c0;
                const size_t grow = row0 + sub * 16 + r;
                if (OUTMODE == 0) {
                    uint32_t hh[4], ll[4];
#pragma unroll
                    for (int q = 0; q < 4; q++) {
                        float v0 = fmaxf(s[2*q], 0.f);
                        float v1 = fmaxf(s[2*q+1], 0.f);
                        if (gc0 + 2*q == onecol)     v0 = 1.0f;
                        if (gc0 + 2*q + 1 == onecol) v1 = 1.0f;
                        __nv_bfloat16 h0 = __float2bfloat16(v0);
                        __nv_bfloat16 h1 = __float2bfloat16(v1);
                        __nv_bfloat16 l0 = __float2bfloat16(v0 - __bfloat162float(h0));
                        __nv_bfloat16 l1 = __float2bfloat16(v1 - __bfloat162float(h1));
                        hh[q] = (uint32_t)__bfloat16_as_ushort(h0) | ((uint32_t)__bfloat16_as_ushort(h1) << 16);
                        ll[q] = (uint32_t)__bfloat16_as_ushort(l0) | ((uint32_t)__bfloat16_as_ushort(l1) << 16);
                    }
                    *(uint4*)(outH + grow * ND + gc0) = make_uint4(hh[0], hh[1], hh[2], hh[3]);
                    *(uint4*)(outL + grow * ND + gc0) = make_uint4(ll[0], ll[1], ll[2], ll[3]);
                } else {
                    // fused segment-sum: atomic add real cols into ep[tgt*64+c]
                    if (grow < (size_t)M) {
                        int tg = __ldg(tgt + grow);
                        float* dst = ep + (size_t)tg * 64 + gc0;
#pragma unroll
                        for (int q = 0; q < 8; q++) {
                            if (gc0 + q < 50) atomicAdd(dst + q, s[q]);
                        }
                    }
                }
                __syncwarp();
            }
        }
        __syncthreads();
        buf ^= 1;
    }
}

// ===================== SIMT GEMM (node MLP) =================================
template <int NS>
__global__ __launch_bounds__(256, 2)
void gemm_kernel(const float* __restrict__ A, int lda,
                 const float* __restrict__ W, const float* __restrict__ B,
                 float* __restrict__ C, int ldc,
                 int M, int din, int dout, int relu, int padstore)
{
    constexpr int PN = NS * 32;
    extern __shared__ float sm[];
    float* Ws = sm;
    float* Bs = Ws + ((din + 3) & ~3) * PN;
    const int tid = threadIdx.x;
    const int din4 = (din + 3) & ~3;
    for (int idx = tid; idx < din4 * PN; idx += 256) {
        int k = idx / PN, j = idx - k * PN;
        Ws[idx] = (k < din && j < dout) ? W[(size_t)k * dout + j] : 0.f;
    }
    for (int j = tid; j < PN; j += 256) Bs[j] = (j < dout) ? B[j] : 0.f;
    __syncthreads();
    const int lane = tid & 31;
    const int gwarp = blockIdx.x * 8 + (tid >> 5);
    const int nwarp = gridDim.x * 8;
    for (int sidx = gwarp; sidx < (M + 7) >> 3; sidx += nwarp) {
        const int row0 = sidx << 3;
        const float* ap[8];
#pragma unroll
        for (int r = 0; r < 8; r++) {
            int rr = row0 + r; if (rr > M - 1) rr = M - 1;
            ap[r] = A + (size_t)rr * lda;
        }
        float acc[8][NS];
#pragma unroll
        for (int r = 0; r < 8; r++)
#pragma unroll
            for (int s = 0; s < NS; s++) acc[r][s] = 0.f;
#pragma unroll 2
        for (int k = 0; k < din4; k += 4) {
            float4 a[8];
#pragma unroll
            for (int r = 0; r < 8; r++) a[r] = *(const float4*)(ap[r] + k);
#pragma unroll
            for (int kk = 0; kk < 4; kk++) {
                float wv[NS];
#pragma unroll
                for (int s = 0; s < NS; s++) wv[s] = Ws[(k + kk) * PN + lane + (s << 5)];
#pragma unroll
                for (int r = 0; r < 8; r++) {
                    float av = (kk == 0) ? a[r].x : (kk == 1) ? a[r].y : (kk == 2) ? a[r].z : a[r].w;
#pragma unroll
                    for (int s = 0; s < NS; s++) acc[r][s] = fmaf(av, wv[s], acc[r][s]);
                }
            }
        }
#pragma unroll
        for (int r = 0; r < 8; r++) {
            int row = row0 + r;
            if (row < M) {
#pragma unroll
                for (int s = 0; s < NS; s++) {
                    int j = lane + (s << 5);
                    float v = acc[r][s] + Bs[j];
                    if (relu) v = fmaxf(v, 0.f);
                    if (padstore || j < dout) C[(size_t)row * ldc + j] = v;
                }
            }
        }
    }
}

// ===================== host ==================================================
static inline size_t smbytes(int din, int PN)
{
    int din4 = (din + 3) & ~3;
    return (size_t)(din4 * PN + PN) * sizeof(float);
}
static inline size_t fl_smem(int KT, int ND, int nwarp)
{
    int KD = KT * 16, ASTR = KD + 8, WSTR = ND + 8;
    return (size_t)(2 * KD * WSTR * 2) + (size_t)(2 * 2 * 64 * ASTR * 2) + (size_t)nwarp * 1024;
}

extern "C" void kernel_launch(void* const* d_in, const int* in_sizes, int n_in,
                              void* d_out, int out_size)
{
    const float* t   = (const float*)d_in[0];
    const float* x   = (const float*)d_in[1];
    const float* ofx = (const float*)d_in[2];
    const int* src   = (const int*)d_in[3];
    const int* tgt   = (const int*)d_in[4];
    const float* RW[5] = {(const float*)d_in[5], (const float*)d_in[7], (const float*)d_in[9],
                          (const float*)d_in[11], (const float*)d_in[13]};
    const float* Rb[5] = {(const float*)d_in[6], (const float*)d_in[8], (const float*)d_in[10],
                          (const float*)d_in[12], (const float*)d_in[14]};
    const float* OW0 = (const float*)d_in[15];
    const float* Ob0 = (const float*)d_in[16];
    const float* OW1 = (const float*)d_in[17];
    const float* Ob1 = (const float*)d_in[18];
    float* out = (float*)d_out;

    const int M = in_sizes[3];
    const int N = in_sizes[1] / 4;

    __nv_bfloat16 *rpH, *rpL, *Xh, *Xl, *Yh, *Yl, *wst;
    float* ep;
    cudaGetSymbolAddress((void**)&rpH, g_rpH);
    cudaGetSymbolAddress((void**)&rpL, g_rpL);
    cudaGetSymbolAddress((void**)&Xh,  g_Xh);
    cudaGetSymbolAddress((void**)&Xl,  g_Xl);
    cudaGetSymbolAddress((void**)&Yh,  g_Yh);
    cudaGetSymbolAddress((void**)&Yl,  g_Yl);
    cudaGetSymbolAddress((void**)&ep,  g_eprime);
    cudaGetSymbolAddress((void**)&wst, g_wstage);

    int nsm = 148;
    cudaDeviceGetAttribute(&nsm, cudaDevAttrMultiProcessorCount, 0);

    // ---- weight prep: images [KD][WSTR] hi then lo ---------------------------
    const size_t woff[5] = {0, 5376, 5376 + 53760, 5376 + 2*53760, 5376 + 3*53760};
    const int wdin[5]  = {13, 150, 150, 150, 150};
    const int wdout[5] = {150, 150, 150, 150, 50};
    const int wKD[5]   = {16, 160, 160, 160, 160};
    const int wWSTR[5] = {168, 168, 168, 168, 72};
    const int wbrow[5] = {13, 150, 150, 150, 150};
    for (int i = 0; i < 5; i++) {
        int tot = wKD[i] * wWSTR[i];
        prep_w<<<(tot + 255) / 256, 256>>>(RW[i], Rb[i], wdin[i], wdout[i],
                                           wKD[i], wWSTR[i], wbrow[i], wst + woff[i]);
    }

    zero_kernel<<<(N * 64 + 255) / 256, 256>>>(ep, N * 64);
    gather_kernel<<<(M + 255) / 256, 256>>>(x, ofx, src, tgt, t, rpH, rpL, M);

    const size_t sm0 = fl_smem(1, 160, 10);
    const size_t sm1 = fl_smem(10, 160, 10);
    const size_t sm4 = fl_smem(10, 64, 8);
    cudaFuncSetAttribute(fused_layer<1, 160, 10, 1, 0>,  cudaFuncAttributeMaxDynamicSharedMemorySize, (int)sm0);
    cudaFuncSetAttribute(fused_layer<10, 160, 10, 1, 0>, cudaFuncAttributeMaxDynamicSharedMemorySize, (int)sm1);
    cudaFuncSetAttribute(fused_layer<10, 64, 4, 2, 1>,   cudaFuncAttributeMaxDynamicSharedMemorySize, (int)sm4);

    // ---- edge MLP -------------------------------------------------------------
    fused_layer<1, 160, 10, 1, 0> <<<nsm, 320, sm0>>>(rpH, rpL, wst + woff[0], Xh, Xl, nullptr, nullptr, M, 150);
    fused_layer<10, 160, 10, 1, 0><<<nsm, 320, sm1>>>(Xh, Xl, wst + woff[1], Yh, Yl, nullptr, nullptr, M, 150);
    fused_layer<10, 160, 10, 1, 0><<<nsm, 320, sm1>>>(Yh, Yl, wst + woff[2], Xh, Xl, nullptr, nullptr, M, 150);
    fused_layer<10, 160, 10, 1, 0><<<nsm, 320, sm1>>>(Xh, Xl, wst + woff[3], Yh, Yl, nullptr, nullptr, M, 150);
    // L4 with fused segment-sum (atomics straight into ep)
    fused_layer<10, 64, 4, 2, 1>  <<<nsm, 256, sm4>>>(Yh, Yl, wst + woff[4], nullptr, nullptr, tgt, ep, M, -1);

    // ---- node MLP ----------------------------------------------------------------
    cudaFuncSetAttribute(gemm_kernel<4>, cudaFuncAttributeMaxDynamicSharedMemorySize, 112 * 1024);
    cudaFuncSetAttribute(gemm_kernel<1>, cudaFuncAttributeMaxDynamicSharedMemorySize, 112 * 1024);
    float* nb = (float*)rpH;   // reuse
    gemm_kernel<4><<<2 * nsm, 256, smbytes(50, 128)>>>(ep, 64, OW0, Ob0, nb, 128, N, 50, 100, 1, 1);
    gemm_kernel<1><<<2 * nsm, 256, smbytes(100, 32)>>>(nb, 128, OW1, Ob1, out, 4, N, 100, 4, 0, 0);
}

// round 8
// speedup vs baseline: 1.0061x; 1.0061x over previous
#include <cuda_runtime.h>
#include <cuda_bf16.h>
#include <mma.h>
#include <cstdint>
#include <cstddef>

using namespace nvcuda;

// ===================== scratch (no allocations allowed) =====================
#define MAX_EDGES 2000000
#define MAX_NODES 100000
#define SLACK 128

__device__ __align__(128) __nv_bfloat16 g_rpH[(size_t)(MAX_EDGES + SLACK) * 16];
__device__ __align__(128) __nv_bfloat16 g_rpL[(size_t)(MAX_EDGES + SLACK) * 16];
__device__ __align__(128) __nv_bfloat16 g_Xh[(size_t)(MAX_EDGES + SLACK) * 160];
__device__ __align__(128) __nv_bfloat16 g_Xl[(size_t)(MAX_EDGES + SLACK) * 160];
__device__ __align__(128) __nv_bfloat16 g_Yh[(size_t)(MAX_EDGES + SLACK) * 160];
__device__ __align__(128) __nv_bfloat16 g_Yl[(size_t)(MAX_EDGES + SLACK) * 160];
__device__ float g_eprime[(size_t)MAX_NODES * 64];
__device__ __align__(128) __nv_bfloat16 g_wstage[262144];

// ===================== cp.async helpers ======================================
__device__ __forceinline__ uint32_t smem_u32(const void* p) {
    uint32_t a;
    asm("{ .reg .u64 t; cvta.to.shared.u64 t, %1; cvt.u32.u64 %0, t; }" : "=r"(a) : "l"(p));
    return a;
}
__device__ __forceinline__ void cpa16(uint32_t dst, const void* src) {
    asm volatile("cp.async.cg.shared.global [%0], [%1], 16;" :: "r"(dst), "l"(src));
}
#define CP_COMMIT() asm volatile("cp.async.commit_group;" ::: "memory")
#define CP_WAIT1()  asm volatile("cp.async.wait_group 1;" ::: "memory")

// ===================== merged weight prep ====================================
struct PrepCfg {
    const float* W;
    const float* b;
    int din, dout, KD, WSTR, brow;
    int off;          // element offset into g_wstage
};
struct PrepPack { PrepCfg c[5]; };

__global__ void prep_all(PrepPack p, __nv_bfloat16* __restrict__ wst, int total)
{
    int idx = blockIdx.x * blockDim.x + threadIdx.x;
    if (idx >= total) return;
#pragma unroll
    for (int L = 0; L < 5; L++) {
        int tot = p.c[L].KD * p.c[L].WSTR;
        if (idx < tot) {
            int k = idx / p.c[L].WSTR, n = idx - k * p.c[L].WSTR;
            float v = 0.f;
            if (n < p.c[L].dout) {
                if (k < p.c[L].din) v = p.c[L].W[(size_t)k * p.c[L].dout + n];
                else if (k == p.c[L].brow) v = p.c[L].b[n];
            }
            __nv_bfloat16 h = __float2bfloat16(v);
            __nv_bfloat16 l = __float2bfloat16(v - __bfloat162float(h));
            wst[p.c[L].off + idx] = h;
            wst[p.c[L].off + tot + idx] = l;
            return;
        }
        idx -= tot;
    }
}

// ===================== gather: R'[M,16] bf16 hi/lo (col13 = 1 for bias) =====
__global__ void gather_kernel(const float* __restrict__ x,
                              const float* __restrict__ ofx,
                              const int* __restrict__ src,
                              const int* __restrict__ tgt,
                              const float* __restrict__ t,
                              __nv_bfloat16* __restrict__ oh,
                              __nv_bfloat16* __restrict__ ol, int M)
{
    int e = blockIdx.x * blockDim.x + threadIdx.x;
    if (e >= M) return;
    int s = src[e], g = tgt[e];
    float v[16];
    float4 xs = *(const float4*)(x + (size_t)4 * s);
    float2 os = *(const float2*)(ofx + (size_t)2 * s);
    float4 xt = *(const float4*)(x + (size_t)4 * g);
    float2 ot = *(const float2*)(ofx + (size_t)2 * g);
    v[0]=xs.x; v[1]=xs.y; v[2]=xs.z; v[3]=xs.w; v[4]=os.x; v[5]=os.y;
    v[6]=xt.x; v[7]=xt.y; v[8]=xt.z; v[9]=xt.w; v[10]=ot.x; v[11]=ot.y;
    v[12]=t[0]; v[13]=1.0f; v[14]=0.f; v[15]=0.f;
    uint32_t wh[8], wl[8];
#pragma unroll
    for (int i = 0; i < 8; i++) {
        __nv_bfloat16 h0 = __float2bfloat16(v[2*i]);
        __nv_bfloat16 h1 = __float2bfloat16(v[2*i+1]);
        __nv_bfloat16 l0 = __float2bfloat16(v[2*i]   - __bfloat162float(h0));
        __nv_bfloat16 l1 = __float2bfloat16(v[2*i+1] - __bfloat162float(h1));
        wh[i] = (uint32_t)__bfloat16_as_ushort(h0) | ((uint32_t)__bfloat16_as_ushort(h1) << 16);
        wl[i] = (uint32_t)__bfloat16_as_ushort(l0) | ((uint32_t)__bfloat16_as_ushort(l1) << 16);
    }
    uint4* ph = (uint4*)(oh + (size_t)e * 16);
    uint4* pl = (uint4*)(ol + (size_t)e * 16);
    ph[0] = make_uint4(wh[0], wh[1], wh[2], wh[3]);
    ph[1] = make_uint4(wh[4], wh[5], wh[6], wh[7]);
    pl[0] = make_uint4(wl[0], wl[1], wl[2], wl[3]);
    pl[1] = make_uint4(wl[4], wl[5], wl[6], wl[7]);
}

__global__ void zero_kernel(float* __restrict__ p, int n)
{
    int i = blockIdx.x * blockDim.x + threadIdx.x;
    if (i < n) p[i] = 0.f;
}

// ===================== fused wmma layer ======================================
// B fragments register-resident; A tiles (64 rows) double-buffered via cp.async.
// 3 term-accumulators per sub (independent HMMA chains), summed at the end.
// OUTMODE 0: relu -> bf16 hi/lo planes (width ND), col onecol forced to 1.0
// OUTMODE 1: fused segment-sum: atomicAdd cols<50 into ep[tgt[row]*64 + col]
template <int KT, int ND, int WN, int WM, int OUTMODE>
__global__ __launch_bounds__(32 * WN * WM, 1)
void fused_layer(const __nv_bfloat16* __restrict__ inH,
                 const __nv_bfloat16* __restrict__ inL,
                 const __nv_bfloat16* __restrict__ wimg,
                 __nv_bfloat16* __restrict__ outH,
                 __nv_bfloat16* __restrict__ outL,
                 const int* __restrict__ tgt,
                 float* __restrict__ ep,
                 int M, int onecol)
{
    constexpr int THREADS = 32 * WN * WM;
    constexpr int KD = KT * 16;
    constexpr int ASTR = KD + 8;
    constexpr int WSTR = ND + 8;
    constexpr int WPLANE = KD * WSTR;
    constexpr int ABUF_ELE = 2 * 64 * ASTR;
    constexpr int CPR = KD / 8;
    constexpr int NCHUNK = 64 * CPR * 2;

    extern __shared__ unsigned char smem[];
    __nv_bfloat16* Wh = (__nv_bfloat16*)smem;
    __nv_bfloat16* Wl = Wh + WPLANE;
    __nv_bfloat16* A0 = Wl + WPLANE;
    float* scr = (float*)(A0 + 2 * ABUF_ELE);

    const int tid = threadIdx.x;
    const int wid = tid >> 5;
    const int lane = tid & 31;
    const int warp_n = wid % WN;
    const int warp_m = wid / WN;
    const uint32_t a_u32 = smem_u32(A0);

    {   // weights -> smem
        const uint4* s4 = (const uint4*)wimg;
        uint4* d4 = (uint4*)smem;
        for (int i = tid; i < (2 * WPLANE * 2) / 16; i += THREADS) d4[i] = s4[i];
    }
    __syncthreads();

    // hoist B fragments into registers
    wmma::fragment<wmma::matrix_b, 16, 16, 16, __nv_bfloat16, wmma::row_major> bH[KT], bL[KT];
#pragma unroll
    for (int k0 = 0; k0 < KT; k0++) {
        wmma::load_matrix_sync(bH[k0], Wh + (k0 * 16) * WSTR + warp_n * 16, WSTR);
        wmma::load_matrix_sync(bL[k0], Wl + (k0 * 16) * WSTR + warp_n * 16, WSTR);
    }

    const int ntiles = (M + 63) >> 6;
    float* scrw = scr + wid * 256;

    auto stage = [&](int b, int tile) {
        const int row0 = tile << 6;
        const uint32_t abase = a_u32 + b * (ABUF_ELE * 2);
        for (int i = tid; i < NCHUNK; i += THREADS) {
            int plane = i / (64 * CPR);
            int rem = i - plane * (64 * CPR);
            int row = rem / CPR, ch = rem - row * CPR;
            int rsrc = row0 + row; if (rsrc >= M) rsrc = M - 1;
            const __nv_bfloat16* s = (plane ? inL : inH) + (size_t)rsrc * KD + ch * 8;
            cpa16(abase + plane * (64 * ASTR * 2) + (row * ASTR + ch * 8) * 2, s);
        }
        CP_COMMIT();
    };

    int tile = blockIdx.x;
    if (tile < ntiles) stage(0, tile); else CP_COMMIT();
    int buf = 0;

    for (; tile < ntiles; tile += gridDim.x) {
        const int nxt = tile + gridDim.x;
        stage(buf ^ 1, nxt < ntiles ? nxt : tile);
        CP_WAIT1();
        __syncthreads();

        const __nv_bfloat16* Ah = A0 + buf * ABUF_ELE;
        const __nv_bfloat16* Al = Ah + 64 * ASTR;
        const size_t row0 = (size_t)tile << 6;

        for (int sub = warp_m; sub < 4; sub += WM) {
            wmma::fragment<wmma::accumulator, 16, 16, 16, float> acc0, acc1, acc2;
            wmma::fill_fragment(acc0, 0.f);
            wmma::fill_fragment(acc1, 0.f);
            wmma::fill_fragment(acc2, 0.f);
#pragma unroll
            for (int k0 = 0; k0 < KT; k0++) {
                wmma::fragment<wmma::matrix_a, 16, 16, 16, __nv_bfloat16, wmma::row_major> aH, aL;
                wmma::load_matrix_sync(aH, Ah + (sub * 16) * ASTR + k0 * 16, ASTR);
                wmma::load_matrix_sync(aL, Al + (sub * 16) * ASTR + k0 * 16, ASTR);
                wmma::mma_sync(acc0, aH, bH[k0], acc0);
                wmma::mma_sync(acc1, aH, bL[k0], acc1);
                wmma::mma_sync(acc2, aL, bH[k0], acc2);
            }
#pragma unroll
            for (int e = 0; e < acc0.num_elements; e++)
                acc0.x[e] += acc1.x[e] + acc2.x[e];

            wmma::store_matrix_sync(scrw, acc0, 16, wmma::mem_row_major);
            __syncwarp();

            const int r = lane >> 1, c0 = (lane & 1) * 8;
            const float* s = scrw + r * 16 + c0;
            const int gc0 = warp_n * 16 + c0;
            const size_t grow = row0 + sub * 16 + r;
            if (OUTMODE == 0) {
                uint32_t hh[4], ll[4];
#pragma unroll
                for (int q = 0; q < 4; q++) {
                    float v0 = fmaxf(s[2*q], 0.f);
                    float v1 = fmaxf(s[2*q+1], 0.f);
                    if (gc0 + 2*q == onecol)     v0 = 1.0f;
                    if (gc0 + 2*q + 1 == onecol) v1 = 1.0f;
                    __nv_bfloat16 h0 = __float2bfloat16(v0);
                    __nv_bfloat16 h1 = __float2bfloat16(v1);
                    __nv_bfloat16 l0 = __float2bfloat16(v0 - __bfloat162float(h0));
                    __nv_bfloat16 l1 = __float2bfloat16(v1 - __bfloat162float(h1));
                    hh[q] = (uint32_t)__bfloat16_as_ushort(h0) | ((uint32_t)__bfloat16_as_ushort(h1) << 16);
                    ll[q] = (uint32_t)__bfloat16_as_ushort(l0) | ((uint32_t)__bfloat16_as_ushort(l1) << 16);
                }
                *(uint4*)(outH + grow * ND + gc0) = make_uint4(hh[0], hh[1], hh[2], hh[3]);
                *(uint4*)(outL + grow * ND + gc0) = make_uint4(ll[0], ll[1], ll[2], ll[3]);
            } else {
                if (grow < (size_t)M) {
                    int tg = __ldg(tgt + grow);
                    float* dst = ep + (size_t)tg * 64 + gc0;
#pragma unroll
                    for (int q = 0; q < 8; q++) {
                        if (gc0 + q < 50) atomicAdd(dst + q, s[q]);
                    }
                }
            }
            __syncwarp();
        }
        __syncthreads();
        buf ^= 1;
    }
}

// ===================== SIMT GEMM (node MLP) =================================
template <int NS>
__global__ __launch_bounds__(256, 2)
void gemm_kernel(const float* __restrict__ A, int lda,
                 const float* __restrict__ W, const float* __restrict__ B,
                 float* __restrict__ C, int ldc,
                 int M, int din, int dout, int relu, int padstore)
{
    constexpr int PN = NS * 32;
    extern __shared__ float sm[];
    float* Ws = sm;
    float* Bs = Ws + ((din + 3) & ~3) * PN;
    const int tid = threadIdx.x;
    const int din4 = (din + 3) & ~3;
    for (int idx = tid; idx < din4 * PN; idx += 256) {
        int k = idx / PN, j = idx - k * PN;
        Ws[idx] = (k < din && j < dout) ? W[(size_t)k * dout + j] : 0.f;
    }
    for (int j = tid; j < PN; j += 256) Bs[j] = (j < dout) ? B[j] : 0.f;
    __syncthreads();
    const int lane = tid & 31;
    const int gwarp = blockIdx.x * 8 + (tid >> 5);
    const int nwarp = gridDim.x * 8;
    for (int sidx = gwarp; sidx < (M + 7) >> 3; sidx += nwarp) {
        const int row0 = sidx << 3;
        const float* ap[8];
#pragma unroll
        for (int r = 0; r < 8; r++) {
            int rr = row0 + r; if (rr > M - 1) rr = M - 1;
            ap[r] = A + (size_t)rr * lda;
        }
        float acc[8][NS];
#pragma unroll
        for (int r = 0; r < 8; r++)
#pragma unroll
            for (int s = 0; s < NS; s++) acc[r][s] = 0.f;
#pragma unroll 2
        for (int k = 0; k < din4; k += 4) {
            float4 a[8];
#pragma unroll
            for (int r = 0; r < 8; r++) a[r] = *(const float4*)(ap[r] + k);
#pragma unroll
            for (int kk = 0; kk < 4; kk++) {
                float wv[NS];
#pragma unroll
                for (int s = 0; s < NS; s++) wv[s] = Ws[(k + kk) * PN + lane + (s << 5)];
#pragma unroll
                for (int r = 0; r < 8; r++) {
                    float av = (kk == 0) ? a[r].x : (kk == 1) ? a[r].y : (kk == 2) ? a[r].z : a[r].w;
#pragma unroll
                    for (int s = 0; s < NS; s++) acc[r][s] = fmaf(av, wv[s], acc[r][s]);
                }
            }
        }
#pragma unroll
        for (int r = 0; r < 8; r++) {
            int row = row0 + r;
            if (row < M) {
#pragma unroll
                for (int s = 0; s < NS; s++) {
                    int j = lane + (s << 5);
                    float v = acc[r][s] + Bs[j];
                    if (relu) v = fmaxf(v, 0.f);
                    if (padstore || j < dout) C[(size_t)row * ldc + j] = v;
                }
            }
        }
    }
}

// ===================== host ==================================================
static inline size_t smbytes(int din, int PN)
{
    int din4 = (din + 3) & ~3;
    return (size_t)(din4 * PN + PN) * sizeof(float);
}
static inline size_t fl_smem(int KT, int ND, int nwarp)
{
    int KD = KT * 16, ASTR = KD + 8, WSTR = ND + 8;
    return (size_t)(2 * KD * WSTR * 2) + (size_t)(2 * 2 * 64 * ASTR * 2) + (size_t)nwarp * 1024;
}

extern "C" void kernel_launch(void* const* d_in, const int* in_sizes, int n_in,
                              void* d_out, int out_size)
{
    const float* t   = (const float*)d_in[0];
    const float* x   = (const float*)d_in[1];
    const float* ofx = (const float*)d_in[2];
    const int* src   = (const int*)d_in[3];
    const int* tgt   = (const int*)d_in[4];
    const float* RW[5] = {(const float*)d_in[5], (const float*)d_in[7], (const float*)d_in[9],
                          (const float*)d_in[11], (const float*)d_in[13]};
    const float* Rb[5] = {(const float*)d_in[6], (const float*)d_in[8], (const float*)d_in[10],
                          (const float*)d_in[12], (const float*)d_in[14]};
    const float* OW0 = (const float*)d_in[15];
    const float* Ob0 = (const float*)d_in[16];
    const float* OW1 = (const float*)d_in[17];
    const float* Ob1 = (const float*)d_in[18];
    float* out = (float*)d_out;

    const int M = in_sizes[3];
    const int N = in_sizes[1] / 4;

    __nv_bfloat16 *rpH, *rpL, *Xh, *Xl, *Yh, *Yl, *wst;
    float* ep;
    cudaGetSymbolAddress((void**)&rpH, g_rpH);
    cudaGetSymbolAddress((void**)&rpL, g_rpL);
    cudaGetSymbolAddress((void**)&Xh,  g_Xh);
    cudaGetSymbolAddress((void**)&Xl,  g_Xl);
    cudaGetSymbolAddress((void**)&Yh,  g_Yh);
    cudaGetSymbolAddress((void**)&Yl,  g_Yl);
    cudaGetSymbolAddress((void**)&ep,  g_eprime);
    cudaGetSymbolAddress((void**)&wst, g_wstage);

    int nsm = 148;
    cudaDeviceGetAttribute(&nsm, cudaDevAttrMultiProcessorCount, 0);

    // ---- merged weight prep --------------------------------------------------
    const int woff[5] = {0, 5376, 5376 + 53760, 5376 + 2*53760, 5376 + 3*53760};
    const int wdin[5]  = {13, 150, 150, 150, 150};
    const int wdout[5] = {150, 150, 150, 150, 50};
    const int wKD[5]   = {16, 160, 160, 160, 160};
    const int wWSTR[5] = {168, 168, 168, 168, 72};
    const int wbrow[5] = {13, 150, 150, 150, 150};
    PrepPack pk;
    int ptotal = 0;
    for (int i = 0; i < 5; i++) {
        pk.c[i] = PrepCfg{RW[i], Rb[i], wdin[i], wdout[i], wKD[i], wWSTR[i], wbrow[i], woff[i]};
        ptotal += wKD[i] * wWSTR[i];
    }
    prep_all<<<(ptotal + 255) / 256, 256>>>(pk, wst, ptotal);

    zero_kernel<<<(N * 64 + 255) / 256, 256>>>(ep, N * 64);
    gather_kernel<<<(M + 255) / 256, 256>>>(x, ofx, src, tgt, t, rpH, rpL, M);

    const size_t sm0 = fl_smem(1, 160, 10);
    const size_t sm1 = fl_smem(10, 160, 10);
    const size_t sm4 = fl_smem(10, 64, 8);
    cudaFuncSetAttribute(fused_layer<1, 160, 10, 1, 0>,  cudaFuncAttributeMaxDynamicSharedMemorySize, (int)sm0);
    cudaFuncSetAttribute(fused_layer<10, 160, 10, 1, 0>, cudaFuncAttributeMaxDynamicSharedMemorySize, (int)sm1);
    cudaFuncSetAttribute(fused_layer<10, 64, 4, 2, 1>,   cudaFuncAttributeMaxDynamicSharedMemorySize, (int)sm4);

    // ---- edge MLP (launch idx: L0=3, L1=4, L2=5 <- ncu -s 5 captures L2) ------
    fused_layer<1, 160, 10, 1, 0> <<<nsm, 320, sm0>>>(rpH, rpL, wst + woff[0], Xh, Xl, nullptr, nullptr, M, 150);
    fused_layer<10, 160, 10, 1, 0><<<nsm, 320, sm1>>>(Xh, Xl, wst + woff[1], Yh, Yl, nullptr, nullptr, M, 150);
    fused_layer<10, 160, 10, 1, 0><<<nsm, 320, sm1>>>(Yh, Yl, wst + woff[2], Xh, Xl, nullptr, nullptr, M, 150);
    fused_layer<10, 160, 10, 1, 0><<<nsm, 320, sm1>>>(Xh, Xl, wst + woff[3], Yh, Yl, nullptr, nullptr, M, 150);
    // L4 with fused segment-sum (atomics straight into ep)
    fused_layer<10, 64, 4, 2, 1>  <<<nsm, 256, sm4>>>(Yh, Yl, wst + woff[4], nullptr, nullptr, tgt, ep, M, -1);

    // ---- node MLP ----------------------------------------------------------------
    cudaFuncSetAttribute(gemm_kernel<4>, cudaFuncAttributeMaxDynamicSharedMemorySize, 112 * 1024);
    cudaFuncSetAttribute(gemm_kernel<1>, cudaFuncAttributeMaxDynamicSharedMemorySize, 112 * 1024);
    float* nb = (float*)rpH;   // reuse
    gemm_kernel<4><<<2 * nsm, 256, smbytes(50, 128)>>>(ep, 64, OW0, Ob0, nb, 128, N, 50, 100, 1, 1);
    gemm_kernel<1><<<2 * nsm, 256, smbytes(100, 32)>>>(nb, 128, OW1, Ob1, out, 4, N, 100, 4, 0, 0);
}

// round 9
// speedup vs baseline: 1.4352x; 1.4265x over previous
#include <cuda_runtime.h>
#include <cuda_bf16.h>
#include <cstdint>
#include <cstddef>

// ===================== scratch (no allocations allowed) =====================
#define MAX_EDGES 2000000
#define MAX_NODES 100000
#define SLACK 128

__device__ __align__(128) __nv_bfloat16 g_rpH[(size_t)(MAX_EDGES + SLACK) * 16];
__device__ __align__(128) __nv_bfloat16 g_rpL[(size_t)(MAX_EDGES + SLACK) * 16];
__device__ __align__(128) __nv_bfloat16 g_Xh[(size_t)(MAX_EDGES + SLACK) * 160];
__device__ __align__(128) __nv_bfloat16 g_Xl[(size_t)(MAX_EDGES + SLACK) * 160];
__device__ __align__(128) __nv_bfloat16 g_Yh[(size_t)(MAX_EDGES + SLACK) * 160];
__device__ __align__(128) __nv_bfloat16 g_Yl[(size_t)(MAX_EDGES + SLACK) * 160];
__device__ float g_eprime[(size_t)MAX_NODES * 64];
__device__ __align__(128) __nv_bfloat16 g_wstage[262144];

// ===================== low-level helpers =====================================
__device__ __forceinline__ uint32_t smem_u32(const void* p) {
    uint32_t a;
    asm("{ .reg .u64 t; cvta.to.shared.u64 t, %1; cvt.u32.u64 %0, t; }" : "=r"(a) : "l"(p));
    return a;
}
__device__ __forceinline__ void cpa16(uint32_t dst, const void* src) {
    asm volatile("cp.async.cg.shared.global [%0], [%1], 16;" :: "r"(dst), "l"(src));
}
#define CP_COMMIT() asm volatile("cp.async.commit_group;" ::: "memory")
#define CP_WAIT0()  asm volatile("cp.async.wait_group 0;" ::: "memory")
#define CP_WAIT1()  asm volatile("cp.async.wait_group 1;" ::: "memory")

__device__ __forceinline__ void mma_bf16(float* c, const uint32_t* a, uint32_t b0, uint32_t b1) {
    asm volatile(
        "mma.sync.aligned.m16n8k16.row.col.f32.bf16.bf16.f32 "
        "{%0,%1,%2,%3}, {%4,%5,%6,%7}, {%8,%9}, {%0,%1,%2,%3};"
        : "+f"(c[0]), "+f"(c[1]), "+f"(c[2]), "+f"(c[3])
        : "r"(a[0]), "r"(a[1]), "r"(a[2]), "r"(a[3]), "r"(b0), "r"(b1));
}
__device__ __forceinline__ void ldmx4(uint32_t* r, uint32_t a) {
    asm volatile("ldmatrix.sync.aligned.m8n8.x4.shared.b16 {%0,%1,%2,%3}, [%4];"
        : "=r"(r[0]), "=r"(r[1]), "=r"(r[2]), "=r"(r[3]) : "r"(a) : "memory");
}
__device__ __forceinline__ void split2(float v0, float v1, uint32_t& hi, uint32_t& lo) {
    __nv_bfloat16 h0 = __float2bfloat16(v0), h1 = __float2bfloat16(v1);
    __nv_bfloat16 l0 = __float2bfloat16(v0 - __bfloat162float(h0));
    __nv_bfloat16 l1 = __float2bfloat16(v1 - __bfloat162float(h1));
    hi = (uint32_t)__bfloat16_as_ushort(h0) | ((uint32_t)__bfloat16_as_ushort(h1) << 16);
    lo = (uint32_t)__bfloat16_as_ushort(l0) | ((uint32_t)__bfloat16_as_ushort(l1) << 16);
}

// ===================== merged weight prep ====================================
struct PrepCfg {
    const float* W; const float* b;
    int din, dout, KD, WSTR, brow, off;
};
struct PrepPack { PrepCfg c[5]; };

__global__ void prep_all(PrepPack p, __nv_bfloat16* __restrict__ wst, int total)
{
    int idx = blockIdx.x * blockDim.x + threadIdx.x;
    if (idx >= total) return;
#pragma unroll
    for (int L = 0; L < 5; L++) {
        int tot = p.c[L].KD * p.c[L].WSTR;
        if (idx < tot) {
            int k = idx / p.c[L].WSTR, n = idx - k * p.c[L].WSTR;
            float v = 0.f;
            if (n < p.c[L].dout) {
                if (k < p.c[L].din) v = p.c[L].W[(size_t)k * p.c[L].dout + n];
                else if (k == p.c[L].brow) v = p.c[L].b[n];
            }
            __nv_bfloat16 h = __float2bfloat16(v);
            __nv_bfloat16 l = __float2bfloat16(v - __bfloat162float(h));
            wst[p.c[L].off + idx] = h;
            wst[p.c[L].off + tot + idx] = l;
            return;
        }
        idx -= tot;
    }
}

// ===================== gather ================================================
__global__ void gather_kernel(const float* __restrict__ x,
                              const float* __restrict__ ofx,
                              const int* __restrict__ src,
                              const int* __restrict__ tgt,
                              const float* __restrict__ t,
                              __nv_bfloat16* __restrict__ oh,
                              __nv_bfloat16* __restrict__ ol, int M)
{
    int e = blockIdx.x * blockDim.x + threadIdx.x;
    if (e >= M) return;
    int s = src[e], g = tgt[e];
    float v[16];
    float4 xs = *(const float4*)(x + (size_t)4 * s);
    float2 os = *(const float2*)(ofx + (size_t)2 * s);
    float4 xt = *(const float4*)(x + (size_t)4 * g);
    float2 ot = *(const float2*)(ofx + (size_t)2 * g);
    v[0]=xs.x; v[1]=xs.y; v[2]=xs.z; v[3]=xs.w; v[4]=os.x; v[5]=os.y;
    v[6]=xt.x; v[7]=xt.y; v[8]=xt.z; v[9]=xt.w; v[10]=ot.x; v[11]=ot.y;
    v[12]=t[0]; v[13]=1.0f; v[14]=0.f; v[15]=0.f;
    uint32_t wh[8], wl[8];
#pragma unroll
    for (int i = 0; i < 8; i++) split2(v[2*i], v[2*i+1], wh[i], wl[i]);
    uint4* ph = (uint4*)(oh + (size_t)e * 16);
    uint4* pl = (uint4*)(ol + (size_t)e * 16);
    ph[0] = make_uint4(wh[0], wh[1], wh[2], wh[3]);
    ph[1] = make_uint4(wh[4], wh[5], wh[6], wh[7]);
    pl[0] = make_uint4(wl[0], wl[1], wl[2], wl[3]);
    pl[1] = make_uint4(wl[4], wl[5], wl[6], wl[7]);
}

__global__ void zero_kernel(float* __restrict__ p, int n)
{
    int i = blockIdx.x * blockDim.x + threadIdx.x;
    if (i < n) p[i] = 0.f;
}

// ===================== fused layer pair ======================================
// GEMM1 (KT1 k-tiles -> 160 cols, relu, col150=1) into smem INT tile;
// GEMM2 (K=160 -> 160 cols, relu, col150=1) from INT, B register-resident,
// direct-register epilogue -> gmem hi/lo planes.
template <int KT1>
__global__ __launch_bounds__(320, 1)
void fused_pair(const __nv_bfloat16* __restrict__ inH,
                const __nv_bfloat16* __restrict__ inL,
                const __nv_bfloat16* __restrict__ w1img,   // [KD1][168] hi,lo
                const __nv_bfloat16* __restrict__ w2img,   // [160][168] hi,lo
                __nv_bfloat16* __restrict__ outH,
                __nv_bfloat16* __restrict__ outL,
                int M)
{
    constexpr int NW = 10, THREADS = 320;
    constexpr int KD1 = KT1 * 16, ASTR1 = KD1 + 8;
    constexpr int KT2 = 10, ASTR2 = 168, ND = 160, WSTR = 168;
    constexpr int S1 = NW * KT1 * 32 * 16;          // bytes per cache plane
    constexpr int OFF_C1H = 0, OFF_C1L = S1, OFF_A = 2 * S1;
    constexpr int SA = 2 * 64 * ASTR1 * 2;
    constexpr int OFF_INT = OFF_A + SA;
    constexpr int PL_A = 64 * ASTR1 * 2;            // A plane stride (bytes)
    constexpr int PL_I = 64 * ASTR2 * 2;
    constexpr int CPR1 = KD1 / 8, NCH1 = 64 * CPR1 * 2;

    extern __shared__ unsigned char smem[];
    const uint32_t sbu = smem_u32(smem);
    const int tid = threadIdx.x, wid = tid >> 5, lane = tid & 31;
    const int g = lane >> 2, tg = lane & 3;

    // ---- build GEMM1 B cache (packed per-lane frags) -----------------------
    {
        const ushort* WH = (const ushort*)w1img;
        const ushort* WL = WH + KD1 * WSTR;
        uint4* ch = (uint4*)(smem + OFF_C1H);
        uint4* cl = (uint4*)(smem + OFF_C1L);
#pragma unroll
        for (int k0 = 0; k0 < KT1; k0++) {
            uint32_t bh[4], bl[4];
#pragma unroll
            for (int nh = 0; nh < 2; nh++)
#pragma unroll
                for (int r = 0; r < 2; r++) {
                    int k = k0 * 16 + tg * 2 + r * 8;
                    int n = wid * 16 + nh * 8 + g;
                    bh[nh*2+r] = (uint32_t)WH[k*WSTR+n] | ((uint32_t)WH[(k+1)*WSTR+n] << 16);
                    bl[nh*2+r] = (uint32_t)WL[k*WSTR+n] | ((uint32_t)WL[(k+1)*WSTR+n] << 16);
                }
            ch[(wid*KT1+k0)*32 + lane] = make_uint4(bh[0], bh[1], bh[2], bh[3]);
            cl[(wid*KT1+k0)*32 + lane] = make_uint4(bl[0], bl[1], bl[2], bl[3]);
        }
    }
    // ---- GEMM2 B fragments: register-resident ------------------------------
    uint32_t pbh[KT2][4], pbl[KT2][4];
    {
        const ushort* WH = (const ushort*)w2img;
        const ushort* WL = WH + 160 * WSTR;
#pragma unroll
        for (int k0 = 0; k0 < KT2; k0++)
#pragma unroll
            for (int nh = 0; nh < 2; nh++)
#pragma unroll
                for (int r = 0; r < 2; r++) {
                    int k = k0 * 16 + tg * 2 + r * 8;
                    int n = wid * 16 + nh * 8 + g;
                    pbh[k0][nh*2+r] = (uint32_t)WH[k*WSTR+n] | ((uint32_t)WH[(k+1)*WSTR+n] << 16);
                    pbl[k0][nh*2+r] = (uint32_t)WL[k*WSTR+n] | ((uint32_t)WL[(k+1)*WSTR+n] << 16);
                }
    }
    __syncthreads();

    const uint4* c1h = (const uint4*)(smem + OFF_C1H);
    const uint4* c1l = (const uint4*)(smem + OFF_C1L);
    const int ntiles = (M + 63) >> 6;

    auto stage = [&](int tile) {
        const int row0 = tile << 6;
        const uint32_t abase = sbu + OFF_A;
        for (int i = tid; i < NCH1; i += THREADS) {
            int plane = i / (64 * CPR1);
            int rem = i - plane * (64 * CPR1);
            int row = rem / CPR1, ch = rem - row * CPR1;
            int rsrc = row0 + row; if (rsrc >= M) rsrc = M - 1;
            const __nv_bfloat16* s = (plane ? inL : inH) + (size_t)rsrc * KD1 + ch * 8;
            cpa16(abase + plane * PL_A + (row * ASTR1 + ch * 8) * 2, s);
        }
        CP_COMMIT();
    };

    int tile = blockIdx.x;
    if (tile < ntiles) stage(tile);

    for (; tile < ntiles; tile += gridDim.x) {
        CP_WAIT0();
        __syncthreads();                       // A ready; INT free
        const size_t row0 = (size_t)tile << 6;

        // ---------------- GEMM1: A-stage -> INT -----------------------------
        for (int sub = 0; sub < 4; sub++) {
            float accM[2][4] = {}, accC[2][4] = {};
#pragma unroll
            for (int k0 = 0; k0 < KT1; k0++) {
                uint32_t aH[4], aL[4];
                uint32_t col = (uint32_t)(k0 * 16 + ((lane >> 4) << 3));
                uint32_t rofs = (uint32_t)((sub * 16 + (lane & 15)) * ASTR1);
                ldmx4(aH, sbu + OFF_A + (rofs + col) * 2);
                ldmx4(aL, sbu + OFF_A + PL_A + (rofs + col) * 2);
                uint4 h4 = c1h[(wid*KT1+k0)*32 + lane];
                uint4 l4 = c1l[(wid*KT1+k0)*32 + lane];
                mma_bf16(accM[0], aH, h4.x, h4.y);
                mma_bf16(accM[1], aH, h4.z, h4.w);
                mma_bf16(accC[0], aH, l4.x, l4.y);
                mma_bf16(accC[1], aH, l4.z, l4.w);
                mma_bf16(accC[0], aL, h4.x, h4.y);
                mma_bf16(accC[1], aL, h4.z, h4.w);
            }
#pragma unroll
            for (int nh = 0; nh < 2; nh++) {
                float v0 = fmaxf(accM[nh][0] + accC[nh][0], 0.f);
                float v1 = fmaxf(accM[nh][1] + accC[nh][1], 0.f);
                float v2 = fmaxf(accM[nh][2] + accC[nh][2], 0.f);
                float v3 = fmaxf(accM[nh][3] + accC[nh][3], 0.f);
                int gc = wid * 16 + nh * 8 + tg * 2;
                if (gc == 150)     { v0 = 1.f; v2 = 1.f; }
                if (gc + 1 == 150) { v1 = 1.f; v3 = 1.f; }
                uint32_t h0, l0, h1, l1;
                split2(v0, v1, h0, l0);
                split2(v2, v3, h1, l1);
                int r0 = sub * 16 + g;
                *(uint32_t*)(smem + OFF_INT + (r0 * ASTR2 + gc) * 2)            = h0;
                *(uint32_t*)(smem + OFF_INT + PL_I + (r0 * ASTR2 + gc) * 2)     = l0;
                *(uint32_t*)(smem + OFF_INT + ((r0+8) * ASTR2 + gc) * 2)        = h1;
                *(uint32_t*)(smem + OFF_INT + PL_I + ((r0+8) * ASTR2 + gc) * 2) = l1;
            }
        }
        __syncthreads();                       // INT complete; A consumed

        int nxt = tile + gridDim.x;
        if (nxt < ntiles) stage(nxt);          // overlap with GEMM2

        // ---------------- GEMM2: INT -> gmem ---------------------------------
        for (int sub = 0; sub < 4; sub++) {
            float accM[2][4] = {}, accC[2][4] = {};
#pragma unroll
            for (int k0 = 0; k0 < KT2; k0++) {
                uint32_t aH[4], aL[4];
                uint32_t col = (uint32_t)(k0 * 16 + ((lane >> 4) << 3));
                uint32_t rofs = (uint32_t)((sub * 16 + (lane & 15)) * ASTR2);
                ldmx4(aH, sbu + OFF_INT + (rofs + col) * 2);
                ldmx4(aL, sbu + OFF_INT + PL_I + (rofs + col) * 2);
                mma_bf16(accM[0], aH, pbh[k0][0], pbh[k0][1]);
                mma_bf16(accM[1], aH, pbh[k0][2], pbh[k0][3]);
                mma_bf16(accC[0], aH, pbl[k0][0], pbl[k0][1]);
                mma_bf16(accC[1], aH, pbl[k0][2], pbl[k0][3]);
                mma_bf16(accC[0], aL, pbh[k0][0], pbh[k0][1]);
                mma_bf16(accC[1], aL, pbh[k0][2], pbh[k0][3]);
            }
#pragma unroll
            for (int nh = 0; nh < 2; nh++) {
                float v0 = fmaxf(accM[nh][0] + accC[nh][0], 0.f);
                float v1 = fmaxf(accM[nh][1] + accC[nh][1], 0.f);
                float v2 = fmaxf(accM[nh][2] + accC[nh][2], 0.f);
                float v3 = fmaxf(accM[nh][3] + accC[nh][3], 0.f);
                int gc = wid * 16 + nh * 8 + tg * 2;
                if (gc == 150)     { v0 = 1.f; v2 = 1.f; }
                if (gc + 1 == 150) { v1 = 1.f; v3 = 1.f; }
                uint32_t h0, l0, h1, l1;
                split2(v0, v1, h0, l0);
                split2(v2, v3, h1, l1);
                size_t gr0 = row0 + sub * 16 + g;
                *(uint32_t*)(outH + gr0 * ND + gc)       = h0;
                *(uint32_t*)(outL + gr0 * ND + gc)       = l0;
                *(uint32_t*)(outH + (gr0+8) * ND + gc)   = h1;
                *(uint32_t*)(outL + (gr0+8) * ND + gc)   = l1;
            }
        }
        __syncthreads();                       // INT reads done before next G1
    }
}

// ===================== final layer with fused segment-sum ===================
// K=160 -> 64 cols (50 real), atomics straight from accumulator regs.
__global__ __launch_bounds__(256, 1)
void layer_atomic(const __nv_bfloat16* __restrict__ inH,
                  const __nv_bfloat16* __restrict__ inL,
                  const __nv_bfloat16* __restrict__ wimg,   // [160][72] hi,lo
                  const int* __restrict__ tgt,
                  float* __restrict__ ep,
                  int M)
{
    constexpr int THREADS = 256, KT = 10, ASTR = 168, WSTR = 72;
    constexpr int PL_A = 64 * ASTR * 2;
    constexpr int ABUF = 2 * PL_A;
    constexpr int CPR = 20, NCH = 64 * CPR * 2;

    extern __shared__ unsigned char smem[];
    const uint32_t sbu = smem_u32(smem);
    const int tid = threadIdx.x, wid = tid >> 5, lane = tid & 31;
    const int g = lane >> 2, tg = lane & 3;
    const int warp_n = wid & 3, warp_m = wid >> 2;

    uint32_t pbh[KT][4], pbl[KT][4];
    {
        const ushort* WH = (const ushort*)wimg;
        const ushort* WL = WH + 160 * WSTR;
#pragma unroll
        for (int k0 = 0; k0 < KT; k0++)
#pragma unroll
            for (int nh = 0; nh < 2; nh++)
#pragma unroll
                for (int r = 0; r < 2; r++) {
                    int k = k0 * 16 + tg * 2 + r * 8;
                    int n = warp_n * 16 + nh * 8 + g;
                    pbh[k0][nh*2+r] = (uint32_t)WH[k*WSTR+n] | ((uint32_t)WH[(k+1)*WSTR+n] << 16);
                    pbl[k0][nh*2+r] = (uint32_t)WL[k*WSTR+n] | ((uint32_t)WL[(k+1)*WSTR+n] << 16);
                }
    }

    const int ntiles = (M + 63) >> 6;
    auto stage = [&](int b, int tile) {
        const int row0 = tile << 6;
        const uint32_t abase = sbu + b * ABUF;
        for (int i = tid; i < NCH; i += THREADS) {
            int plane = i / (64 * CPR);
            int rem = i - plane * (64 * CPR);
            int row = rem / CPR, ch = rem - row * CPR;
            int rsrc = row0 + row; if (rsrc >= M) rsrc = M - 1;
            const __nv_bfloat16* s = (plane ? inL : inH) + (size_t)rsrc * 160 + ch * 8;
            cpa16(abase + plane * PL_A + (row * ASTR + ch * 8) * 2, s);
        }
        CP_COMMIT();
    };

    int tile = blockIdx.x;
    if (tile < ntiles) stage(0, tile); else CP_COMMIT();
    int buf = 0;

    for (; tile < ntiles; tile += gridDim.x) {
        const int nxt = tile + gridDim.x;
        stage(buf ^ 1, nxt < ntiles ? nxt : tile);
        CP_WAIT1();
        __syncthreads();
        const size_t row0 = (size_t)tile << 6;
        const uint32_t abase = sbu + buf * ABUF;

        for (int sub = warp_m; sub < 4; sub += 2) {
            float accM[2][4] = {}, accC[2][4] = {};
#pragma unroll
            for (int k0 = 0; k0 < KT; k0++) {
                uint32_t aH[4], aL[4];
                uint32_t col = (uint32_t)(k0 * 16 + ((lane >> 4) << 3));
                uint32_t rofs = (uint32_t)((sub * 16 + (lane & 15)) * ASTR);
                ldmx4(aH, abase + (rofs + col) * 2);
                ldmx4(aL, abase + PL_A + (rofs + col) * 2);
                mma_bf16(accM[0], aH, pbh[k0][0], pbh[k0][1]);
                mma_bf16(accM[1], aH, pbh[k0][2], pbh[k0][3]);
                mma_bf16(accC[0], aH, pbl[k0][0], pbl[k0][1]);
                mma_bf16(accC[1], aH, pbl[k0][2], pbl[k0][3]);
                mma_bf16(accC[0], aL, pbh[k0][0], pbh[k0][1]);
                mma_bf16(accC[1], aL, pbh[k0][2], pbh[k0][3]);
            }
            size_t gr0 = row0 + sub * 16 + g;
            size_t gr1 = gr0 + 8;
            int t0 = (gr0 < (size_t)M) ? __ldg(tgt + gr0) : -1;
            int t1 = (gr1 < (size_t)M) ? __ldg(tgt + gr1) : -1;
#pragma unroll
            for (int nh = 0; nh < 2; nh++) {
                int gc = warp_n * 16 + nh * 8 + tg * 2;
                float v0 = accM[nh][0] + accC[nh][0];
                float v1 = accM[nh][1] + accC[nh][1];
                float v2 = accM[nh][2] + accC[nh][2];
                float v3 = accM[nh][3] + accC[nh][3];
                if (t0 >= 0) {
                    if (gc < 50)     atomicAdd(ep + (size_t)t0 * 64 + gc, v0);
                    if (gc + 1 < 50) atomicAdd(ep + (size_t)t0 * 64 + gc + 1, v1);
                }
                if (t1 >= 0) {
                    if (gc < 50)     atomicAdd(ep + (size_t)t1 * 64 + gc, v2);
                    if (gc + 1 < 50) atomicAdd(ep + (size_t)t1 * 64 + gc + 1, v3);
                }
            }
        }
        __syncthreads();
        buf ^= 1;
    }
}

// ===================== SIMT GEMM (node MLP) =================================
template <int NS>
__global__ __launch_bounds__(256, 2)
void gemm_kernel(const float* __restrict__ A, int lda,
                 const float* __restrict__ W, const float* __restrict__ B,
                 float* __restrict__ C, int ldc,
                 int M, int din, int dout, int relu, int padstore)
{
    constexpr int PN = NS * 32;
    extern __shared__ float sm[];
    float* Ws = sm;
    float* Bs = Ws + ((din + 3) & ~3) * PN;
    const int tid = threadIdx.x;
    const int din4 = (din + 3) & ~3;
    for (int idx = tid; idx < din4 * PN; idx += 256) {
        int k = idx / PN, j = idx - k * PN;
        Ws[idx] = (k < din && j < dout) ? W[(size_t)k * dout + j] : 0.f;
    }
    for (int j = tid; j < PN; j += 256) Bs[j] = (j < dout) ? B[j] : 0.f;
    __syncthreads();
    const int lane = tid & 31;
    const int gwarp = blockIdx.x * 8 + (tid >> 5);
    const int nwarp = gridDim.x * 8;
    for (int sidx = gwarp; sidx < (M + 7) >> 3; sidx += nwarp) {
        const int row0 = sidx << 3;
        const float* ap[8];
#pragma unroll
        for (int r = 0; r < 8; r++) {
            int rr = row0 + r; if (rr > M - 1) rr = M - 1;
            ap[r] = A + (size_t)rr * lda;
        }
        float acc[8][NS];
#pragma unroll
        for (int r = 0; r < 8; r++)
#pragma unroll
            for (int s = 0; s < NS; s++) acc[r][s] = 0.f;
#pragma unroll 2
        for (int k = 0; k < din4; k += 4) {
            float4 a[8];
#pragma unroll
            for (int r = 0; r < 8; r++) a[r] = *(const float4*)(ap[r] + k);
#pragma unroll
            for (int kk = 0; kk < 4; kk++) {
                float wv[NS];
#pragma unroll
                for (int s = 0; s < NS; s++) wv[s] = Ws[(k + kk) * PN + lane + (s << 5)];
#pragma unroll
                for (int r = 0; r < 8; r++) {
                    float av = (kk == 0) ? a[r].x : (kk == 1) ? a[r].y : (kk == 2) ? a[r].z : a[r].w;
#pragma unroll
                    for (int s = 0; s < NS; s++) acc[r][s] = fmaf(av, wv[s], acc[r][s]);
                }
            }
        }
#pragma unroll
        for (int r = 0; r < 8; r++) {
            int row = row0 + r;
            if (row < M) {
#pragma unroll
                for (int s = 0; s < NS; s++) {
                    int j = lane + (s << 5);
                    float v = acc[r][s] + Bs[j];
                    if (relu) v = fmaxf(v, 0.f);
                    if (padstore || j < dout) C[(size_t)row * ldc + j] = v;
                }
            }
        }
    }
}

// ===================== host ==================================================
static inline size_t smbytes(int din, int PN)
{
    int din4 = (din + 3) & ~3;
    return (size_t)(din4 * PN + PN) * sizeof(float);
}

extern "C" void kernel_launch(void* const* d_in, const int* in_sizes, int n_in,
                              void* d_out, int out_size)
{
    const float* t   = (const float*)d_in[0];
    const float* x   = (const float*)d_in[1];
    const float* ofx = (const float*)d_in[2];
    const int* src   = (const int*)d_in[3];
    const int* tgt   = (const int*)d_in[4];
    const float* RW[5] = {(const float*)d_in[5], (const float*)d_in[7], (const float*)d_in[9],
                          (const float*)d_in[11], (const float*)d_in[13]};
    const float* Rb[5] = {(const float*)d_in[6], (const float*)d_in[8], (const float*)d_in[10],
                          (const float*)d_in[12], (const float*)d_in[14]};
    const float* OW0 = (const float*)d_in[15];
    const float* Ob0 = (const float*)d_in[16];
    const float* OW1 = (const float*)d_in[17];
    const float* Ob1 = (const float*)d_in[18];
    float* out = (float*)d_out;

    const int M = in_sizes[3];
    const int N = in_sizes[1] / 4;

    __nv_bfloat16 *rpH, *rpL, *Xh, *Xl, *Yh, *Yl, *wst;
    float* ep;
    cudaGetSymbolAddress((void**)&rpH, g_rpH);
    cudaGetSymbolAddress((void**)&rpL, g_rpL);
    cudaGetSymbolAddress((void**)&Xh,  g_Xh);
    cudaGetSymbolAddress((void**)&Xl,  g_Xl);
    cudaGetSymbolAddress((void**)&Yh,  g_Yh);
    cudaGetSymbolAddress((void**)&Yl,  g_Yl);
    cudaGetSymbolAddress((void**)&ep,  g_eprime);
    cudaGetSymbolAddress((void**)&wst, g_wstage);

    int nsm = 148;
    cudaDeviceGetAttribute(&nsm, cudaDevAttrMultiProcessorCount, 0);

    // weight images: L0 16x168, L1-3 160x168, L4 160x72 (hi plane then lo)
    const int woff[5] = {0, 5376, 59136, 112896, 166656};
    const int wdin[5]  = {13, 150, 150, 150, 150};
    const int wdout[5] = {150, 150, 150, 150, 50};
    const int wKD[5]   = {16, 160, 160, 160, 160};
    const int wWSTR[5] = {168, 168, 168, 168, 72};
    const int wbrow[5] = {13, 150, 150, 150, 150};
    PrepPack pk;
    int ptotal = 0;
    for (int i = 0; i < 5; i++) {
        pk.c[i] = PrepCfg{RW[i], Rb[i], wdin[i], wdout[i], wKD[i], wWSTR[i], wbrow[i], woff[i]};
        ptotal += wKD[i] * wWSTR[i];
    }
    prep_all<<<(ptotal + 255) / 256, 256>>>(pk, wst, ptotal);

    zero_kernel<<<(N * 64 + 255) / 256, 256>>>(ep, N * 64);
    gather_kernel<<<(M + 255) / 256, 256>>>(x, ofx, src, tgt, t, rpH, rpL, M);

    // smem sizes
    const int sm01 = 2*(10*1*32*16) + 2*64*24*2 + 2*64*168*2;    // 59392
    const int sm23 = 2*(10*10*32*16) + 2*64*168*2 + 2*64*168*2;  // 188416
    const int sm4  = 2 * 2 * 64 * 168 * 2;                       // 86016
    cudaFuncSetAttribute(fused_pair<1>,  cudaFuncAttributeMaxDynamicSharedMemorySize, sm01);
    cudaFuncSetAttribute(fused_pair<10>, cudaFuncAttributeMaxDynamicSharedMemorySize, sm23);
    cudaFuncSetAttribute(layer_atomic,   cudaFuncAttributeMaxDynamicSharedMemorySize, sm4);

    // edge MLP: [L0+L1] -> X ; [L2+L3] -> Y ; [L4 + segment-sum] -> ep
    fused_pair<1> <<<nsm, 320, sm01>>>(rpH, rpL, wst + woff[0], wst + woff[1], Xh, Xl, M);
    fused_pair<10><<<nsm, 320, sm23>>>(Xh, Xl, wst + woff[2], wst + woff[3], Yh, Yl, M);
    layer_atomic  <<<nsm, 256, sm4>>>(Yh, Yl, wst + woff[4], tgt, ep, M);

    // node MLP
    cudaFuncSetAttribute(gemm_kernel<4>, cudaFuncAttributeMaxDynamicSharedMemorySize, 112 * 1024);
    cudaFuncSetAttribute(gemm_kernel<1>, cudaFuncAttributeMaxDynamicSharedMemorySize, 112 * 1024);
    float* nb = (float*)rpH;
    gemm_kernel<4><<<2 * nsm, 256, smbytes(50, 128)>>>(ep, 64, OW0, Ob0, nb, 128, N, 50, 100, 1, 1);
    gemm_kernel<1><<<2 * nsm, 256, smbytes(100, 32)>>>(nb, 128, OW1, Ob1, out, 4, N, 100, 4, 0, 0);
}

// round 10
// speedup vs baseline: 1.5353x; 1.0698x over previous
#include <cuda_runtime.h>
#include <cuda_bf16.h>
#include <cstdint>
#include <cstddef>

// ===================== scratch (no allocations allowed) =====================
#define MAX_EDGES 2000000
#define MAX_NODES 100000
#define SLACK 128

__device__ __align__(128) __nv_bfloat16 g_rpH[(size_t)(MAX_EDGES + SLACK) * 16];
__device__ __align__(128) __nv_bfloat16 g_rpL[(size_t)(MAX_EDGES + SLACK) * 16];
__device__ __align__(128) __nv_bfloat16 g_Xh[(size_t)(MAX_EDGES + SLACK) * 160];
__device__ __align__(128) __nv_bfloat16 g_Xl[(size_t)(MAX_EDGES + SLACK) * 160];
__device__ __align__(128) __nv_bfloat16 g_Yh[(size_t)(MAX_EDGES + SLACK) * 160];
__device__ __align__(128) __nv_bfloat16 g_Yl[(size_t)(MAX_EDGES + SLACK) * 160];
__device__ float g_eprime[(size_t)MAX_NODES * 64];
__device__ __align__(128) __nv_bfloat16 g_wstage[262144];

// ===================== low-level helpers =====================================
__device__ __forceinline__ uint32_t smem_u32(const void* p) {
    uint32_t a;
    asm("{ .reg .u64 t; cvta.to.shared.u64 t, %1; cvt.u32.u64 %0, t; }" : "=r"(a) : "l"(p));
    return a;
}
__device__ __forceinline__ void cpa16(uint32_t dst, const void* src) {
    asm volatile("cp.async.cg.shared.global [%0], [%1], 16;" :: "r"(dst), "l"(src));
}
#define CP_COMMIT() asm volatile("cp.async.commit_group;" ::: "memory")
#define CP_WAIT0()  asm volatile("cp.async.wait_group 0;" ::: "memory")
#define CP_WAIT1()  asm volatile("cp.async.wait_group 1;" ::: "memory")

__device__ __forceinline__ void mma_bf16(float* c, const uint32_t* a, uint32_t b0, uint32_t b1) {
    asm volatile(
        "mma.sync.aligned.m16n8k16.row.col.f32.bf16.bf16.f32 "
        "{%0,%1,%2,%3}, {%4,%5,%6,%7}, {%8,%9}, {%0,%1,%2,%3};"
        : "+f"(c[0]), "+f"(c[1]), "+f"(c[2]), "+f"(c[3])
        : "r"(a[0]), "r"(a[1]), "r"(a[2]), "r"(a[3]), "r"(b0), "r"(b1));
}
__device__ __forceinline__ void ldmx4(uint32_t* r, uint32_t a) {
    asm volatile("ldmatrix.sync.aligned.m8n8.x4.shared.b16 {%0,%1,%2,%3}, [%4];"
        : "=r"(r[0]), "=r"(r[1]), "=r"(r[2]), "=r"(r[3]) : "r"(a) : "memory");
}
__device__ __forceinline__ void split2(float v0, float v1, uint32_t& hi, uint32_t& lo) {
    __nv_bfloat16 h0 = __float2bfloat16(v0), h1 = __float2bfloat16(v1);
    __nv_bfloat16 l0 = __float2bfloat16(v0 - __bfloat162float(h0));
    __nv_bfloat16 l1 = __float2bfloat16(v1 - __bfloat162float(h1));
    hi = (uint32_t)__bfloat16_as_ushort(h0) | ((uint32_t)__bfloat16_as_ushort(h1) << 16);
    lo = (uint32_t)__bfloat16_as_ushort(l0) | ((uint32_t)__bfloat16_as_ushort(l1) << 16);
}

// ===================== merged weight prep ====================================
struct PrepCfg {
    const float* W; const float* b;
    int din, dout, KD, WSTR, brow, off;
};
struct PrepPack { PrepCfg c[5]; };

__global__ void prep_all(PrepPack p, __nv_bfloat16* __restrict__ wst, int total)
{
    int idx = blockIdx.x * blockDim.x + threadIdx.x;
    if (idx >= total) return;
#pragma unroll
    for (int L = 0; L < 5; L++) {
        int tot = p.c[L].KD * p.c[L].WSTR;
        if (idx < tot) {
            int k = idx / p.c[L].WSTR, n = idx - k * p.c[L].WSTR;
            float v = 0.f;
            if (n < p.c[L].dout) {
                if (k < p.c[L].din) v = p.c[L].W[(size_t)k * p.c[L].dout + n];
                else if (k == p.c[L].brow) v = p.c[L].b[n];
            }
            __nv_bfloat16 h = __float2bfloat16(v);
            __nv_bfloat16 l = __float2bfloat16(v - __bfloat162float(h));
            wst[p.c[L].off + idx] = h;
            wst[p.c[L].off + tot + idx] = l;
            return;
        }
        idx -= tot;
    }
}

// ===================== gather ================================================
__global__ void gather_kernel(const float* __restrict__ x,
                              const float* __restrict__ ofx,
                              const int* __restrict__ src,
                              const int* __restrict__ tgt,
                              const float* __restrict__ t,
                              __nv_bfloat16* __restrict__ oh,
                              __nv_bfloat16* __restrict__ ol, int M)
{
    int e = blockIdx.x * blockDim.x + threadIdx.x;
    if (e >= M) return;
    int s = src[e], g = tgt[e];
    float v[16];
    float4 xs = *(const float4*)(x + (size_t)4 * s);
    float2 os = *(const float2*)(ofx + (size_t)2 * s);
    float4 xt = *(const float4*)(x + (size_t)4 * g);
    float2 ot = *(const float2*)(ofx + (size_t)2 * g);
    v[0]=xs.x; v[1]=xs.y; v[2]=xs.z; v[3]=xs.w; v[4]=os.x; v[5]=os.y;
    v[6]=xt.x; v[7]=xt.y; v[8]=xt.z; v[9]=xt.w; v[10]=ot.x; v[11]=ot.y;
    v[12]=t[0]; v[13]=1.0f; v[14]=0.f; v[15]=0.f;
    uint32_t wh[8], wl[8];
#pragma unroll
    for (int i = 0; i < 8; i++) split2(v[2*i], v[2*i+1], wh[i], wl[i]);
    uint4* ph = (uint4*)(oh + (size_t)e * 16);
    uint4* pl = (uint4*)(ol + (size_t)e * 16);
    ph[0] = make_uint4(wh[0], wh[1], wh[2], wh[3]);
    ph[1] = make_uint4(wh[4], wh[5], wh[6], wh[7]);
    pl[0] = make_uint4(wl[0], wl[1], wl[2], wl[3]);
    pl[1] = make_uint4(wl[4], wl[5], wl[6], wl[7]);
}

__global__ void zero_kernel(float* __restrict__ p, int n)
{
    int i = blockIdx.x * blockDim.x + threadIdx.x;
    if (i < n) p[i] = 0.f;
}

// ===================== fused layer pair (packed-fragment pipeline) ==========
// PACKIN=0: A input row-major bf16 planes (width KD1), GEMM1 A via ldmatrix.
// PACKIN=1: A input packed fragments (uint4/lane), GEMM1 A via LDS.128.
// INT and outputs always packed: frag (k0,sub) at uint4 idx (k0*4+sub)*32+lane,
// tile base = tile*1280 uint4 per plane (hi plane array, lo plane array).
template <int KT1, int PACKIN>
__global__ __launch_bounds__(320, 1)
void fused_pair(const __nv_bfloat16* __restrict__ inH,
                const __nv_bfloat16* __restrict__ inL,
                const __nv_bfloat16* __restrict__ w1img,   // [KD1][168] hi,lo
                const __nv_bfloat16* __restrict__ w2img,   // [160][168] hi,lo
                __nv_bfloat16* __restrict__ outH,
                __nv_bfloat16* __restrict__ outL,
                int M)
{
    constexpr int NW = 10, THREADS = 320;
    constexpr int KD1 = KT1 * 16, ASTR1 = KD1 + 8;
    constexpr int KT2 = 10, WSTR = 168;
    constexpr int S1 = NW * KT1 * 512;              // B1 cache bytes/plane
    constexpr int OFF_A = 2 * S1;
    constexpr int PL_A = 64 * ASTR1 * 2;            // row-major plane bytes
    constexpr int ASIZE = PACKIN ? 40960 : 2 * PL_A;
    constexpr int OFF_INT = OFF_A + ASIZE;
    constexpr int CPR1 = KD1 / 8, NCH1 = 64 * CPR1 * 2;

    extern __shared__ unsigned char smem[];
    const uint32_t sbu = smem_u32(smem);
    const int tid = threadIdx.x, wid = tid >> 5, lane = tid & 31;
    const int g = lane >> 2, tg = lane & 3;
    const int wn = wid % 5, wm = wid / 5;           // GEMM1 2D layout

    // ---- build GEMM1 B cache (warp wid builds 16-col slice wid) -------------
    {
        const ushort* WH = (const ushort*)w1img;
        const ushort* WL = WH + KD1 * WSTR;
        uint4* ch = (uint4*)(smem);
        uint4* cl = (uint4*)(smem + S1);
#pragma unroll
        for (int k0 = 0; k0 < KT1; k0++) {
            uint32_t bh[4], bl[4];
#pragma unroll
            for (int nh = 0; nh < 2; nh++)
#pragma unroll
                for (int r = 0; r < 2; r++) {
                    int k = k0 * 16 + tg * 2 + r * 8;
                    int n = wid * 16 + nh * 8 + g;
                    bh[nh*2+r] = (uint32_t)WH[k*WSTR+n] | ((uint32_t)WH[(k+1)*WSTR+n] << 16);
                    bl[nh*2+r] = (uint32_t)WL[k*WSTR+n] | ((uint32_t)WL[(k+1)*WSTR+n] << 16);
                }
            ch[(wid*KT1+k0)*32 + lane] = make_uint4(bh[0], bh[1], bh[2], bh[3]);
            cl[(wid*KT1+k0)*32 + lane] = make_uint4(bl[0], bl[1], bl[2], bl[3]);
        }
    }
    // ---- GEMM2 B fragments: register-resident -------------------------------
    uint32_t pbh[KT2][4], pbl[KT2][4];
    {
        const ushort* WH = (const ushort*)w2img;
        const ushort* WL = WH + 160 * WSTR;
#pragma unroll
        for (int k0 = 0; k0 < KT2; k0++)
#pragma unroll
            for (int nh = 0; nh < 2; nh++)
#pragma unroll
                for (int r = 0; r < 2; r++) {
                    int k = k0 * 16 + tg * 2 + r * 8;
                    int n = wid * 16 + nh * 8 + g;
                    pbh[k0][nh*2+r] = (uint32_t)WH[k*WSTR+n] | ((uint32_t)WH[(k+1)*WSTR+n] << 16);
                    pbl[k0][nh*2+r] = (uint32_t)WL[k*WSTR+n] | ((uint32_t)WL[(k+1)*WSTR+n] << 16);
                }
    }
    __syncthreads();

    const uint4* c1h = (const uint4*)(smem);
    const uint4* c1l = (const uint4*)(smem + S1);
    const int ntiles = (M + 63) >> 6;

    auto stage = [&](int tile) {
        if (PACKIN) {
            const uint4* hp = (const uint4*)inH;
            const uint4* lp = (const uint4*)inL;
            for (int i = tid; i < 2560; i += THREADS) {
                int plane = i / 1280, off = i - plane * 1280;
                const uint4* s = (plane ? lp : hp) + (size_t)tile * 1280 + off;
                cpa16(sbu + OFF_A + plane * 20480 + off * 16, s);
            }
        } else {
            const int row0 = tile << 6;
            for (int i = tid; i < NCH1; i += THREADS) {
                int plane = i / (64 * CPR1);
                int rem = i - plane * (64 * CPR1);
                int row = rem / CPR1, ch = rem - row * CPR1;
                int rsrc = row0 + row; if (rsrc >= M) rsrc = M - 1;
                const __nv_bfloat16* s = (plane ? inL : inH) + (size_t)rsrc * KD1 + ch * 8;
                cpa16(sbu + OFF_A + plane * PL_A + (row * ASTR1 + ch * 8) * 2, s);
            }
        }
        CP_COMMIT();
    };

    int tile = blockIdx.x;
    if (tile < ntiles) stage(tile);

    for (; tile < ntiles; tile += gridDim.x) {
        CP_WAIT0();
        __syncthreads();                       // A ready; INT free

        // ---------------- GEMM1 (2D): A -> INT packed -----------------------
        for (int si = 0; si < 2; si++) {
            const int sub = wm * 2 + si;
            float accM[4][4] = {}, accC[4][4] = {};
#pragma unroll
            for (int k0 = 0; k0 < KT1; k0++) {
                uint32_t aH[4], aL[4];
                if (PACKIN) {
                    const uint4* ap = (const uint4*)(smem + OFF_A);
                    uint4 a4 = ap[(k0*4 + sub)*32 + lane];
                    uint4 b4 = ap[1280 + (k0*4 + sub)*32 + lane];
                    aH[0]=a4.x; aH[1]=a4.y; aH[2]=a4.z; aH[3]=a4.w;
                    aL[0]=b4.x; aL[1]=b4.y; aL[2]=b4.z; aL[3]=b4.w;
                } else {
                    uint32_t col = (uint32_t)(k0 * 16 + ((lane >> 4) << 3));
                    uint32_t rofs = (uint32_t)((sub * 16 + (lane & 15)) * ASTR1);
                    ldmx4(aH, sbu + OFF_A + (rofs + col) * 2);
                    ldmx4(aL, sbu + OFF_A + PL_A + (rofs + col) * 2);
                }
#pragma unroll
                for (int s2 = 0; s2 < 2; s2++) {
                    const int slice = wn * 2 + s2;
                    uint4 h4 = c1h[(slice*KT1 + k0)*32 + lane];
                    uint4 l4 = c1l[(slice*KT1 + k0)*32 + lane];
                    mma_bf16(accM[s2*2+0], aH, h4.x, h4.y);
                    mma_bf16(accM[s2*2+1], aH, h4.z, h4.w);
                    mma_bf16(accC[s2*2+0], aH, l4.x, l4.y);
                    mma_bf16(accC[s2*2+1], aH, l4.z, l4.w);
                    mma_bf16(accC[s2*2+0], aL, h4.x, h4.y);
                    mma_bf16(accC[s2*2+1], aL, h4.z, h4.w);
                }
            }
#pragma unroll
            for (int s2 = 0; s2 < 2; s2++) {
                const int slice = wn * 2 + s2;
                uint32_t ph[4], pl[4];
#pragma unroll
                for (int nh = 0; nh < 2; nh++) {
                    int a = s2 * 2 + nh;
                    float v0 = fmaxf(accM[a][0] + accC[a][0], 0.f);
                    float v1 = fmaxf(accM[a][1] + accC[a][1], 0.f);
                    float v2 = fmaxf(accM[a][2] + accC[a][2], 0.f);
                    float v3 = fmaxf(accM[a][3] + accC[a][3], 0.f);
                    int gc = slice * 16 + nh * 8 + tg * 2;
                    if (gc == 150)     { v0 = 1.f; v2 = 1.f; }
                    if (gc + 1 == 150) { v1 = 1.f; v3 = 1.f; }
                    split2(v0, v1, ph[nh*2],   pl[nh*2]);
                    split2(v2, v3, ph[nh*2+1], pl[nh*2+1]);
                }
                uint4* ih = (uint4*)(smem + OFF_INT);
                ih[(slice*4 + sub)*32 + lane]        = make_uint4(ph[0], ph[1], ph[2], ph[3]);
                ih[1280 + (slice*4 + sub)*32 + lane] = make_uint4(pl[0], pl[1], pl[2], pl[3]);
            }
        }
        __syncthreads();                       // INT complete; A consumed

        int nxt = tile + gridDim.x;
        if (nxt < ntiles) stage(nxt);          // overlap with GEMM2

        // ---------------- GEMM2 (1D, reg-B): INT -> packed gmem --------------
        for (int sub = 0; sub < 4; sub++) {
            float accM[2][4] = {}, accC[2][4] = {};
#pragma unroll
            for (int k0 = 0; k0 < KT2; k0++) {
                const uint4* ip = (const uint4*)(smem + OFF_INT);
                uint4 a4 = ip[(k0*4 + sub)*32 + lane];
                uint4 b4 = ip[1280 + (k0*4 + sub)*32 + lane];
                uint32_t aH[4] = {a4.x, a4.y, a4.z, a4.w};
                uint32_t aL[4] = {b4.x, b4.y, b4.z, b4.w};
                mma_bf16(accM[0], aH, pbh[k0][0], pbh[k0][1]);
                mma_bf16(accM[1], aH, pbh[k0][2], pbh[k0][3]);
                mma_bf16(accC[0], aH, pbl[k0][0], pbl[k0][1]);
                mma_bf16(accC[1], aH, pbl[k0][2], pbl[k0][3]);
                mma_bf16(accC[0], aL, pbh[k0][0], pbh[k0][1]);
                mma_bf16(accC[1], aL, pbh[k0][2], pbh[k0][3]);
            }
            uint32_t ph[4], pl[4];
#pragma unroll
            for (int nh = 0; nh < 2; nh++) {
                float v0 = fmaxf(accM[nh][0] + accC[nh][0], 0.f);
                float v1 = fmaxf(accM[nh][1] + accC[nh][1], 0.f);
                float v2 = fmaxf(accM[nh][2] + accC[nh][2], 0.f);
                float v3 = fmaxf(accM[nh][3] + accC[nh][3], 0.f);
                int gc = wid * 16 + nh * 8 + tg * 2;
                if (gc == 150)     { v0 = 1.f; v2 = 1.f; }
                if (gc + 1 == 150) { v1 = 1.f; v3 = 1.f; }
                split2(v0, v1, ph[nh*2],   pl[nh*2]);
                split2(v2, v3, ph[nh*2+1], pl[nh*2+1]);
            }
            uint4* oh = (uint4*)outH;
            uint4* ol = (uint4*)outL;
            size_t base = ((size_t)tile * 40 + wid * 4 + sub) * 32 + lane;
            oh[base] = make_uint4(ph[0], ph[1], ph[2], ph[3]);
            ol[base] = make_uint4(pl[0], pl[1], pl[2], pl[3]);
        }
        __syncthreads();                       // INT reads done before next G1
    }
}

// ===================== final layer with fused segment-sum ===================
// Packed A input; K=160 -> 64 cols (50 real); atomics from accumulator regs.
__global__ __launch_bounds__(256, 1)
void layer_atomic(const __nv_bfloat16* __restrict__ inH,
                  const __nv_bfloat16* __restrict__ inL,
                  const __nv_bfloat16* __restrict__ wimg,   // [160][72] hi,lo
                  const int* __restrict__ tgt,
                  float* __restrict__ ep,
                  int M)
{
    constexpr int THREADS = 256, KT = 10, WSTR = 72;
    constexpr int ABUF = 40960;                       // 2 planes x 20480

    extern __shared__ unsigned char smem[];
    const uint32_t sbu = smem_u32(smem);
    const int tid = threadIdx.x, wid = tid >> 5, lane = tid & 31;
    const int g = lane >> 2, tg = lane & 3;
    const int warp_n = wid & 3, warp_m = wid >> 2;

    uint32_t pbh[KT][4], pbl[KT][4];
    {
        const ushort* WH = (const ushort*)wimg;
        const ushort* WL = WH + 160 * WSTR;
#pragma unroll
        for (int k0 = 0; k0 < KT; k0++)
#pragma unroll
            for (int nh = 0; nh < 2; nh++)
#pragma unroll
                for (int r = 0; r < 2; r++) {
                    int k = k0 * 16 + tg * 2 + r * 8;
                    int n = warp_n * 16 + nh * 8 + g;
                    pbh[k0][nh*2+r] = (uint32_t)WH[k*WSTR+n] | ((uint32_t)WH[(k+1)*WSTR+n] << 16);
                    pbl[k0][nh*2+r] = (uint32_t)WL[k*WSTR+n] | ((uint32_t)WL[(k+1)*WSTR+n] << 16);
                }
    }

    const int ntiles = (M + 63) >> 6;
    const uint4* hp = (const uint4*)inH;
    const uint4* lp = (const uint4*)inL;

    auto stage = [&](int b, int tile) {
        for (int i = tid; i < 2560; i += THREADS) {
            int plane = i / 1280, off = i - plane * 1280;
            const uint4* s = (plane ? lp : hp) + (size_t)tile * 1280 + off;
            cpa16(sbu + b * ABUF + plane * 20480 + off * 16, s);
        }
        CP_COMMIT();
    };

    int tile = blockIdx.x;
    if (tile < ntiles) stage(0, tile); else CP_COMMIT();
    int buf = 0;

    for (; tile < ntiles; tile += gridDim.x) {
        const int nxt = tile + gridDim.x;
        stage(buf ^ 1, nxt < ntiles ? nxt : tile);
        CP_WAIT1();
        __syncthreads();
        const size_t row0 = (size_t)tile << 6;
        const uint4* ap = (const uint4*)(smem + buf * ABUF);

        for (int sub = warp_m; sub < 4; sub += 2) {
            float accM[2][4] = {}, accC[2][4] = {};
#pragma unroll
            for (int k0 = 0; k0 < KT; k0++) {
                uint4 a4 = ap[(k0*4 + sub)*32 + lane];
                uint4 b4 = ap[1280 + (k0*4 + sub)*32 + lane];
                uint32_t aH[4] = {a4.x, a4.y, a4.z, a4.w};
                uint32_t aL[4] = {b4.x, b4.y, b4.z, b4.w};
                mma_bf16(accM[0], aH, pbh[k0][0], pbh[k0][1]);
                mma_bf16(accM[1], aH, pbh[k0][2], pbh[k0][3]);
                mma_bf16(accC[0], aH, pbl[k0][0], pbl[k0][1]);
                mma_bf16(accC[1], aH, pbl[k0][2], pbl[k0][3]);
                mma_bf16(accC[0], aL, pbh[k0][0], pbh[k0][1]);
                mma_bf16(accC[1], aL, pbh[k0][2], pbh[k0][3]);
            }
            size_t gr0 = row0 + sub * 16 + g;
            size_t gr1 = gr0 + 8;
            int t0 = (gr0 < (size_t)M) ? __ldg(tgt + gr0) : -1;
            int t1 = (gr1 < (size_t)M) ? __ldg(tgt + gr1) : -1;
#pragma unroll
            for (int nh = 0; nh < 2; nh++) {
                int gc = warp_n * 16 + nh * 8 + tg * 2;
                float v0 = accM[nh][0] + accC[nh][0];
                float v1 = accM[nh][1] + accC[nh][1];
                float v2 = accM[nh][2] + accC[nh][2];
                float v3 = accM[nh][3] + accC[nh][3];
                if (t0 >= 0) {
                    if (gc < 50)     atomicAdd(ep + (size_t)t0 * 64 + gc, v0);
                    if (gc + 1 < 50) atomicAdd(ep + (size_t)t0 * 64 + gc + 1, v1);
                }
                if (t1 >= 0) {
                    if (gc < 50)     atomicAdd(ep + (size_t)t1 * 64 + gc, v2);
                    if (gc + 1 < 50) atomicAdd(ep + (size_t)t1 * 64 + gc + 1, v3);
                }
            }
        }
        __syncthreads();
        buf ^= 1;
    }
}

// ===================== SIMT GEMM (node MLP) =================================
template <int NS>
__global__ __launch_bounds__(256, 2)
void gemm_kernel(const float* __restrict__ A, int lda,
                 const float* __restrict__ W, const float* __restrict__ B,
                 float* __restrict__ C, int ldc,
                 int M, int din, int dout, int relu, int padstore)
{
    constexpr int PN = NS * 32;
    extern __shared__ float sm[];
    float* Ws = sm;
    float* Bs = Ws + ((din + 3) & ~3) * PN;
    const int tid = threadIdx.x;
    const int din4 = (din + 3) & ~3;
    for (int idx = tid; idx < din4 * PN; idx += 256) {
        int k = idx / PN, j = idx - k * PN;
        Ws[idx] = (k < din && j < dout) ? W[(size_t)k * dout + j] : 0.f;
    }
    for (int j = tid; j < PN; j += 256) Bs[j] = (j < dout) ? B[j] : 0.f;
    __syncthreads();
    const int lane = tid & 31;
    const int gwarp = blockIdx.x * 8 + (tid >> 5);
    const int nwarp = gridDim.x * 8;
    for (int sidx = gwarp; sidx < (M + 7) >> 3; sidx += nwarp) {
        const int row0 = sidx << 3;
        const float* ap[8];
#pragma unroll
        for (int r = 0; r < 8; r++) {
            int rr = row0 + r; if (rr > M - 1) rr = M - 1;
            ap[r] = A + (size_t)rr * lda;
        }
        float acc[8][NS];
#pragma unroll
        for (int r = 0; r < 8; r++)
#pragma unroll
            for (int s = 0; s < NS; s++) acc[r][s] = 0.f;
#pragma unroll 2
        for (int k = 0; k < din4; k += 4) {
            float4 a[8];
#pragma unroll
            for (int r = 0; r < 8; r++) a[r] = *(const float4*)(ap[r] + k);
#pragma unroll
            for (int kk = 0; kk < 4; kk++) {
                float wv[NS];
#pragma unroll
                for (int s = 0; s < NS; s++) wv[s] = Ws[(k + kk) * PN + lane + (s << 5)];
#pragma unroll
                for (int r = 0; r < 8; r++) {
                    float av = (kk == 0) ? a[r].x : (kk == 1) ? a[r].y : (kk == 2) ? a[r].z : a[r].w;
#pragma unroll
                    for (int s = 0; s < NS; s++) acc[r][s] = fmaf(av, wv[s], acc[r][s]);
                }
            }
        }
#pragma unroll
        for (int r = 0; r < 8; r++) {
            int row = row0 + r;
            if (row < M) {
#pragma unroll
                for (int s = 0; s < NS; s++) {
                    int j = lane + (s << 5);
                    float v = acc[r][s] + Bs[j];
                    if (relu) v = fmaxf(v, 0.f);
                    if (padstore || j < dout) C[(size_t)row * ldc + j] = v;
                }
            }
        }
    }
}

// ===================== host ==================================================
static inline size_t smbytes(int din, int PN)
{
    int din4 = (din + 3) & ~3;
    return (size_t)(din4 * PN + PN) * sizeof(float);
}

extern "C" void kernel_launch(void* const* d_in, const int* in_sizes, int n_in,
                              void* d_out, int out_size)
{
    const float* t   = (const float*)d_in[0];
    const float* x   = (const float*)d_in[1];
    const float* ofx = (const float*)d_in[2];
    const int* src   = (const int*)d_in[3];
    const int* tgt   = (const int*)d_in[4];
    const float* RW[5] = {(const float*)d_in[5], (const float*)d_in[7], (const float*)d_in[9],
                          (const float*)d_in[11], (const float*)d_in[13]};
    const float* Rb[5] = {(const float*)d_in[6], (const float*)d_in[8], (const float*)d_in[10],
                          (const float*)d_in[12], (const float*)d_in[14]};
    const float* OW0 = (const float*)d_in[15];
    const float* Ob0 = (const float*)d_in[16];
    const float* OW1 = (const float*)d_in[17];
    const float* Ob1 = (const float*)d_in[18];
    float* out = (float*)d_out;

    const int M = in_sizes[3];
    const int N = in_sizes[1] / 4;

    __nv_bfloat16 *rpH, *rpL, *Xh, *Xl, *Yh, *Yl, *wst;
    float* ep;
    cudaGetSymbolAddress((void**)&rpH, g_rpH);
    cudaGetSymbolAddress((void**)&rpL, g_rpL);
    cudaGetSymbolAddress((void**)&Xh,  g_Xh);
    cudaGetSymbolAddress((void**)&Xl,  g_Xl);
    cudaGetSymbolAddress((void**)&Yh,  g_Yh);
    cudaGetSymbolAddress((void**)&Yl,  g_Yl);
    cudaGetSymbolAddress((void**)&ep,  g_eprime);
    cudaGetSymbolAddress((void**)&wst, g_wstage);

    int nsm = 148;
    cudaDeviceGetAttribute(&nsm, cudaDevAttrMultiProcessorCount, 0);

    // weight images: L0 16x168, L1-3 160x168, L4 160x72 (hi plane then lo)
    const int woff[5] = {0, 5376, 59136, 112896, 166656};
    const int wdin[5]  = {13, 150, 150, 150, 150};
    const int wdout[5] = {150, 150, 150, 150, 50};
    const int wKD[5]   = {16, 160, 160, 160, 160};
    const int wWSTR[5] = {168, 168, 168, 168, 72};
    const int wbrow[5] = {13, 150, 150, 150, 150};
    PrepPack pk;
    int ptotal = 0;
    for (int i = 0; i < 5; i++) {
        pk.c[i] = PrepCfg{RW[i], Rb[i], wdin[i], wdout[i], wKD[i], wWSTR[i], wbrow[i], woff[i]};
        ptotal += wKD[i] * wWSTR[i];
    }
    prep_all<<<(ptotal + 255) / 256, 256>>>(pk, wst, ptotal);

    zero_kernel<<<(N * 64 + 255) / 256, 256>>>(ep, N * 64);
    gather_kernel<<<(M + 255) / 256, 256>>>(x, ofx, src, tgt, t, rpH, rpL, M);

    // smem: pair<1,0>: 2*5120 + 6144 + 40960 = 57344
    //       pair<10,1>: 2*51200 + 40960 + 40960 = 184320
    //       layer_atomic: 2*40960 = 81920
    const int sm01 = 57344;
    const int sm23 = 184320;
    const int sm4  = 81920;
    cudaFuncSetAttribute(fused_pair<1, 0>,  cudaFuncAttributeMaxDynamicSharedMemorySize, sm01);
    cudaFuncSetAttribute(fused_pair<10, 1>, cudaFuncAttributeMaxDynamicSharedMemorySize, sm23);
    cudaFuncSetAttribute(layer_atomic,      cudaFuncAttributeMaxDynamicSharedMemorySize, sm4);

    // edge MLP: [L0+L1] -> X packed ; [L2+L3] -> Y packed ; [L4 + scatter] -> ep
    fused_pair<1, 0> <<<nsm, 320, sm01>>>(rpH, rpL, wst + woff[0], wst + woff[1], Xh, Xl, M);
    fused_pair<10, 1><<<nsm, 320, sm23>>>(Xh, Xl, wst + woff[2], wst + woff[3], Yh, Yl, M);
    layer_atomic     <<<nsm, 256, sm4>>>(Yh, Yl, wst + woff[4], tgt, ep, M);

    // node MLP
    cudaFuncSetAttribute(gemm_kernel<4>, cudaFuncAttributeMaxDynamicSharedMemorySize, 112 * 1024);
    cudaFuncSetAttribute(gemm_kernel<1>, cudaFuncAttributeMaxDynamicSharedMemorySize, 112 * 1024);
    float* nb = (float*)rpH;
    gemm_kernel<4><<<2 * nsm, 256, smbytes(50, 128)>>>(ep, 64, OW0, Ob0, nb, 128, N, 50, 100, 1, 1);
    gemm_kernel<1><<<2 * nsm, 256, smbytes(100, 32)>>>(nb, 128, OW1, Ob1, out, 4, N, 100, 4, 0, 0);
}

// round 11
// speedup vs baseline: 1.5762x; 1.0266x over previous
#include <cuda_runtime.h>
#include <cuda_bf16.h>
#include <cstdint>
#include <cstddef>

// ===================== scratch (no allocations allowed) =====================
#define MAX_EDGES 2000000
#define MAX_NODES 100000
#define SLACK 128

__device__ __align__(128) __nv_bfloat16 g_rpH[(size_t)(MAX_EDGES + SLACK) * 16];
__device__ __align__(128) __nv_bfloat16 g_rpL[(size_t)(MAX_EDGES + SLACK) * 16];
__device__ __align__(128) __nv_bfloat16 g_Xh[(size_t)(MAX_EDGES + SLACK) * 160];
__device__ __align__(128) __nv_bfloat16 g_Xl[(size_t)(MAX_EDGES + SLACK) * 160];
__device__ __align__(128) __nv_bfloat16 g_Yh[(size_t)(MAX_EDGES + SLACK) * 160];
__device__ __align__(128) __nv_bfloat16 g_Yl[(size_t)(MAX_EDGES + SLACK) * 160];
__device__ float g_eprime[(size_t)MAX_NODES * 64];
__device__ __align__(128) __nv_bfloat16 g_wstage[262144];

// ===================== low-level helpers =====================================
__device__ __forceinline__ uint32_t smem_u32(const void* p) {
    uint32_t a;
    asm("{ .reg .u64 t; cvta.to.shared.u64 t, %1; cvt.u32.u64 %0, t; }" : "=r"(a) : "l"(p));
    return a;
}
__device__ __forceinline__ void cpa16(uint32_t dst, const void* src) {
    asm volatile("cp.async.cg.shared.global [%0], [%1], 16;" :: "r"(dst), "l"(src));
}
#define CP_COMMIT() asm volatile("cp.async.commit_group;" ::: "memory")
#define CP_WAIT0()  asm volatile("cp.async.wait_group 0;" ::: "memory")
#define CP_WAIT1()  asm volatile("cp.async.wait_group 1;" ::: "memory")

__device__ __forceinline__ void mma_bf16(float* c, const uint32_t* a, uint32_t b0, uint32_t b1) {
    asm volatile(
        "mma.sync.aligned.m16n8k16.row.col.f32.bf16.bf16.f32 "
        "{%0,%1,%2,%3}, {%4,%5,%6,%7}, {%8,%9}, {%0,%1,%2,%3};"
        : "+f"(c[0]), "+f"(c[1]), "+f"(c[2]), "+f"(c[3])
        : "r"(a[0]), "r"(a[1]), "r"(a[2]), "r"(a[3]), "r"(b0), "r"(b1));
}
__device__ __forceinline__ void ldmx4(uint32_t* r, uint32_t a) {
    asm volatile("ldmatrix.sync.aligned.m8n8.x4.shared.b16 {%0,%1,%2,%3}, [%4];"
        : "=r"(r[0]), "=r"(r[1]), "=r"(r[2]), "=r"(r[3]) : "r"(a) : "memory");
}
__device__ __forceinline__ void split2(float v0, float v1, uint32_t& hi, uint32_t& lo) {
    __nv_bfloat16 h0 = __float2bfloat16(v0), h1 = __float2bfloat16(v1);
    __nv_bfloat16 l0 = __float2bfloat16(v0 - __bfloat162float(h0));
    __nv_bfloat16 l1 = __float2bfloat16(v1 - __bfloat162float(h1));
    hi = (uint32_t)__bfloat16_as_ushort(h0) | ((uint32_t)__bfloat16_as_ushort(h1) << 16);
    lo = (uint32_t)__bfloat16_as_ushort(l0) | ((uint32_t)__bfloat16_as_ushort(l1) << 16);
}

// ===================== merged weight prep ====================================
struct PrepCfg {
    const float* W; const float* b;
    int din, dout, KD, WSTR, brow, off;
};
struct PrepPack { PrepCfg c[5]; };

__global__ void prep_all(PrepPack p, __nv_bfloat16* __restrict__ wst, int total)
{
    int idx = blockIdx.x * blockDim.x + threadIdx.x;
    if (idx >= total) return;
#pragma unroll
    for (int L = 0; L < 5; L++) {
        int tot = p.c[L].KD * p.c[L].WSTR;
        if (idx < tot) {
            int k = idx / p.c[L].WSTR, n = idx - k * p.c[L].WSTR;
            float v = 0.f;
            if (n < p.c[L].dout) {
                if (k < p.c[L].din) v = p.c[L].W[(size_t)k * p.c[L].dout + n];
                else if (k == p.c[L].brow) v = p.c[L].b[n];
            }
            __nv_bfloat16 h = __float2bfloat16(v);
            __nv_bfloat16 l = __float2bfloat16(v - __bfloat162float(h));
            wst[p.c[L].off + idx] = h;
            wst[p.c[L].off + tot + idx] = l;
            return;
        }
        idx -= tot;
    }
}

// ===================== gather ================================================
__global__ void gather_kernel(const float* __restrict__ x,
                              const float* __restrict__ ofx,
                              const int* __restrict__ src,
                              const int* __restrict__ tgt,
                              const float* __restrict__ t,
                              __nv_bfloat16* __restrict__ oh,
                              __nv_bfloat16* __restrict__ ol, int M)
{
    int e = blockIdx.x * blockDim.x + threadIdx.x;
    if (e >= M) return;
    int s = src[e], g = tgt[e];
    float v[16];
    float4 xs = *(const float4*)(x + (size_t)4 * s);
    float2 os = *(const float2*)(ofx + (size_t)2 * s);
    float4 xt = *(const float4*)(x + (size_t)4 * g);
    float2 ot = *(const float2*)(ofx + (size_t)2 * g);
    v[0]=xs.x; v[1]=xs.y; v[2]=xs.z; v[3]=xs.w; v[4]=os.x; v[5]=os.y;
    v[6]=xt.x; v[7]=xt.y; v[8]=xt.z; v[9]=xt.w; v[10]=ot.x; v[11]=ot.y;
    v[12]=t[0]; v[13]=1.0f; v[14]=0.f; v[15]=0.f;
    uint32_t wh[8], wl[8];
#pragma unroll
    for (int i = 0; i < 8; i++) split2(v[2*i], v[2*i+1], wh[i], wl[i]);
    uint4* ph = (uint4*)(oh + (size_t)e * 16);
    uint4* pl = (uint4*)(ol + (size_t)e * 16);
    ph[0] = make_uint4(wh[0], wh[1], wh[2], wh[3]);
    ph[1] = make_uint4(wh[4], wh[5], wh[6], wh[7]);
    pl[0] = make_uint4(wl[0], wl[1], wl[2], wl[3]);
    pl[1] = make_uint4(wl[4], wl[5], wl[6], wl[7]);
}

__global__ void zero_kernel(float* __restrict__ p, int n)
{
    int i = blockIdx.x * blockDim.x + threadIdx.x;
    if (i < n) p[i] = 0.f;
}

// ===================== pair1: L0+L1 fused, single-sync pipeline ==============
// G1 (K=16): B1 register-resident, A via direct LDG.32 from rp (L1-reused).
// G2 (K=160): B2 register-resident, INT double-buffered in smem (packed frags).
// One __syncthreads per tile. Per-warp order: G2(t) then G1(t+1).
__global__ __launch_bounds__(320, 1)
void pair1_kernel(const __nv_bfloat16* __restrict__ rpH,
                  const __nv_bfloat16* __restrict__ rpL,
                  const __nv_bfloat16* __restrict__ w1img,   // [16][168] hi,lo
                  const __nv_bfloat16* __restrict__ w2img,   // [160][168] hi,lo
                  __nv_bfloat16* __restrict__ outH,
                  __nv_bfloat16* __restrict__ outL,
                  int M)
{
    constexpr int WSTR = 168;
    extern __shared__ unsigned char smem[];
    uint4* INT = (uint4*)smem;                     // 2 bufs x 2560 uint4

    const int tid = threadIdx.x, wid = tid >> 5, lane = tid & 31;
    const int g = lane >> 2, tg = lane & 3;
    const int wn = wid % 5, wm = wid / 5;

    // B1 regs (2 slices for G1 2D layout)
    uint32_t b1h[2][4], b1l[2][4];
    {
        const ushort* WH = (const ushort*)w1img;
        const ushort* WL = WH + 16 * WSTR;
#pragma unroll
        for (int s2 = 0; s2 < 2; s2++) {
            int slice = wn * 2 + s2;
#pragma unroll
            for (int nh = 0; nh < 2; nh++)
#pragma unroll
                for (int r = 0; r < 2; r++) {
                    int k = tg * 2 + r * 8;
                    int n = slice * 16 + nh * 8 + g;
                    b1h[s2][nh*2+r] = (uint32_t)WH[k*WSTR+n] | ((uint32_t)WH[(k+1)*WSTR+n] << 16);
                    b1l[s2][nh*2+r] = (uint32_t)WL[k*WSTR+n] | ((uint32_t)WL[(k+1)*WSTR+n] << 16);
                }
        }
    }
    // B2 regs (slice = wid)
    uint32_t pbh[10][4], pbl[10][4];
    {
        const ushort* WH = (const ushort*)w2img;
        const ushort* WL = WH + 160 * WSTR;
#pragma unroll
        for (int k0 = 0; k0 < 10; k0++)
#pragma unroll
            for (int nh = 0; nh < 2; nh++)
#pragma unroll
                for (int r = 0; r < 2; r++) {
                    int k = k0 * 16 + tg * 2 + r * 8;
                    int n = wid * 16 + nh * 8 + g;
                    pbh[k0][nh*2+r] = (uint32_t)WH[k*WSTR+n] | ((uint32_t)WH[(k+1)*WSTR+n] << 16);
                    pbl[k0][nh*2+r] = (uint32_t)WL[k*WSTR+n] | ((uint32_t)WL[(k+1)*WSTR+n] << 16);
                }
    }

    const int ntiles = (M + 63) >> 6;

    // ---- G1: rp -> INT[buf] (packed) ----------------------------------------
    auto g1 = [&](int tile, int buf) {
        uint4* ih = INT + buf * 2560;
        const int row0 = tile << 6;
#pragma unroll
        for (int si = 0; si < 2; si++) {
            const int sub = wm * 2 + si;
            int r0 = row0 + sub * 16 + g;
            int r1 = r0 + 8;
            if (r0 > M - 1) r0 = M - 1;
            if (r1 > M - 1) r1 = M - 1;
            const __nv_bfloat16* h0p = rpH + (size_t)r0 * 16 + tg * 2;
            const __nv_bfloat16* h1p = rpH + (size_t)r1 * 16 + tg * 2;
            const __nv_bfloat16* l0p = rpL + (size_t)r0 * 16 + tg * 2;
            const __nv_bfloat16* l1p = rpL + (size_t)r1 * 16 + tg * 2;
            uint32_t aH[4], aL[4];
            aH[0] = *(const uint32_t*)h0p;
            aH[1] = *(const uint32_t*)h1p;
            aH[2] = *(const uint32_t*)(h0p + 8);
            aH[3] = *(const uint32_t*)(h1p + 8);
            aL[0] = *(const uint32_t*)l0p;
            aL[1] = *(const uint32_t*)l1p;
            aL[2] = *(const uint32_t*)(l0p + 8);
            aL[3] = *(const uint32_t*)(l1p + 8);

            float accM[4][4] = {}, accC[4][4] = {};
#pragma unroll
            for (int s2 = 0; s2 < 2; s2++) {
                mma_bf16(accM[s2*2+0], aH, b1h[s2][0], b1h[s2][1]);
                mma_bf16(accM[s2*2+1], aH, b1h[s2][2], b1h[s2][3]);
                mma_bf16(accC[s2*2+0], aH, b1l[s2][0], b1l[s2][1]);
                mma_bf16(accC[s2*2+1], aH, b1l[s2][2], b1l[s2][3]);
                mma_bf16(accC[s2*2+0], aL, b1h[s2][0], b1h[s2][1]);
                mma_bf16(accC[s2*2+1], aL, b1h[s2][2], b1h[s2][3]);
            }
#pragma unroll
            for (int s2 = 0; s2 < 2; s2++) {
                const int slice = wn * 2 + s2;
                uint32_t ph[4], pl[4];
#pragma unroll
                for (int nh = 0; nh < 2; nh++) {
                    int a = s2 * 2 + nh;
                    float v0 = fmaxf(accM[a][0] + accC[a][0], 0.f);
                    float v1 = fmaxf(accM[a][1] + accC[a][1], 0.f);
                    float v2 = fmaxf(accM[a][2] + accC[a][2], 0.f);
                    float v3 = fmaxf(accM[a][3] + accC[a][3], 0.f);
                    int gc = slice * 16 + nh * 8 + tg * 2;
                    if (gc == 150)     { v0 = 1.f; v2 = 1.f; }
                    if (gc + 1 == 150) { v1 = 1.f; v3 = 1.f; }
                    split2(v0, v1, ph[nh*2],   pl[nh*2]);
                    split2(v2, v3, ph[nh*2+1], pl[nh*2+1]);
                }
                ih[(slice*4 + sub)*32 + lane]        = make_uint4(ph[0], ph[1], ph[2], ph[3]);
                ih[1280 + (slice*4 + sub)*32 + lane] = make_uint4(pl[0], pl[1], pl[2], pl[3]);
            }
        }
    };

    // ---- G2: INT[buf] -> packed gmem -----------------------------------------
    auto g2 = [&](int tile, int buf) {
        const uint4* ip = INT + buf * 2560;
        uint4* oh = (uint4*)outH;
        uint4* ol = (uint4*)outL;
#pragma unroll
        for (int sub = 0; sub < 4; sub++) {
            float accM[2][4] = {}, accC[2][4] = {};
#pragma unroll
            for (int k0 = 0; k0 < 10; k0++) {
                uint4 a4 = ip[(k0*4 + sub)*32 + lane];
                uint4 b4 = ip[1280 + (k0*4 + sub)*32 + lane];
                uint32_t aH[4] = {a4.x, a4.y, a4.z, a4.w};
                uint32_t aL[4] = {b4.x, b4.y, b4.z, b4.w};
                mma_bf16(accM[0], aH, pbh[k0][0], pbh[k0][1]);
                mma_bf16(accM[1], aH, pbh[k0][2], pbh[k0][3]);
                mma_bf16(accC[0], aH, pbl[k0][0], pbl[k0][1]);
                mma_bf16(accC[1], aH, pbl[k0][2], pbl[k0][3]);
                mma_bf16(accC[0], aL, pbh[k0][0], pbh[k0][1]);
                mma_bf16(accC[1], aL, pbh[k0][2], pbh[k0][3]);
            }
            uint32_t ph[4], pl[4];
#pragma unroll
            for (int nh = 0; nh < 2; nh++) {
                float v0 = fmaxf(accM[nh][0] + accC[nh][0], 0.f);
                float v1 = fmaxf(accM[nh][1] + accC[nh][1], 0.f);
                float v2 = fmaxf(accM[nh][2] + accC[nh][2], 0.f);
                float v3 = fmaxf(accM[nh][3] + accC[nh][3], 0.f);
                int gc = wid * 16 + nh * 8 + tg * 2;
                if (gc == 150)     { v0 = 1.f; v2 = 1.f; }
                if (gc + 1 == 150) { v1 = 1.f; v3 = 1.f; }
                split2(v0, v1, ph[nh*2],   pl[nh*2]);
                split2(v2, v3, ph[nh*2+1], pl[nh*2+1]);
            }
            size_t base = ((size_t)tile * 40 + wid * 4 + sub) * 32 + lane;
            oh[base] = make_uint4(ph[0], ph[1], ph[2], ph[3]);
            ol[base] = make_uint4(pl[0], pl[1], pl[2], pl[3]);
        }
    };

    int t = blockIdx.x;
    if (t < ntiles) g1(t, 0);
    int i = 0;
    for (; t < ntiles; t += gridDim.x, i++) {
        __syncthreads();                       // INT[i&1] published; prev readers done
        g2(t, i & 1);
        int nxt = t + gridDim.x;
        if (nxt < ntiles) g1(nxt, (i + 1) & 1);
    }
}

// ===================== pair2: L2+L3 (round-10 structure, PACKIN=1) ===========
__global__ __launch_bounds__(320, 1)
void pair2_kernel(const __nv_bfloat16* __restrict__ inH,
                  const __nv_bfloat16* __restrict__ inL,
                  const __nv_bfloat16* __restrict__ w1img,   // [160][168] hi,lo
                  const __nv_bfloat16* __restrict__ w2img,   // [160][168] hi,lo
                  __nv_bfloat16* __restrict__ outH,
                  __nv_bfloat16* __restrict__ outL,
                  int M)
{
    constexpr int THREADS = 320, KT = 10, WSTR = 168;
    constexpr int S1 = 10 * KT * 512;
    constexpr int OFF_A = 2 * S1;
    constexpr int OFF_INT = OFF_A + 40960;

    extern __shared__ unsigned char smem[];
    const uint32_t sbu = smem_u32(smem);
    const int tid = threadIdx.x, wid = tid >> 5, lane = tid & 31;
    const int g = lane >> 2, tg = lane & 3;
    const int wn = wid % 5, wm = wid / 5;

    {
        const ushort* WH = (const ushort*)w1img;
        const ushort* WL = WH + 160 * WSTR;
        uint4* ch = (uint4*)(smem);
        uint4* cl = (uint4*)(smem + S1);
#pragma unroll
        for (int k0 = 0; k0 < KT; k0++) {
            uint32_t bh[4], bl[4];
#pragma unroll
            for (int nh = 0; nh < 2; nh++)
#pragma unroll
                for (int r = 0; r < 2; r++) {
                    int k = k0 * 16 + tg * 2 + r * 8;
                    int n = wid * 16 + nh * 8 + g;
                    bh[nh*2+r] = (uint32_t)WH[k*WSTR+n] | ((uint32_t)WH[(k+1)*WSTR+n] << 16);
                    bl[nh*2+r] = (uint32_t)WL[k*WSTR+n] | ((uint32_t)WL[(k+1)*WSTR+n] << 16);
                }
            ch[(wid*KT+k0)*32 + lane] = make_uint4(bh[0], bh[1], bh[2], bh[3]);
            cl[(wid*KT+k0)*32 + lane] = make_uint4(bl[0], bl[1], bl[2], bl[3]);
        }
    }
    uint32_t pbh[KT][4], pbl[KT][4];
    {
        const ushort* WH = (const ushort*)w2img;
        const ushort* WL = WH + 160 * WSTR;
#pragma unroll
        for (int k0 = 0; k0 < KT; k0++)
#pragma unroll
            for (int nh = 0; nh < 2; nh++)
#pragma unroll
                for (int r = 0; r < 2; r++) {
                    int k = k0 * 16 + tg * 2 + r * 8;
                    int n = wid * 16 + nh * 8 + g;
                    pbh[k0][nh*2+r] = (uint32_t)WH[k*WSTR+n] | ((uint32_t)WH[(k+1)*WSTR+n] << 16);
                    pbl[k0][nh*2+r] = (uint32_t)WL[k*WSTR+n] | ((uint32_t)WL[(k+1)*WSTR+n] << 16);
                }
    }
    __syncthreads();

    const uint4* c1h = (const uint4*)(smem);
    const uint4* c1l = (const uint4*)(smem + S1);
    const int ntiles = (M + 63) >> 6;

    auto stage = [&](int tile) {
        const uint4* hp = (const uint4*)inH;
        const uint4* lp = (const uint4*)inL;
        for (int i = tid; i < 2560; i += THREADS) {
            int plane = i / 1280, off = i - plane * 1280;
            const uint4* s = (plane ? lp : hp) + (size_t)tile * 1280 + off;
            cpa16(sbu + OFF_A + plane * 20480 + off * 16, s);
        }
        CP_COMMIT();
    };

    int tile = blockIdx.x;
    if (tile < ntiles) stage(tile);

    for (; tile < ntiles; tile += gridDim.x) {
        CP_WAIT0();
        __syncthreads();

        for (int si = 0; si < 2; si++) {
            const int sub = wm * 2 + si;
            float accM[4][4] = {}, accC[4][4] = {};
#pragma unroll
            for (int k0 = 0; k0 < KT; k0++) {
                const uint4* ap = (const uint4*)(smem + OFF_A);
                uint4 a4 = ap[(k0*4 + sub)*32 + lane];
                uint4 b4 = ap[1280 + (k0*4 + sub)*32 + lane];
                uint32_t aH[4] = {a4.x, a4.y, a4.z, a4.w};
                uint32_t aL[4] = {b4.x, b4.y, b4.z, b4.w};
#pragma unroll
                for (int s2 = 0; s2 < 2; s2++) {
                    const int slice = wn * 2 + s2;
                    uint4 h4 = c1h[(slice*KT + k0)*32 + lane];
                    uint4 l4 = c1l[(slice*KT + k0)*32 + lane];
                    mma_bf16(accM[s2*2+0], aH, h4.x, h4.y);
                    mma_bf16(accM[s2*2+1], aH, h4.z, h4.w);
                    mma_bf16(accC[s2*2+0], aH, l4.x, l4.y);
                    mma_bf16(accC[s2*2+1], aH, l4.z, l4.w);
                    mma_bf16(accC[s2*2+0], aL, h4.x, h4.y);
                    mma_bf16(accC[s2*2+1], aL, h4.z, h4.w);
                }
            }
#pragma unroll
            for (int s2 = 0; s2 < 2; s2++) {
                const int slice = wn * 2 + s2;
                uint32_t ph[4], pl[4];
#pragma unroll
                for (int nh = 0; nh < 2; nh++) {
                    int a = s2 * 2 + nh;
                    float v0 = fmaxf(accM[a][0] + accC[a][0], 0.f);
                    float v1 = fmaxf(accM[a][1] + accC[a][1], 0.f);
                    float v2 = fmaxf(accM[a][2] + accC[a][2], 0.f);
                    float v3 = fmaxf(accM[a][3] + accC[a][3], 0.f);
                    int gc = slice * 16 + nh * 8 + tg * 2;
                    if (gc == 150)     { v0 = 1.f; v2 = 1.f; }
                    if (gc + 1 == 150) { v1 = 1.f; v3 = 1.f; }
                    split2(v0, v1, ph[nh*2],   pl[nh*2]);
                    split2(v2, v3, ph[nh*2+1], pl[nh*2+1]);
                }
                uint4* ih = (uint4*)(smem + OFF_INT);
                ih[(slice*4 + sub)*32 + lane]        = make_uint4(ph[0], ph[1], ph[2], ph[3]);
                ih[1280 + (slice*4 + sub)*32 + lane] = make_uint4(pl[0], pl[1], pl[2], pl[3]);
            }
        }
        __syncthreads();

        int nxt = tile + gridDim.x;
        if (nxt < ntiles) stage(nxt);

        for (int sub = 0; sub < 4; sub++) {
            float accM[2][4] = {}, accC[2][4] = {};
#pragma unroll
            for (int k0 = 0; k0 < KT; k0++) {
                const uint4* ip = (const uint4*)(smem + OFF_INT);
                uint4 a4 = ip[(k0*4 + sub)*32 + lane];
                uint4 b4 = ip[1280 + (k0*4 + sub)*32 + lane];
                uint32_t aH[4] = {a4.x, a4.y, a4.z, a4.w};
                uint32_t aL[4] = {b4.x, b4.y, b4.z, b4.w};
                mma_bf16(accM[0], aH, pbh[k0][0], pbh[k0][1]);
                mma_bf16(accM[1], aH, pbh[k0][2], pbh[k0][3]);
                mma_bf16(accC[0], aH, pbl[k0][0], pbl[k0][1]);
                mma_bf16(accC[1], aH, pbl[k0][2], pbl[k0][3]);
                mma_bf16(accC[0], aL, pbh[k0][0], pbh[k0][1]);
                mma_bf16(accC[1], aL, pbh[k0][2], pbh[k0][3]);
            }
            uint32_t ph[4], pl[4];
#pragma unroll
            for (int nh = 0; nh < 2; nh++) {
                float v0 = fmaxf(accM[nh][0] + accC[nh][0], 0.f);
                float v1 = fmaxf(accM[nh][1] + accC[nh][1], 0.f);
                float v2 = fmaxf(accM[nh][2] + accC[nh][2], 0.f);
                float v3 = fmaxf(accM[nh][3] + accC[nh][3], 0.f);
                int gc = wid * 16 + nh * 8 + tg * 2;
                if (gc == 150)     { v0 = 1.f; v2 = 1.f; }
                if (gc + 1 == 150) { v1 = 1.f; v3 = 1.f; }
                split2(v0, v1, ph[nh*2],   pl[nh*2]);
                split2(v2, v3, ph[nh*2+1], pl[nh*2+1]);
            }
            uint4* oh = (uint4*)outH;
            uint4* ol = (uint4*)outL;
            size_t base = ((size_t)tile * 40 + wid * 4 + sub) * 32 + lane;
            oh[base] = make_uint4(ph[0], ph[1], ph[2], ph[3]);
            ol[base] = make_uint4(pl[0], pl[1], pl[2], pl[3]);
        }
        __syncthreads();
    }
}

// ===================== final layer + fused segment-sum (16 warps) ============
// 3-slot cp.async ring, ONE sync per tile; warp = (wn 0-3, sub = wm 0-3).
__global__ __launch_bounds__(512, 1)
void layer_atomic(const __nv_bfloat16* __restrict__ inH,
                  const __nv_bfloat16* __restrict__ inL,
                  const __nv_bfloat16* __restrict__ wimg,   // [160][72] hi,lo
                  const int* __restrict__ tgt,
                  float* __restrict__ ep,
                  int M)
{
    constexpr int THREADS = 512, KT = 10, WSTR = 72;
    constexpr int SLOT = 40960;

    extern __shared__ unsigned char smem[];
    const uint32_t sbu = smem_u32(smem);
    const int tid = threadIdx.x, wid = tid >> 5, lane = tid & 31;
    const int g = lane >> 2, tg = lane & 3;
    const int warp_n = wid & 3, sub = wid >> 2;

    uint32_t pbh[KT][4], pbl[KT][4];
    {
        const ushort* WH = (const ushort*)wimg;
        const ushort* WL = WH + 160 * WSTR;
#pragma unroll
        for (int k0 = 0; k0 < KT; k0++)
#pragma unroll
            for (int nh = 0; nh < 2; nh++)
#pragma unroll
                for (int r = 0; r < 2; r++) {
                    int k = k0 * 16 + tg * 2 + r * 8;
                    int n = warp_n * 16 + nh * 8 + g;
                    pbh[k0][nh*2+r] = (uint32_t)WH[k*WSTR+n] | ((uint32_t)WH[(k+1)*WSTR+n] << 16);
                    pbl[k0][nh*2+r] = (uint32_t)WL[k*WSTR+n] | ((uint32_t)WL[(k+1)*WSTR+n] << 16);
                }
    }

    const int ntiles = (M + 63) >> 6;
    const uint4* hp = (const uint4*)inH;
    const uint4* lp = (const uint4*)inL;

    auto stage = [&](int slot, int tile) {
        if (tile < ntiles) {
            for (int i = tid; i < 2560; i += THREADS) {
                int plane = i / 1280, off = i - plane * 1280;
                const uint4* s = (plane ? lp : hp) + (size_t)tile * 1280 + off;
                cpa16(sbu + slot * SLOT + plane * 20480 + off * 16, s);
            }
        }
        CP_COMMIT();
    };

    int t0 = blockIdx.x;
    stage(0, t0);
    stage(1, t0 + gridDim.x);

    int i = 0;
    for (int t = t0; t < ntiles; t += gridDim.x, i++) {
        CP_WAIT1();
        __syncthreads();
        stage((i + 2) % 3, t + 2 * gridDim.x);

        const uint4* ap = (const uint4*)(smem + (i % 3) * SLOT);
        const size_t row0 = (size_t)t << 6;

        float accM[2][4] = {}, accC[2][4] = {};
#pragma unroll
        for (int k0 = 0; k0 < KT; k0++) {
            uint4 a4 = ap[(k0*4 + sub)*32 + lane];
            uint4 b4 = ap[1280 + (k0*4 + sub)*32 + lane];
            uint32_t aH[4] = {a4.x, a4.y, a4.z, a4.w};
            uint32_t aL[4] = {b4.x, b4.y, b4.z, b4.w};
            mma_bf16(accM[0], aH, pbh[k0][0], pbh[k0][1]);
            mma_bf16(accM[1], aH, pbh[k0][2], pbh[k0][3]);
            mma_bf16(accC[0], aH, pbl[k0][0], pbl[k0][1]);
            mma_bf16(accC[1], aH, pbl[k0][2], pbl[k0][3]);
            mma_bf16(accC[0], aL, pbh[k0][0], pbh[k0][1]);
            mma_bf16(accC[1], aL, pbh[k0][2], pbh[k0][3]);
        }
        size_t gr0 = row0 + sub * 16 + g;
        size_t gr1 = gr0 + 8;
        int t0i = (gr0 < (size_t)M) ? __ldg(tgt + gr0) : -1;
        int t1i = (gr1 < (size_t)M) ? __ldg(tgt + gr1) : -1;
#pragma unroll
        for (int nh = 0; nh < 2; nh++) {
            int gc = warp_n * 16 + nh * 8 + tg * 2;
            float v0 = accM[nh][0] + accC[nh][0];
            float v1 = accM[nh][1] + accC[nh][1];
            float v2 = accM[nh][2] + accC[nh][2];
            float v3 = accM[nh][3] + accC[nh][3];
            if (t0i >= 0) {
                if (gc < 50)     atomicAdd(ep + (size_t)t0i * 64 + gc, v0);
                if (gc + 1 < 50) atomicAdd(ep + (size_t)t0i * 64 + gc + 1, v1);
            }
            if (t1i >= 0) {
                if (gc < 50)     atomicAdd(ep + (size_t)t1i * 64 + gc, v2);
                if (gc + 1 < 50) atomicAdd(ep + (size_t)t1i * 64 + gc + 1, v3);
            }
        }
    }
}

// ===================== SIMT GEMM (node MLP) =================================
template <int NS>
__global__ __launch_bounds__(256, 2)
void gemm_kernel(const float* __restrict__ A, int lda,
                 const float* __restrict__ W, const float* __restrict__ B,
                 float* __restrict__ C, int ldc,
                 int M, int din, int dout, int relu, int padstore)
{
    constexpr int PN = NS * 32;
    extern __shared__ float sm[];
    float* Ws = sm;
    float* Bs = Ws + ((din + 3) & ~3) * PN;
    const int tid = threadIdx.x;
    const int din4 = (din + 3) & ~3;
    for (int idx = tid; idx < din4 * PN; idx += 256) {
        int k = idx / PN, j = idx - k * PN;
        Ws[idx] = (k < din && j < dout) ? W[(size_t)k * dout + j] : 0.f;
    }
    for (int j = tid; j < PN; j += 256) Bs[j] = (j < dout) ? B[j] : 0.f;
    __syncthreads();
    const int lane = tid & 31;
    const int gwarp = blockIdx.x * 8 + (tid >> 5);
    const int nwarp = gridDim.x * 8;
    for (int sidx = gwarp; sidx < (M + 7) >> 3; sidx += nwarp) {
        const int row0 = sidx << 3;
        const float* ap[8];
#pragma unroll
        for (int r = 0; r < 8; r++) {
            int rr = row0 + r; if (rr > M - 1) rr = M - 1;
            ap[r] = A + (size_t)rr * lda;
        }
        float acc[8][NS];
#pragma unroll
        for (int r = 0; r < 8; r++)
#pragma unroll
            for (int s = 0; s < NS; s++) acc[r][s] = 0.f;
#pragma unroll 2
        for (int k = 0; k < din4; k += 4) {
            float4 a[8];
#pragma unroll
            for (int r = 0; r < 8; r++) a[r] = *(const float4*)(ap[r] + k);
#pragma unroll
            for (int kk = 0; kk < 4; kk++) {
                float wv[NS];
#pragma unroll
                for (int s = 0; s < NS; s++) wv[s] = Ws[(k + kk) * PN + lane + (s << 5)];
#pragma unroll
                for (int r = 0; r < 8; r++) {
                    float av = (kk == 0) ? a[r].x : (kk == 1) ? a[r].y : (kk == 2) ? a[r].z : a[r].w;
#pragma unroll
                    for (int s = 0; s < NS; s++) acc[r][s] = fmaf(av, wv[s], acc[r][s]);
                }
            }
        }
#pragma unroll
        for (int r = 0; r < 8; r++) {
            int row = row0 + r;
            if (row < M) {
#pragma unroll
                for (int s = 0; s < NS; s++) {
                    int j = lane + (s << 5);
                    float v = acc[r][s] + Bs[j];
                    if (relu) v = fmaxf(v, 0.f);
                    if (padstore || j < dout) C[(size_t)row * ldc + j] = v;
                }
            }
        }
    }
}

// ===================== host ==================================================
static inline size_t smbytes(int din, int PN)
{
    int din4 = (din + 3) & ~3;
    return (size_t)(din4 * PN + PN) * sizeof(float);
}

extern "C" void kernel_launch(void* const* d_in, const int* in_sizes, int n_in,
                              void* d_out, int out_size)
{
    const float* t   = (const float*)d_in[0];
    const float* x   = (const float*)d_in[1];
    const float* ofx = (const float*)d_in[2];
    const int* src   = (const int*)d_in[3];
    const int* tgt   = (const int*)d_in[4];
    const float* RW[5] = {(const float*)d_in[5], (const float*)d_in[7], (const float*)d_in[9],
                          (const float*)d_in[11], (const float*)d_in[13]};
    const float* Rb[5] = {(const float*)d_in[6], (const float*)d_in[8], (const float*)d_in[10],
                          (const float*)d_in[12], (const float*)d_in[14]};
    const float* OW0 = (const float*)d_in[15];
    const float* Ob0 = (const float*)d_in[16];
    const float* OW1 = (const float*)d_in[17];
    const float* Ob1 = (const float*)d_in[18];
    float* out = (float*)d_out;

    const int M = in_sizes[3];
    const int N = in_sizes[1] / 4;

    __nv_bfloat16 *rpH, *rpL, *Xh, *Xl, *Yh, *Yl, *wst;
    float* ep;
    cudaGetSymbolAddress((void**)&rpH, g_rpH);
    cudaGetSymbolAddress((void**)&rpL, g_rpL);
    cudaGetSymbolAddress((void**)&Xh,  g_Xh);
    cudaGetSymbolAddress((void**)&Xl,  g_Xl);
    cudaGetSymbolAddress((void**)&Yh,  g_Yh);
    cudaGetSymbolAddress((void**)&Yl,  g_Yl);
    cudaGetSymbolAddress((void**)&ep,  g_eprime);
    cudaGetSymbolAddress((void**)&wst, g_wstage);

    int nsm = 148;
    cudaDeviceGetAttribute(&nsm, cudaDevAttrMultiProcessorCount, 0);

    const int woff[5] = {0, 5376, 59136, 112896, 166656};
    const int wdin[5]  = {13, 150, 150, 150, 150};
    const int wdout[5] = {150, 150, 150, 150, 50};
    const int wKD[5]   = {16, 160, 160, 160, 160};
    const int wWSTR[5] = {168, 168, 168, 168, 72};
    const int wbrow[5] = {13, 150, 150, 150, 150};
    PrepPack pk;
    int ptotal = 0;
    for (int i = 0; i < 5; i++) {
        pk.c[i] = PrepCfg{RW[i], Rb[i], wdin[i], wdout[i], wKD[i], wWSTR[i], wbrow[i], woff[i]};
        ptotal += wKD[i] * wWSTR[i];
    }
    prep_all<<<(ptotal + 255) / 256, 256>>>(pk, wst, ptotal);

    zero_kernel<<<(N * 64 + 255) / 256, 256>>>(ep, N * 64);
    gather_kernel<<<(M + 255) / 256, 256>>>(x, ofx, src, tgt, t, rpH, rpL, M);

    const int sm01 = 81920;                       // INT x2
    const int sm23 = 2*51200 + 40960 + 40960;     // 184320
    const int sm4  = 3 * 40960;                   // 122880
    cudaFuncSetAttribute(pair1_kernel, cudaFuncAttributeMaxDynamicSharedMemorySize, sm01);
    cudaFuncSetAttribute(pair2_kernel, cudaFuncAttributeMaxDynamicSharedMemorySize, sm23);
    cudaFuncSetAttribute(layer_atomic, cudaFuncAttributeMaxDynamicSharedMemorySize, sm4);

    pair1_kernel<<<nsm, 320, sm01>>>(rpH, rpL, wst + woff[0], wst + woff[1], Xh, Xl, M);
    pair2_kernel<<<nsm, 320, sm23>>>(Xh, Xl, wst + woff[2], wst + woff[3], Yh, Yl, M);
    layer_atomic<<<nsm, 512, sm4>>>(Yh, Yl, wst + woff[4], tgt, ep, M);

    cudaFuncSetAttribute(gemm_kernel<4>, cudaFuncAttributeMaxDynamicSharedMemorySize, 112 * 1024);
    cudaFuncSetAttribute(gemm_kernel<1>, cudaFuncAttributeMaxDynamicSharedMemorySize, 112 * 1024);
    float* nb = (float*)rpH;
    gemm_kernel<4><<<2 * nsm, 256, smbytes(50, 128)>>>(ep, 64, OW0, Ob0, nb, 128, N, 50, 100, 1, 1);
    gemm_kernel<1><<<2 * nsm, 256, smbytes(100, 32)>>>(nb, 128, OW1, Ob1, out, 4, N, 100, 4, 0, 0);
}

// round 12
// speedup vs baseline: 1.5953x; 1.0121x over previous
#include <cuda_runtime.h>
#include <cuda_bf16.h>
#include <cstdint>
#include <cstddef>

// ===================== scratch (no allocations allowed) =====================
#define MAX_EDGES 2000000
#define MAX_NODES 100000
#define SLACK 128

__device__ __align__(128) __nv_bfloat16 g_rpH[(size_t)(MAX_EDGES + SLACK) * 16];
__device__ __align__(128) __nv_bfloat16 g_rpL[(size_t)(MAX_EDGES + SLACK) * 16];
__device__ __align__(128) __nv_bfloat16 g_Xh[(size_t)(MAX_EDGES + SLACK) * 160];
__device__ __align__(128) __nv_bfloat16 g_Xl[(size_t)(MAX_EDGES + SLACK) * 160];
__device__ __align__(128) __nv_bfloat16 g_Yh[(size_t)(MAX_EDGES + SLACK) * 160];
__device__ __align__(128) __nv_bfloat16 g_Yl[(size_t)(MAX_EDGES + SLACK) * 160];
__device__ float g_eprime[(size_t)MAX_NODES * 64];
__device__ __align__(128) __nv_bfloat16 g_wstage[262144];

// ===================== low-level helpers =====================================
__device__ __forceinline__ uint32_t smem_u32(const void* p) {
    uint32_t a;
    asm("{ .reg .u64 t; cvta.to.shared.u64 t, %1; cvt.u32.u64 %0, t; }" : "=r"(a) : "l"(p));
    return a;
}
__device__ __forceinline__ void cpa16(uint32_t dst, const void* src) {
    asm volatile("cp.async.cg.shared.global [%0], [%1], 16;" :: "r"(dst), "l"(src));
}
#define CP_COMMIT() asm volatile("cp.async.commit_group;" ::: "memory")
#define CP_WAIT0()  asm volatile("cp.async.wait_group 0;" ::: "memory")
#define CP_WAIT1()  asm volatile("cp.async.wait_group 1;" ::: "memory")

__device__ __forceinline__ void mma_bf16(float* c, const uint32_t* a, uint32_t b0, uint32_t b1) {
    asm volatile(
        "mma.sync.aligned.m16n8k16.row.col.f32.bf16.bf16.f32 "
        "{%0,%1,%2,%3}, {%4,%5,%6,%7}, {%8,%9}, {%0,%1,%2,%3};"
        : "+f"(c[0]), "+f"(c[1]), "+f"(c[2]), "+f"(c[3])
        : "r"(a[0]), "r"(a[1]), "r"(a[2]), "r"(a[3]), "r"(b0), "r"(b1));
}
__device__ __forceinline__ void red2(float* gp, float v0, float v1) {
    asm volatile("red.global.add.v2.f32 [%0], {%1, %2};" :: "l"(gp), "f"(v0), "f"(v1) : "memory");
}
__device__ __forceinline__ void split2(float v0, float v1, uint32_t& hi, uint32_t& lo) {
    __nv_bfloat16 h0 = __float2bfloat16(v0), h1 = __float2bfloat16(v1);
    __nv_bfloat16 l0 = __float2bfloat16(v0 - __bfloat162float(h0));
    __nv_bfloat16 l1 = __float2bfloat16(v1 - __bfloat162float(h1));
    hi = (uint32_t)__bfloat16_as_ushort(h0) | ((uint32_t)__bfloat16_as_ushort(h1) << 16);
    lo = (uint32_t)__bfloat16_as_ushort(l0) | ((uint32_t)__bfloat16_as_ushort(l1) << 16);
}

// ===================== merged weight prep ====================================
struct PrepCfg {
    const float* W; const float* b;
    int din, dout, KD, WSTR, brow, off;
};
struct PrepPack { PrepCfg c[5]; };

__global__ void prep_all(PrepPack p, __nv_bfloat16* __restrict__ wst, int total)
{
    int idx = blockIdx.x * blockDim.x + threadIdx.x;
    if (idx >= total) return;
#pragma unroll
    for (int L = 0; L < 5; L++) {
        int tot = p.c[L].KD * p.c[L].WSTR;
        if (idx < tot) {
            int k = idx / p.c[L].WSTR, n = idx - k * p.c[L].WSTR;
            float v = 0.f;
            if (n < p.c[L].dout) {
                if (k < p.c[L].din) v = p.c[L].W[(size_t)k * p.c[L].dout + n];
                else if (k == p.c[L].brow) v = p.c[L].b[n];
            }
            __nv_bfloat16 h = __float2bfloat16(v);
            __nv_bfloat16 l = __float2bfloat16(v - __bfloat162float(h));
            wst[p.c[L].off + idx] = h;
            wst[p.c[L].off + tot + idx] = l;
            return;
        }
        idx -= tot;
    }
}

// ===================== gather ================================================
__global__ void gather_kernel(const float* __restrict__ x,
                              const float* __restrict__ ofx,
                              const int* __restrict__ src,
                              const int* __restrict__ tgt,
                              const float* __restrict__ t,
                              __nv_bfloat16* __restrict__ oh,
                              __nv_bfloat16* __restrict__ ol, int M)
{
    int e = blockIdx.x * blockDim.x + threadIdx.x;
    if (e >= M) return;
    int s = src[e], g = tgt[e];
    float v[16];
    float4 xs = *(const float4*)(x + (size_t)4 * s);
    float2 os = *(const float2*)(ofx + (size_t)2 * s);
    float4 xt = *(const float4*)(x + (size_t)4 * g);
    float2 ot = *(const float2*)(ofx + (size_t)2 * g);
    v[0]=xs.x; v[1]=xs.y; v[2]=xs.z; v[3]=xs.w; v[4]=os.x; v[5]=os.y;
    v[6]=xt.x; v[7]=xt.y; v[8]=xt.z; v[9]=xt.w; v[10]=ot.x; v[11]=ot.y;
    v[12]=t[0]; v[13]=1.0f; v[14]=0.f; v[15]=0.f;
    uint32_t wh[8], wl[8];
#pragma unroll
    for (int i = 0; i < 8; i++) split2(v[2*i], v[2*i+1], wh[i], wl[i]);
    uint4* ph = (uint4*)(oh + (size_t)e * 16);
    uint4* pl = (uint4*)(ol + (size_t)e * 16);
    ph[0] = make_uint4(wh[0], wh[1], wh[2], wh[3]);
    ph[1] = make_uint4(wh[4], wh[5], wh[6], wh[7]);
    pl[0] = make_uint4(wl[0], wl[1], wl[2], wl[3]);
    pl[1] = make_uint4(wl[4], wl[5], wl[6], wl[7]);
}

__global__ void zero_kernel(float* __restrict__ p, int n)
{
    int i = blockIdx.x * blockDim.x + threadIdx.x;
    if (i < n) p[i] = 0.f;
}

// ===================== pair1: L0+L1 fused, single-sync pipeline ==============
__global__ __launch_bounds__(320, 1)
void pair1_kernel(const __nv_bfloat16* __restrict__ rpH,
                  const __nv_bfloat16* __restrict__ rpL,
                  const __nv_bfloat16* __restrict__ w1img,   // [16][168] hi,lo
                  const __nv_bfloat16* __restrict__ w2img,   // [160][168] hi,lo
                  __nv_bfloat16* __restrict__ outH,
                  __nv_bfloat16* __restrict__ outL,
                  int M)
{
    constexpr int WSTR = 168;
    extern __shared__ unsigned char smem[];
    uint4* INT = (uint4*)smem;                     // 2 bufs x 2560 uint4

    const int tid = threadIdx.x, wid = tid >> 5, lane = tid & 31;
    const int g = lane >> 2, tg = lane & 3;
    const int wn = wid % 5, wm = wid / 5;

    // B1 regs (2 slices)
    uint32_t b1h[2][4], b1l[2][4];
    {
        const ushort* WH = (const ushort*)w1img;
        const ushort* WL = WH + 16 * WSTR;
#pragma unroll
        for (int s2 = 0; s2 < 2; s2++) {
            int slice = wn * 2 + s2;
#pragma unroll
            for (int nh = 0; nh < 2; nh++)
#pragma unroll
                for (int r = 0; r < 2; r++) {
                    int k = tg * 2 + r * 8;
                    int n = slice * 16 + nh * 8 + g;
                    b1h[s2][nh*2+r] = (uint32_t)WH[k*WSTR+n] | ((uint32_t)WH[(k+1)*WSTR+n] << 16);
                    b1l[s2][nh*2+r] = (uint32_t)WL[k*WSTR+n] | ((uint32_t)WL[(k+1)*WSTR+n] << 16);
                }
        }
    }
    // B2 regs (slice = wid)
    uint32_t pbh[10][4], pbl[10][4];
    {
        const ushort* WH = (const ushort*)w2img;
        const ushort* WL = WH + 160 * WSTR;
#pragma unroll
        for (int k0 = 0; k0 < 10; k0++)
#pragma unroll
            for (int nh = 0; nh < 2; nh++)
#pragma unroll
                for (int r = 0; r < 2; r++) {
                    int k = k0 * 16 + tg * 2 + r * 8;
                    int n = wid * 16 + nh * 8 + g;
                    pbh[k0][nh*2+r] = (uint32_t)WH[k*WSTR+n] | ((uint32_t)WH[(k+1)*WSTR+n] << 16);
                    pbl[k0][nh*2+r] = (uint32_t)WL[k*WSTR+n] | ((uint32_t)WL[(k+1)*WSTR+n] << 16);
                }
    }

    const int ntiles = (M + 63) >> 6;

    // prefetch next-tile A for this warp's 2 subs into regs
    uint32_t pAH[2][4], pAL[2][4];
    auto prefetch = [&](int tile) {
        const int row0 = tile << 6;
#pragma unroll
        for (int si = 0; si < 2; si++) {
            const int sub = wm * 2 + si;
            int r0 = row0 + sub * 16 + g;
            int r1 = r0 + 8;
            if (r0 > M - 1) r0 = M - 1;
            if (r1 > M - 1) r1 = M - 1;
            const __nv_bfloat16* h0p = rpH + (size_t)r0 * 16 + tg * 2;
            const __nv_bfloat16* h1p = rpH + (size_t)r1 * 16 + tg * 2;
            const __nv_bfloat16* l0p = rpL + (size_t)r0 * 16 + tg * 2;
            const __nv_bfloat16* l1p = rpL + (size_t)r1 * 16 + tg * 2;
            pAH[si][0] = *(const uint32_t*)h0p;
            pAH[si][1] = *(const uint32_t*)h1p;
            pAH[si][2] = *(const uint32_t*)(h0p + 8);
            pAH[si][3] = *(const uint32_t*)(h1p + 8);
            pAL[si][0] = *(const uint32_t*)l0p;
            pAL[si][1] = *(const uint32_t*)l1p;
            pAL[si][2] = *(const uint32_t*)(l0p + 8);
            pAL[si][3] = *(const uint32_t*)(l1p + 8);
        }
    };

    // G1 from prefetched regs -> INT[buf]
    auto g1 = [&](int buf) {
        uint4* ih = INT + buf * 2560;
#pragma unroll
        for (int si = 0; si < 2; si++) {
            const int sub = wm * 2 + si;
            float acc[4][4] = {};
#pragma unroll
            for (int s2 = 0; s2 < 2; s2++) {
                mma_bf16(acc[s2*2+0], pAH[si], b1h[s2][0], b1h[s2][1]);
                mma_bf16(acc[s2*2+0], pAH[si], b1l[s2][0], b1l[s2][1]);
                mma_bf16(acc[s2*2+0], pAL[si], b1h[s2][0], b1h[s2][1]);
                mma_bf16(acc[s2*2+1], pAH[si], b1h[s2][2], b1h[s2][3]);
                mma_bf16(acc[s2*2+1], pAH[si], b1l[s2][2], b1l[s2][3]);
                mma_bf16(acc[s2*2+1], pAL[si], b1h[s2][2], b1h[s2][3]);
            }
#pragma unroll
            for (int s2 = 0; s2 < 2; s2++) {
                const int slice = wn * 2 + s2;
                uint32_t ph[4], pl[4];
#pragma unroll
                for (int nh = 0; nh < 2; nh++) {
                    int a = s2 * 2 + nh;
                    float v0 = fmaxf(acc[a][0], 0.f);
                    float v1 = fmaxf(acc[a][1], 0.f);
                    float v2 = fmaxf(acc[a][2], 0.f);
                    float v3 = fmaxf(acc[a][3], 0.f);
                    int gc = slice * 16 + nh * 8 + tg * 2;
                    if (gc == 150)     { v0 = 1.f; v2 = 1.f; }
                    if (gc + 1 == 150) { v1 = 1.f; v3 = 1.f; }
                    split2(v0, v1, ph[nh*2],   pl[nh*2]);
                    split2(v2, v3, ph[nh*2+1], pl[nh*2+1]);
                }
                ih[(slice*4 + sub)*32 + lane]        = make_uint4(ph[0], ph[1], ph[2], ph[3]);
                ih[1280 + (slice*4 + sub)*32 + lane] = make_uint4(pl[0], pl[1], pl[2], pl[3]);
            }
        }
    };

    auto g2 = [&](int tile, int buf) {
        const uint4* ip = INT + buf * 2560;
        uint4* oh = (uint4*)outH;
        uint4* ol = (uint4*)outL;
#pragma unroll
        for (int sub = 0; sub < 4; sub++) {
            float acc[2][4] = {};
#pragma unroll
            for (int k0 = 0; k0 < 10; k0++) {
                uint4 a4 = ip[(k0*4 + sub)*32 + lane];
                uint4 b4 = ip[1280 + (k0*4 + sub)*32 + lane];
                uint32_t aH[4] = {a4.x, a4.y, a4.z, a4.w};
                uint32_t aL[4] = {b4.x, b4.y, b4.z, b4.w};
                mma_bf16(acc[0], aH, pbh[k0][0], pbh[k0][1]);
                mma_bf16(acc[0], aH, pbl[k0][0], pbl[k0][1]);
                mma_bf16(acc[0], aL, pbh[k0][0], pbh[k0][1]);
                mma_bf16(acc[1], aH, pbh[k0][2], pbh[k0][3]);
                mma_bf16(acc[1], aH, pbl[k0][2], pbl[k0][3]);
                mma_bf16(acc[1], aL, pbh[k0][2], pbh[k0][3]);
            }
            uint32_t ph[4], pl[4];
#pragma unroll
            for (int nh = 0; nh < 2; nh++) {
                float v0 = fmaxf(acc[nh][0], 0.f);
                float v1 = fmaxf(acc[nh][1], 0.f);
                float v2 = fmaxf(acc[nh][2], 0.f);
                float v3 = fmaxf(acc[nh][3], 0.f);
                int gc = wid * 16 + nh * 8 + tg * 2;
                if (gc == 150)     { v0 = 1.f; v2 = 1.f; }
                if (gc + 1 == 150) { v1 = 1.f; v3 = 1.f; }
                split2(v0, v1, ph[nh*2],   pl[nh*2]);
                split2(v2, v3, ph[nh*2+1], pl[nh*2+1]);
            }
            size_t base = ((size_t)tile * 40 + wid * 4 + sub) * 32 + lane;
            oh[base] = make_uint4(ph[0], ph[1], ph[2], ph[3]);
            ol[base] = make_uint4(pl[0], pl[1], pl[2], pl[3]);
        }
    };

    int t = blockIdx.x;
    if (t < ntiles) { prefetch(t); g1(0); }
    int i = 0;
    for (; t < ntiles; t += gridDim.x, i++) {
        int nxt = t + gridDim.x;
        if (nxt < ntiles) prefetch(nxt);       // LDGs overlap sync + G2
        __syncthreads();
        g2(t, i & 1);
        if (nxt < ntiles) g1((i + 1) & 1);
    }
}

// ===================== pair2: L2+L3, k0-outer G1 (B hoisted) =================
__global__ __launch_bounds__(320, 1)
void pair2_kernel(const __nv_bfloat16* __restrict__ inH,
                  const __nv_bfloat16* __restrict__ inL,
                  const __nv_bfloat16* __restrict__ w1img,
                  const __nv_bfloat16* __restrict__ w2img,
                  __nv_bfloat16* __restrict__ outH,
                  __nv_bfloat16* __restrict__ outL,
                  int M)
{
    constexpr int THREADS = 320, KT = 10, WSTR = 168;
    constexpr int S1 = 10 * KT * 512;
    constexpr int OFF_A = 2 * S1;
    constexpr int OFF_INT = OFF_A + 40960;

    extern __shared__ unsigned char smem[];
    const uint32_t sbu = smem_u32(smem);
    const int tid = threadIdx.x, wid = tid >> 5, lane = tid & 31;
    const int g = lane >> 2, tg = lane & 3;
    const int wn = wid % 5, wm = wid / 5;

    {
        const ushort* WH = (const ushort*)w1img;
        const ushort* WL = WH + 160 * WSTR;
        uint4* ch = (uint4*)(smem);
        uint4* cl = (uint4*)(smem + S1);
#pragma unroll
        for (int k0 = 0; k0 < KT; k0++) {
            uint32_t bh[4], bl[4];
#pragma unroll
            for (int nh = 0; nh < 2; nh++)
#pragma unroll
                for (int r = 0; r < 2; r++) {
                    int k = k0 * 16 + tg * 2 + r * 8;
                    int n = wid * 16 + nh * 8 + g;
                    bh[nh*2+r] = (uint32_t)WH[k*WSTR+n] | ((uint32_t)WH[(k+1)*WSTR+n] << 16);
                    bl[nh*2+r] = (uint32_t)WL[k*WSTR+n] | ((uint32_t)WL[(k+1)*WSTR+n] << 16);
                }
            ch[(wid*KT+k0)*32 + lane] = make_uint4(bh[0], bh[1], bh[2], bh[3]);
            cl[(wid*KT+k0)*32 + lane] = make_uint4(bl[0], bl[1], bl[2], bl[3]);
        }
    }
    uint32_t pbh[KT][4], pbl[KT][4];
    {
        const ushort* WH = (const ushort*)w2img;
        const ushort* WL = WH + 160 * WSTR;
#pragma unroll
        for (int k0 = 0; k0 < KT; k0++)
#pragma unroll
            for (int nh = 0; nh < 2; nh++)
#pragma unroll
                for (int r = 0; r < 2; r++) {
                    int k = k0 * 16 + tg * 2 + r * 8;
                    int n = wid * 16 + nh * 8 + g;
                    pbh[k0][nh*2+r] = (uint32_t)WH[k*WSTR+n] | ((uint32_t)WH[(k+1)*WSTR+n] << 16);
                    pbl[k0][nh*2+r] = (uint32_t)WL[k*WSTR+n] | ((uint32_t)WL[(k+1)*WSTR+n] << 16);
                }
    }
    __syncthreads();

    const uint4* c1h = (const uint4*)(smem);
    const uint4* c1l = (const uint4*)(smem + S1);
    const int ntiles = (M + 63) >> 6;

    auto stage = [&](int tile) {
        const uint4* hp = (const uint4*)inH;
        const uint4* lp = (const uint4*)inL;
        for (int i = tid; i < 2560; i += THREADS) {
            int plane = i / 1280, off = i - plane * 1280;
            const uint4* s = (plane ? lp : hp) + (size_t)tile * 1280 + off;
            cpa16(sbu + OFF_A + plane * 20480 + off * 16, s);
        }
        CP_COMMIT();
    };

    int tile = blockIdx.x;
    if (tile < ntiles) stage(tile);

    for (; tile < ntiles; tile += gridDim.x) {
        CP_WAIT0();
        __syncthreads();

        // ---- G1: k0-outer, B-frags hoisted, single acc per unit -------------
        {
            float acc[2][4][4] = {};          // [si][s2*2+nh][4]
            const uint4* ap = (const uint4*)(smem + OFF_A);
#pragma unroll
            for (int k0 = 0; k0 < KT; k0++) {
                uint4 h4[2], l4[2];
#pragma unroll
                for (int s2 = 0; s2 < 2; s2++) {
                    const int slice = wn * 2 + s2;
                    h4[s2] = c1h[(slice*KT + k0)*32 + lane];
                    l4[s2] = c1l[(slice*KT + k0)*32 + lane];
                }
#pragma unroll
                for (int si = 0; si < 2; si++) {
                    const int sub = wm * 2 + si;
                    uint4 a4 = ap[(k0*4 + sub)*32 + lane];
                    uint4 b4 = ap[1280 + (k0*4 + sub)*32 + lane];
                    uint32_t aH[4] = {a4.x, a4.y, a4.z, a4.w};
                    uint32_t aL[4] = {b4.x, b4.y, b4.z, b4.w};
#pragma unroll
                    for (int s2 = 0; s2 < 2; s2++) {
                        mma_bf16(acc[si][s2*2+0], aH, h4[s2].x, h4[s2].y);
                        mma_bf16(acc[si][s2*2+0], aH, l4[s2].x, l4[s2].y);
                        mma_bf16(acc[si][s2*2+0], aL, h4[s2].x, h4[s2].y);
                        mma_bf16(acc[si][s2*2+1], aH, h4[s2].z, h4[s2].w);
                        mma_bf16(acc[si][s2*2+1], aH, l4[s2].z, l4[s2].w);
                        mma_bf16(acc[si][s2*2+1], aL, h4[s2].z, h4[s2].w);
                    }
                }
            }
            uint4* ih = (uint4*)(smem + OFF_INT);
#pragma unroll
            for (int si = 0; si < 2; si++) {
                const int sub = wm * 2 + si;
#pragma unroll
                for (int s2 = 0; s2 < 2; s2++) {
                    const int slice = wn * 2 + s2;
                    uint32_t ph[4], pl[4];
#pragma unroll
                    for (int nh = 0; nh < 2; nh++) {
                        int a = s2 * 2 + nh;
                        float v0 = fmaxf(acc[si][a][0], 0.f);
                        float v1 = fmaxf(acc[si][a][1], 0.f);
                        float v2 = fmaxf(acc[si][a][2], 0.f);
                        float v3 = fmaxf(acc[si][a][3], 0.f);
                        int gc = slice * 16 + nh * 8 + tg * 2;
                        if (gc == 150)     { v0 = 1.f; v2 = 1.f; }
                        if (gc + 1 == 150) { v1 = 1.f; v3 = 1.f; }
                        split2(v0, v1, ph[nh*2],   pl[nh*2]);
                        split2(v2, v3, ph[nh*2+1], pl[nh*2+1]);
                    }
                    ih[(slice*4 + sub)*32 + lane]        = make_uint4(ph[0], ph[1], ph[2], ph[3]);
                    ih[1280 + (slice*4 + sub)*32 + lane] = make_uint4(pl[0], pl[1], pl[2], pl[3]);
                }
            }
        }
        __syncthreads();

        int nxt = tile + gridDim.x;
        if (nxt < ntiles) stage(nxt);

        // ---- G2 --------------------------------------------------------------
        for (int sub = 0; sub < 4; sub++) {
            float acc[2][4] = {};
#pragma unroll
            for (int k0 = 0; k0 < KT; k0++) {
                const uint4* ip = (const uint4*)(smem + OFF_INT);
                uint4 a4 = ip[(k0*4 + sub)*32 + lane];
                uint4 b4 = ip[1280 + (k0*4 + sub)*32 + lane];
                uint32_t aH[4] = {a4.x, a4.y, a4.z, a4.w};
                uint32_t aL[4] = {b4.x, b4.y, b4.z, b4.w};
                mma_bf16(acc[0], aH, pbh[k0][0], pbh[k0][1]);
                mma_bf16(acc[0], aH, pbl[k0][0], pbl[k0][1]);
                mma_bf16(acc[0], aL, pbh[k0][0], pbh[k0][1]);
                mma_bf16(acc[1], aH, pbh[k0][2], pbh[k0][3]);
                mma_bf16(acc[1], aH, pbl[k0][2], pbl[k0][3]);
                mma_bf16(acc[1], aL, pbh[k0][2], pbh[k0][3]);
            }
            uint32_t ph[4], pl[4];
#pragma unroll
            for (int nh = 0; nh < 2; nh++) {
                float v0 = fmaxf(acc[nh][0], 0.f);
                float v1 = fmaxf(acc[nh][1], 0.f);
                float v2 = fmaxf(acc[nh][2], 0.f);
                float v3 = fmaxf(acc[nh][3], 0.f);
                int gc = wid * 16 + nh * 8 + tg * 2;
                if (gc == 150)     { v0 = 1.f; v2 = 1.f; }
                if (gc + 1 == 150) { v1 = 1.f; v3 = 1.f; }
                split2(v0, v1, ph[nh*2],   pl[nh*2]);
                split2(v2, v3, ph[nh*2+1], pl[nh*2+1]);
            }
            uint4* oh = (uint4*)outH;
            uint4* ol = (uint4*)outL;
            size_t base = ((size_t)tile * 40 + wid * 4 + sub) * 32 + lane;
            oh[base] = make_uint4(ph[0], ph[1], ph[2], ph[3]);
            ol[base] = make_uint4(pl[0], pl[1], pl[2], pl[3]);
        }
        __syncthreads();
    }
}

// ===================== final layer + fused segment-sum (16 warps) ============
__global__ __launch_bounds__(512, 1)
void layer_atomic(const __nv_bfloat16* __restrict__ inH,
                  const __nv_bfloat16* __restrict__ inL,
                  const __nv_bfloat16* __restrict__ wimg,   // [160][72] hi,lo
                  const int* __restrict__ tgt,
                  float* __restrict__ ep,
                  int M)
{
    constexpr int THREADS = 512, KT = 10, WSTR = 72;
    constexpr int SLOT = 40960;

    extern __shared__ unsigned char smem[];
    const uint32_t sbu = smem_u32(smem);
    const int tid = threadIdx.x, wid = tid >> 5, lane = tid & 31;
    const int g = lane >> 2, tg = lane & 3;
    const int warp_n = wid & 3, sub = wid >> 2;

    uint32_t pbh[KT][4], pbl[KT][4];
    {
        const ushort* WH = (const ushort*)wimg;
        const ushort* WL = WH + 160 * WSTR;
#pragma unroll
        for (int k0 = 0; k0 < KT; k0++)
#pragma unroll
            for (int nh = 0; nh < 2; nh++)
#pragma unroll
                for (int r = 0; r < 2; r++) {
                    int k = k0 * 16 + tg * 2 + r * 8;
                    int n = warp_n * 16 + nh * 8 + g;
                    pbh[k0][nh*2+r] = (uint32_t)WH[k*WSTR+n] | ((uint32_t)WH[(k+1)*WSTR+n] << 16);
                    pbl[k0][nh*2+r] = (uint32_t)WL[k*WSTR+n] | ((uint32_t)WL[(k+1)*WSTR+n] << 16);
                }
    }

    const int ntiles = (M + 63) >> 6;
    const uint4* hp = (const uint4*)inH;
    const uint4* lp = (const uint4*)inL;

    auto stage = [&](int slot, int tile) {
        if (tile < ntiles) {
            for (int i = tid; i < 2560; i += THREADS) {
                int plane = i / 1280, off = i - plane * 1280;
                const uint4* s = (plane ? lp : hp) + (size_t)tile * 1280 + off;
                cpa16(sbu + slot * SLOT + plane * 20480 + off * 16, s);
            }
        }
        CP_COMMIT();
    };

    int t0 = blockIdx.x;
    stage(0, t0);
    stage(1, t0 + gridDim.x);

    int i = 0;
    for (int t = t0; t < ntiles; t += gridDim.x, i++) {
        CP_WAIT1();
        __syncthreads();
        stage((i + 2) % 3, t + 2 * gridDim.x);

        const uint4* ap = (const uint4*)(smem + (i % 3) * SLOT);
        const size_t row0 = (size_t)t << 6;

        float acc[2][4] = {};
#pragma unroll
        for (int k0 = 0; k0 < KT; k0++) {
            uint4 a4 = ap[(k0*4 + sub)*32 + lane];
            uint4 b4 = ap[1280 + (k0*4 + sub)*32 + lane];
            uint32_t aH[4] = {a4.x, a4.y, a4.z, a4.w};
            uint32_t aL[4] = {b4.x, b4.y, b4.z, b4.w};
            mma_bf16(acc[0], aH, pbh[k0][0], pbh[k0][1]);
            mma_bf16(acc[0], aH, pbl[k0][0], pbl[k0][1]);
            mma_bf16(acc[0], aL, pbh[k0][0], pbh[k0][1]);
            mma_bf16(acc[1], aH, pbh[k0][2], pbh[k0][3]);
            mma_bf16(acc[1], aH, pbl[k0][2], pbl[k0][3]);
            mma_bf16(acc[1], aL, pbh[k0][2], pbh[k0][3]);
        }
        size_t gr0 = row0 + sub * 16 + g;
        size_t gr1 = gr0 + 8;
        int t0i = (gr0 < (size_t)M) ? __ldg(tgt + gr0) : -1;
        int t1i = (gr1 < (size_t)M) ? __ldg(tgt + gr1) : -1;
#pragma unroll
        for (int nh = 0; nh < 2; nh++) {
            int gc = warp_n * 16 + nh * 8 + tg * 2;
            if (gc < 50) {
                if (t0i >= 0) red2(ep + (size_t)t0i * 64 + gc, acc[nh][0], acc[nh][1]);
                if (t1i >= 0) red2(ep + (size_t)t1i * 64 + gc, acc[nh][2], acc[nh][3]);
            }
        }
    }
}

// ===================== SIMT GEMM (node MLP) =================================
template <int NS>
__global__ __launch_bounds__(256, 2)
void gemm_kernel(const float* __restrict__ A, int lda,
                 const float* __restrict__ W, const float* __restrict__ B,
                 float* __restrict__ C, int ldc,
                 int M, int din, int dout, int relu, int padstore)
{
    constexpr int PN = NS * 32;
    extern __shared__ float sm[];
    float* Ws = sm;
    float* Bs = Ws + ((din + 3) & ~3) * PN;
    const int tid = threadIdx.x;
    const int din4 = (din + 3) & ~3;
    for (int idx = tid; idx < din4 * PN; idx += 256) {
        int k = idx / PN, j = idx - k * PN;
        Ws[idx] = (k < din && j < dout) ? W[(size_t)k * dout + j] : 0.f;
    }
    for (int j = tid; j < PN; j += 256) Bs[j] = (j < dout) ? B[j] : 0.f;
    __syncthreads();
    const int lane = tid & 31;
    const int gwarp = blockIdx.x * 8 + (tid >> 5);
    const int nwarp = gridDim.x * 8;
    for (int sidx = gwarp; sidx < (M + 7) >> 3; sidx += nwarp) {
        const int row0 = sidx << 3;
        const float* ap[8];
#pragma unroll
        for (int r = 0; r < 8; r++) {
            int rr = row0 + r; if (rr > M - 1) rr = M - 1;
            ap[r] = A + (size_t)rr * lda;
        }
        float acc[8][NS];
#pragma unroll
        for (int r = 0; r < 8; r++)
#pragma unroll
            for (int s = 0; s < NS; s++) acc[r][s] = 0.f;
#pragma unroll 2
        for (int k = 0; k < din4; k += 4) {
            float4 a[8];
#pragma unroll
            for (int r = 0; r < 8; r++) a[r] = *(const float4*)(ap[r] + k);
#pragma unroll
            for (int kk = 0; kk < 4; kk++) {
                float wv[NS];
#pragma unroll
                for (int s = 0; s < NS; s++) wv[s] = Ws[(k + kk) * PN + lane + (s << 5)];
#pragma unroll
                for (int r = 0; r < 8; r++) {
                    float av = (kk == 0) ? a[r].x : (kk == 1) ? a[r].y : (kk == 2) ? a[r].z : a[r].w;
#pragma unroll
                    for (int s = 0; s < NS; s++) acc[r][s] = fmaf(av, wv[s], acc[r][s]);
                }
            }
        }
#pragma unroll
        for (int r = 0; r < 8; r++) {
            int row = row0 + r;
            if (row < M) {
#pragma unroll
                for (int s = 0; s < NS; s++) {
                    int j = lane + (s << 5);
                    float v = acc[r][s] + Bs[j];
                    if (relu) v = fmaxf(v, 0.f);
                    if (padstore || j < dout) C[(size_t)row * ldc + j] = v;
                }
            }
        }
    }
}

// ===================== host ==================================================
static inline size_t smbytes(int din, int PN)
{
    int din4 = (din + 3) & ~3;
    return (size_t)(din4 * PN + PN) * sizeof(float);
}

extern "C" void kernel_launch(void* const* d_in, const int* in_sizes, int n_in,
                              void* d_out, int out_size)
{
    const float* t   = (const float*)d_in[0];
    const float* x   = (const float*)d_in[1];
    const float* ofx = (const float*)d_in[2];
    const int* src   = (const int*)d_in[3];
    const int* tgt   = (const int*)d_in[4];
    const float* RW[5] = {(const float*)d_in[5], (const float*)d_in[7], (const float*)d_in[9],
                          (const float*)d_in[11], (const float*)d_in[13]};
    const float* Rb[5] = {(const float*)d_in[6], (const float*)d_in[8], (const float*)d_in[10],
                          (const float*)d_in[12], (const float*)d_in[14]};
    const float* OW0 = (const float*)d_in[15];
    const float* Ob0 = (const float*)d_in[16];
    const float* OW1 = (const float*)d_in[17];
    const float* Ob1 = (const float*)d_in[18];
    float* out = (float*)d_out;

    const int M = in_sizes[3];
    const int N = in_sizes[1] / 4;

    __nv_bfloat16 *rpH, *rpL, *Xh, *Xl, *Yh, *Yl, *wst;
    float* ep;
    cudaGetSymbolAddress((void**)&rpH, g_rpH);
    cudaGetSymbolAddress((void**)&rpL, g_rpL);
    cudaGetSymbolAddress((void**)&Xh,  g_Xh);
    cudaGetSymbolAddress((void**)&Xl,  g_Xl);
    cudaGetSymbolAddress((void**)&Yh,  g_Yh);
    cudaGetSymbolAddress((void**)&Yl,  g_Yl);
    cudaGetSymbolAddress((void**)&ep,  g_eprime);
    cudaGetSymbolAddress((void**)&wst, g_wstage);

    int nsm = 148;
    cudaDeviceGetAttribute(&nsm, cudaDevAttrMultiProcessorCount, 0);

    const int woff[5] = {0, 5376, 59136, 112896, 166656};
    const int wdin[5]  = {13, 150, 150, 150, 150};
    const int wdout[5] = {150, 150, 150, 150, 50};
    const int wKD[5]   = {16, 160, 160, 160, 160};
    const int wWSTR[5] = {168, 168, 168, 168, 72};
    const int wbrow[5] = {13, 150, 150, 150, 150};
    PrepPack pk;
    int ptotal = 0;
    for (int i = 0; i < 5; i++) {
        pk.c[i] = PrepCfg{RW[i], Rb[i], wdin[i], wdout[i], wKD[i], wWSTR[i], wbrow[i], woff[i]};
        ptotal += wKD[i] * wWSTR[i];
    }
    prep_all<<<(ptotal + 255) / 256, 256>>>(pk, wst, ptotal);

    zero_kernel<<<(N * 64 + 255) / 256, 256>>>(ep, N * 64);
    gather_kernel<<<(M + 255) / 256, 256>>>(x, ofx, src, tgt, t, rpH, rpL, M);

    const int sm01 = 81920;
    const int sm23 = 2*51200 + 40960 + 40960;     // 184320
    const int sm4  = 3 * 40960;                   // 122880
    cudaFuncSetAttribute(pair1_kernel, cudaFuncAttributeMaxDynamicSharedMemorySize, sm01);
    cudaFuncSetAttribute(pair2_kernel, cudaFuncAttributeMaxDynamicSharedMemorySize, sm23);
    cudaFuncSetAttribute(layer_atomic, cudaFuncAttributeMaxDynamicSharedMemorySize, sm4);

    pair1_kernel<<<nsm, 320, sm01>>>(rpH, rpL, wst + woff[0], wst + woff[1], Xh, Xl, M);
    pair2_kernel<<<nsm, 320, sm23>>>(Xh, Xl, wst + woff[2], wst + woff[3], Yh, Yl, M);
    layer_atomic<<<nsm, 512, sm4>>>(Yh, Yl, wst + woff[4], tgt, ep, M);

    cudaFuncSetAttribute(gemm_kernel<4>, cudaFuncAttributeMaxDynamicSharedMemorySize, 112 * 1024);
    cudaFuncSetAttribute(gemm_kernel<1>, cudaFuncAttributeMaxDynamicSharedMemorySize, 112 * 1024);
    float* nb = (float*)rpH;
    gemm_kernel<4><<<2 * nsm, 256, smbytes(50, 128)>>>(ep, 64, OW0, Ob0, nb, 128, N, 50, 100, 1, 1);
    gemm_kernel<1><<<2 * nsm, 256, smbytes(100, 32)>>>(nb, 128, OW1, Ob1, out, 4, N, 100, 4, 0, 0);
}

// round 13
// speedup vs baseline: 1.6237x; 1.0178x over previous
#include <cuda_runtime.h>
#include <cuda_bf16.h>
#include <cstdint>
#include <cstddef>

// ===================== scratch (no allocations allowed) =====================
#define MAX_EDGES 2000000
#define MAX_NODES 100000
#define SLACK 128

__device__ __align__(128) __nv_bfloat16 g_rpH[(size_t)(MAX_EDGES + SLACK) * 16];
__device__ __align__(128) __nv_bfloat16 g_rpL[(size_t)(MAX_EDGES + SLACK) * 16];
__device__ __align__(128) __nv_bfloat16 g_Xh[(size_t)(MAX_EDGES + SLACK) * 160];
__device__ __align__(128) __nv_bfloat16 g_Xl[(size_t)(MAX_EDGES + SLACK) * 160];
__device__ __align__(128) __nv_bfloat16 g_Yh[(size_t)(MAX_EDGES + SLACK) * 160];
__device__ __align__(128) __nv_bfloat16 g_Yl[(size_t)(MAX_EDGES + SLACK) * 160];
__device__ float g_eprime[(size_t)MAX_NODES * 64];
__device__ __align__(128) __nv_bfloat16 g_wstage[262144];

// ===================== low-level helpers =====================================
__device__ __forceinline__ uint32_t smem_u32(const void* p) {
    uint32_t a;
    asm("{ .reg .u64 t; cvta.to.shared.u64 t, %1; cvt.u32.u64 %0, t; }" : "=r"(a) : "l"(p));
    return a;
}
__device__ __forceinline__ void cpa16(uint32_t dst, const void* src) {
    asm volatile("cp.async.cg.shared.global [%0], [%1], 16;" :: "r"(dst), "l"(src));
}
#define CP_COMMIT() asm volatile("cp.async.commit_group;" ::: "memory")
#define CP_WAIT0()  asm volatile("cp.async.wait_group 0;" ::: "memory")
#define CP_WAIT1()  asm volatile("cp.async.wait_group 1;" ::: "memory")

__device__ __forceinline__ void mma_bf16(float* c, const uint32_t* a, uint32_t b0, uint32_t b1) {
    asm volatile(
        "mma.sync.aligned.m16n8k16.row.col.f32.bf16.bf16.f32 "
        "{%0,%1,%2,%3}, {%4,%5,%6,%7}, {%8,%9}, {%0,%1,%2,%3};"
        : "+f"(c[0]), "+f"(c[1]), "+f"(c[2]), "+f"(c[3])
        : "r"(a[0]), "r"(a[1]), "r"(a[2]), "r"(a[3]), "r"(b0), "r"(b1));
}
__device__ __forceinline__ void red2(float* gp, float v0, float v1) {
    asm volatile("red.global.add.v2.f32 [%0], {%1, %2};" :: "l"(gp), "f"(v0), "f"(v1) : "memory");
}
__device__ __forceinline__ void split2(float v0, float v1, uint32_t& hi, uint32_t& lo) {
    __nv_bfloat16 h0 = __float2bfloat16(v0), h1 = __float2bfloat16(v1);
    __nv_bfloat16 l0 = __float2bfloat16(v0 - __bfloat162float(h0));
    __nv_bfloat16 l1 = __float2bfloat16(v1 - __bfloat162float(h1));
    hi = (uint32_t)__bfloat16_as_ushort(h0) | ((uint32_t)__bfloat16_as_ushort(h1) << 16);
    lo = (uint32_t)__bfloat16_as_ushort(l0) | ((uint32_t)__bfloat16_as_ushort(l1) << 16);
}

// pack acc -> hi/lo uint4 with relu + onecol
__device__ __forceinline__ void pack_epi(const float* a0, const float* a1, int slice, int tg,
                                         uint4& hv, uint4& lv) {
    uint32_t ph[4], pl[4];
#pragma unroll
    for (int nh = 0; nh < 2; nh++) {
        const float* a = nh ? a1 : a0;
        float v0 = fmaxf(a[0], 0.f);
        float v1 = fmaxf(a[1], 0.f);
        float v2 = fmaxf(a[2], 0.f);
        float v3 = fmaxf(a[3], 0.f);
        int gc = slice * 16 + nh * 8 + tg * 2;
        if (gc == 150)     { v0 = 1.f; v2 = 1.f; }
        if (gc + 1 == 150) { v1 = 1.f; v3 = 1.f; }
        split2(v0, v1, ph[nh*2],   pl[nh*2]);
        split2(v2, v3, ph[nh*2+1], pl[nh*2+1]);
    }
    hv = make_uint4(ph[0], ph[1], ph[2], ph[3]);
    lv = make_uint4(pl[0], pl[1], pl[2], pl[3]);
}

// ===================== merged weight prep ====================================
struct PrepCfg {
    const float* W; const float* b;
    int din, dout, KD, WSTR, brow, off;
};
struct PrepPack { PrepCfg c[5]; };

__global__ void prep_all(PrepPack p, __nv_bfloat16* __restrict__ wst, int total)
{
    int idx = blockIdx.x * blockDim.x + threadIdx.x;
    if (idx >= total) return;
#pragma unroll
    for (int L = 0; L < 5; L++) {
        int tot = p.c[L].KD * p.c[L].WSTR;
        if (idx < tot) {
            int k = idx / p.c[L].WSTR, n = idx - k * p.c[L].WSTR;
            float v = 0.f;
            if (n < p.c[L].dout) {
                if (k < p.c[L].din) v = p.c[L].W[(size_t)k * p.c[L].dout + n];
                else if (k == p.c[L].brow) v = p.c[L].b[n];
            }
            __nv_bfloat16 h = __float2bfloat16(v);
            __nv_bfloat16 l = __float2bfloat16(v - __bfloat162float(h));
            wst[p.c[L].off + idx] = h;
            wst[p.c[L].off + tot + idx] = l;
            return;
        }
        idx -= tot;
    }
}

// B fragment gather from weight image (ushort layout [KD][WSTR], hi then lo)
__device__ __forceinline__ void wfrag(const ushort* WH, const ushort* WL, int WSTR,
                                      int k0, int slice, int g, int tg,
                                      uint32_t* bh, uint32_t* bl) {
#pragma unroll
    for (int nh = 0; nh < 2; nh++)
#pragma unroll
        for (int r = 0; r < 2; r++) {
            int k = k0 * 16 + tg * 2 + r * 8;
            int n = slice * 16 + nh * 8 + g;
            bh[nh*2+r] = (uint32_t)WH[k*WSTR+n] | ((uint32_t)WH[(k+1)*WSTR+n] << 16);
            bl[nh*2+r] = (uint32_t)WL[k*WSTR+n] | ((uint32_t)WL[(k+1)*WSTR+n] << 16);
        }
}

// ===================== gather ================================================
__global__ void gather_kernel(const float* __restrict__ x,
                              const float* __restrict__ ofx,
                              const int* __restrict__ src,
                              const int* __restrict__ tgt,
                              const float* __restrict__ t,
                              __nv_bfloat16* __restrict__ oh,
                              __nv_bfloat16* __restrict__ ol, int M)
{
    int e = blockIdx.x * blockDim.x + threadIdx.x;
    if (e >= M) return;
    int s = src[e], g = tgt[e];
    float v[16];
    float4 xs = *(const float4*)(x + (size_t)4 * s);
    float2 os = *(const float2*)(ofx + (size_t)2 * s);
    float4 xt = *(const float4*)(x + (size_t)4 * g);
    float2 ot = *(const float2*)(ofx + (size_t)2 * g);
    v[0]=xs.x; v[1]=xs.y; v[2]=xs.z; v[3]=xs.w; v[4]=os.x; v[5]=os.y;
    v[6]=xt.x; v[7]=xt.y; v[8]=xt.z; v[9]=xt.w; v[10]=ot.x; v[11]=ot.y;
    v[12]=t[0]; v[13]=1.0f; v[14]=0.f; v[15]=0.f;
    uint32_t wh[8], wl[8];
#pragma unroll
    for (int i = 0; i < 8; i++) split2(v[2*i], v[2*i+1], wh[i], wl[i]);
    uint4* ph = (uint4*)(oh + (size_t)e * 16);
    uint4* pl = (uint4*)(ol + (size_t)e * 16);
    ph[0] = make_uint4(wh[0], wh[1], wh[2], wh[3]);
    ph[1] = make_uint4(wh[4], wh[5], wh[6], wh[7]);
    pl[0] = make_uint4(wl[0], wl[1], wl[2], wl[3]);
    pl[1] = make_uint4(wl[4], wl[5], wl[6], wl[7]);
}

__global__ void zero_kernel(float* __restrict__ p, int n)
{
    int i = blockIdx.x * blockDim.x + threadIdx.x;
    if (i < n) p[i] = 0.f;
}

// ===================== pair1: L0+L1 fused, 8 warps balanced ==================
__global__ __launch_bounds__(256, 1)
void pair1_kernel(const __nv_bfloat16* __restrict__ rpH,
                  const __nv_bfloat16* __restrict__ rpL,
                  const __nv_bfloat16* __restrict__ w1img,   // [16][168] hi,lo
                  const __nv_bfloat16* __restrict__ w2img,   // [160][168] hi,lo
                  __nv_bfloat16* __restrict__ outH,
                  __nv_bfloat16* __restrict__ outL,
                  int M)
{
    constexpr int WSTR = 168;
    extern __shared__ unsigned char smem[];
    uint4* INT = (uint4*)smem;                     // 2 bufs x 2560 uint4
    uint4* SB2 = (uint4*)(smem + 81920);           // [2][10][32] hi, +640 lo

    const int tid = threadIdx.x, wid = tid >> 5, lane = tid & 31;
    const int g = lane >> 2, tg = lane & 3;
    const int ss = 8 + (wid >> 2);                 // shared slice (8 or 9)
    const int su = wid & 3;                        // shared sub

    const ushort* W1H = (const ushort*)w1img;
    const ushort* W1L = W1H + 16 * WSTR;
    const ushort* W2H = (const ushort*)w2img;
    const ushort* W2L = W2H + 160 * WSTR;

    // B1 regs: main slice (wid) + shared slice (ss)
    uint32_t b1hm[4], b1lm[4], b1hs[4], b1ls[4];
    wfrag(W1H, W1L, WSTR, 0, wid, g, tg, b1hm, b1lm);
    wfrag(W1H, W1L, WSTR, 0, ss,  g, tg, b1hs, b1ls);

    // B2 regs: main slice
    uint32_t pbh[10][4], pbl[10][4];
#pragma unroll
    for (int k0 = 0; k0 < 10; k0++)
        wfrag(W2H, W2L, WSTR, k0, wid, g, tg, pbh[k0], pbl[k0]);

    // SB2 cache: warp 0 -> slice 8, warp 1 -> slice 9
    if (wid < 2) {
        int slice = 8 + wid;
        for (int k0 = 0; k0 < 10; k0++) {
            uint32_t bh[4], bl[4];
            wfrag(W2H, W2L, WSTR, k0, slice, g, tg, bh, bl);
            SB2[(wid*10 + k0)*32 + lane]       = make_uint4(bh[0], bh[1], bh[2], bh[3]);
            SB2[640 + (wid*10 + k0)*32 + lane] = make_uint4(bl[0], bl[1], bl[2], bl[3]);
        }
    }
    __syncthreads();

    const int ntiles = (M + 63) >> 6;

    uint32_t pAH[4][4], pAL[4][4];   // A frags for all 4 subs
    auto loadA = [&](int tile) {
        const int row0 = tile << 6;
#pragma unroll
        for (int sub = 0; sub < 4; sub++) {
            int r0 = row0 + sub * 16 + g;
            int r1 = r0 + 8;
            if (r0 > M - 1) r0 = M - 1;
            if (r1 > M - 1) r1 = M - 1;
            const __nv_bfloat16* h0p = rpH + (size_t)r0 * 16 + tg * 2;
            const __nv_bfloat16* h1p = rpH + (size_t)r1 * 16 + tg * 2;
            const __nv_bfloat16* l0p = rpL + (size_t)r0 * 16 + tg * 2;
            const __nv_bfloat16* l1p = rpL + (size_t)r1 * 16 + tg * 2;
            pAH[sub][0] = *(const uint32_t*)h0p;
            pAH[sub][1] = *(const uint32_t*)h1p;
            pAH[sub][2] = *(const uint32_t*)(h0p + 8);
            pAH[sub][3] = *(const uint32_t*)(h1p + 8);
            pAL[sub][0] = *(const uint32_t*)l0p;
            pAL[sub][1] = *(const uint32_t*)l1p;
            pAL[sub][2] = *(const uint32_t*)(l0p + 8);
            pAL[sub][3] = *(const uint32_t*)(l1p + 8);
        }
    };

    auto g1 = [&](int buf) {
        uint4* ih = INT + buf * 2560;
#pragma unroll
        for (int sub = 0; sub < 4; sub++) {
            float acc[2][4] = {};
            mma_bf16(acc[0], pAH[sub], b1hm[0], b1hm[1]);
            mma_bf16(acc[0], pAH[sub], b1lm[0], b1lm[1]);
            mma_bf16(acc[0], pAL[sub], b1hm[0], b1hm[1]);
            mma_bf16(acc[1], pAH[sub], b1hm[2], b1hm[3]);
            mma_bf16(acc[1], pAH[sub], b1lm[2], b1lm[3]);
            mma_bf16(acc[1], pAL[sub], b1hm[2], b1hm[3]);
            uint4 hv, lv;
            pack_epi(acc[0], acc[1], wid, tg, hv, lv);
            ih[(wid*4 + sub)*32 + lane]        = hv;
            ih[1280 + (wid*4 + sub)*32 + lane] = lv;
        }
        {   // shared unit (slice ss, sub su)
            float acc[2][4] = {};
            mma_bf16(acc[0], pAH[su], b1hs[0], b1hs[1]);
            mma_bf16(acc[0], pAH[su], b1ls[0], b1ls[1]);
            mma_bf16(acc[0], pAL[su], b1hs[0], b1hs[1]);
            mma_bf16(acc[1], pAH[su], b1hs[2], b1hs[3]);
            mma_bf16(acc[1], pAH[su], b1ls[2], b1ls[3]);
            mma_bf16(acc[1], pAL[su], b1hs[2], b1hs[3]);
            uint4 hv, lv;
            pack_epi(acc[0], acc[1], ss, tg, hv, lv);
            ih[(ss*4 + su)*32 + lane]        = hv;
            ih[1280 + (ss*4 + su)*32 + lane] = lv;
        }
    };

    auto g2 = [&](int tile, int buf) {
        const uint4* ip = INT + buf * 2560;
        uint4* oh = (uint4*)outH;
        uint4* ol = (uint4*)outL;
#pragma unroll
        for (int sub = 0; sub < 4; sub++) {
            float acc[2][4] = {};
#pragma unroll
            for (int k0 = 0; k0 < 10; k0++) {
                uint4 a4 = ip[(k0*4 + sub)*32 + lane];
                uint4 b4 = ip[1280 + (k0*4 + sub)*32 + lane];
                uint32_t aH[4] = {a4.x, a4.y, a4.z, a4.w};
                uint32_t aL[4] = {b4.x, b4.y, b4.z, b4.w};
                mma_bf16(acc[0], aH, pbh[k0][0], pbh[k0][1]);
                mma_bf16(acc[0], aH, pbl[k0][0], pbl[k0][1]);
                mma_bf16(acc[0], aL, pbh[k0][0], pbh[k0][1]);
                mma_bf16(acc[1], aH, pbh[k0][2], pbh[k0][3]);
                mma_bf16(acc[1], aH, pbl[k0][2], pbl[k0][3]);
                mma_bf16(acc[1], aL, pbh[k0][2], pbh[k0][3]);
            }
            uint4 hv, lv;
            pack_epi(acc[0], acc[1], wid, tg, hv, lv);
            size_t base = ((size_t)tile * 40 + wid * 4 + sub) * 32 + lane;
            oh[base] = hv;
            ol[base] = lv;
        }
        {   // shared unit
            float acc[2][4] = {};
            const int sc = ss - 8;
#pragma unroll
            for (int k0 = 0; k0 < 10; k0++) {
                uint4 a4 = ip[(k0*4 + su)*32 + lane];
                uint4 b4 = ip[1280 + (k0*4 + su)*32 + lane];
                uint32_t aH[4] = {a4.x, a4.y, a4.z, a4.w};
                uint32_t aL[4] = {b4.x, b4.y, b4.z, b4.w};
                uint4 h4 = SB2[(sc*10 + k0)*32 + lane];
                uint4 l4 = SB2[640 + (sc*10 + k0)*32 + lane];
                mma_bf16(acc[0], aH, h4.x, h4.y);
                mma_bf16(acc[0], aH, l4.x, l4.y);
                mma_bf16(acc[0], aL, h4.x, h4.y);
                mma_bf16(acc[1], aH, h4.z, h4.w);
                mma_bf16(acc[1], aH, l4.z, l4.w);
                mma_bf16(acc[1], aL, h4.z, h4.w);
            }
            uint4 hv, lv;
            pack_epi(acc[0], acc[1], ss, tg, hv, lv);
            size_t base = ((size_t)tile * 40 + ss * 4 + su) * 32 + lane;
            oh[base] = hv;
            ol[base] = lv;
        }
    };

    int t = blockIdx.x;
    if (t < ntiles) { loadA(t); g1(0); }
    int i = 0;
    for (; t < ntiles; t += gridDim.x, i++) {
        int nxt = t + gridDim.x;
        if (nxt < ntiles) loadA(nxt);
        __syncthreads();
        g2(t, i & 1);
        if (nxt < ntiles) g1((i + 1) & 1);
    }
}

// ===================== pair2: L2+L3, 8 warps balanced ========================
__global__ __launch_bounds__(256, 1)
void pair2_kernel(const __nv_bfloat16* __restrict__ inH,
                  const __nv_bfloat16* __restrict__ inL,
                  const __nv_bfloat16* __restrict__ w1img,
                  const __nv_bfloat16* __restrict__ w2img,
                  __nv_bfloat16* __restrict__ outH,
                  __nv_bfloat16* __restrict__ outL,
                  int M)
{
    constexpr int THREADS = 256, KT = 10, WSTR = 168;
    constexpr int S1 = 10 * KT * 512;              // 51200 B per plane
    constexpr int OFF_SB2 = 2 * S1;                // 20480 B
    constexpr int OFF_A = OFF_SB2 + 20480;         // 40960 B
    constexpr int OFF_INT = OFF_A + 40960;         // 40960 B

    extern __shared__ unsigned char smem[];
    const uint32_t sbu = smem_u32(smem);
    const int tid = threadIdx.x, wid = tid >> 5, lane = tid & 31;
    const int g = lane >> 2, tg = lane & 3;
    const int ss = 8 + (wid >> 2), su = wid & 3;

    const ushort* W1H = (const ushort*)w1img;
    const ushort* W1L = W1H + 160 * WSTR;
    const ushort* W2H = (const ushort*)w2img;
    const ushort* W2L = W2H + 160 * WSTR;

    // B1 cache: all 10 slices (warp w builds slices w, w+8)
    {
        uint4* ch = (uint4*)(smem);
        uint4* cl = (uint4*)(smem + S1);
        for (int s = wid; s < 10; s += 8) {
            for (int k0 = 0; k0 < KT; k0++) {
                uint32_t bh[4], bl[4];
                wfrag(W1H, W1L, WSTR, k0, s, g, tg, bh, bl);
                ch[(s*KT + k0)*32 + lane] = make_uint4(bh[0], bh[1], bh[2], bh[3]);
                cl[(s*KT + k0)*32 + lane] = make_uint4(bl[0], bl[1], bl[2], bl[3]);
            }
        }
    }
    // SB2 cache: slices 8,9 (warps 0,1)
    if (wid < 2) {
        uint4* sb = (uint4*)(smem + OFF_SB2);
        int slice = 8 + wid;
        for (int k0 = 0; k0 < KT; k0++) {
            uint32_t bh[4], bl[4];
            wfrag(W2H, W2L, WSTR, k0, slice, g, tg, bh, bl);
            sb[(wid*KT + k0)*32 + lane]       = make_uint4(bh[0], bh[1], bh[2], bh[3]);
            sb[640 + (wid*KT + k0)*32 + lane] = make_uint4(bl[0], bl[1], bl[2], bl[3]);
        }
    }
    // B2 regs: main slice
    uint32_t pbh[KT][4], pbl[KT][4];
#pragma unroll
    for (int k0 = 0; k0 < KT; k0++)
        wfrag(W2H, W2L, WSTR, k0, wid, g, tg, pbh[k0], pbl[k0]);
    __syncthreads();

    const uint4* c1h = (const uint4*)(smem);
    const uint4* c1l = (const uint4*)(smem + S1);
    const uint4* sb2 = (const uint4*)(smem + OFF_SB2);
    const int ntiles = (M + 63) >> 6;

    auto stage = [&](int tile) {
        const uint4* hp = (const uint4*)inH;
        const uint4* lp = (const uint4*)inL;
        for (int i = tid; i < 2560; i += THREADS) {
            int plane = i / 1280, off = i - plane * 1280;
            const uint4* s = (plane ? lp : hp) + (size_t)tile * 1280 + off;
            cpa16(sbu + OFF_A + plane * 20480 + off * 16, s);
        }
        CP_COMMIT();
    };

    int tile = blockIdx.x;
    if (tile < ntiles) stage(tile);

    for (; tile < ntiles; tile += gridDim.x) {
        CP_WAIT0();
        __syncthreads();

        // ---- G1 main: slice wid, all 4 subs (k0-outer, B hoisted) -----------
        {
            const uint4* ap = (const uint4*)(smem + OFF_A);
            float acc[4][2][4] = {};
#pragma unroll
            for (int k0 = 0; k0 < KT; k0++) {
                uint4 h4 = c1h[(wid*KT + k0)*32 + lane];
                uint4 l4 = c1l[(wid*KT + k0)*32 + lane];
#pragma unroll
                for (int sub = 0; sub < 4; sub++) {
                    uint4 a4 = ap[(k0*4 + sub)*32 + lane];
                    uint4 b4 = ap[1280 + (k0*4 + sub)*32 + lane];
                    uint32_t aH[4] = {a4.x, a4.y, a4.z, a4.w};
                    uint32_t aL[4] = {b4.x, b4.y, b4.z, b4.w};
                    mma_bf16(acc[sub][0], aH, h4.x, h4.y);
                    mma_bf16(acc[sub][0], aH, l4.x, l4.y);
                    mma_bf16(acc[sub][0], aL, h4.x, h4.y);
                    mma_bf16(acc[sub][1], aH, h4.z, h4.w);
                    mma_bf16(acc[sub][1], aH, l4.z, l4.w);
                    mma_bf16(acc[sub][1], aL, h4.z, h4.w);
                }
            }
            uint4* ih = (uint4*)(smem + OFF_INT);
#pragma unroll
            for (int sub = 0; sub < 4; sub++) {
                uint4 hv, lv;
                pack_epi(acc[sub][0], acc[sub][1], wid, tg, hv, lv);
                ih[(wid*4 + sub)*32 + lane]        = hv;
                ih[1280 + (wid*4 + sub)*32 + lane] = lv;
            }
        }
        // ---- G1 shared: slice ss, sub su -------------------------------------
        {
            const uint4* ap = (const uint4*)(smem + OFF_A);
            float acc[2][4] = {};
#pragma unroll
            for (int k0 = 0; k0 < KT; k0++) {
                uint4 h4 = c1h[(ss*KT + k0)*32 + lane];
                uint4 l4 = c1l[(ss*KT + k0)*32 + lane];
                uint4 a4 = ap[(k0*4 + su)*32 + lane];
                uint4 b4 = ap[1280 + (k0*4 + su)*32 + lane];
                uint32_t aH[4] = {a4.x, a4.y, a4.z, a4.w};
                uint32_t aL[4] = {b4.x, b4.y, b4.z, b4.w};
                mma_bf16(acc[0], aH, h4.x, h4.y);
                mma_bf16(acc[0], aH, l4.x, l4.y);
                mma_bf16(acc[0], aL, h4.x, h4.y);
                mma_bf16(acc[1], aH, h4.z, h4.w);
                mma_bf16(acc[1], aH, l4.z, l4.w);
                mma_bf16(acc[1], aL, h4.z, h4.w);
            }
            uint4* ih = (uint4*)(smem + OFF_INT);
            uint4 hv, lv;
            pack_epi(acc[0], acc[1], ss, tg, hv, lv);
            ih[(ss*4 + su)*32 + lane]        = hv;
            ih[1280 + (ss*4 + su)*32 + lane] = lv;
        }
        __syncthreads();

        int nxt = tile + gridDim.x;
        if (nxt < ntiles) stage(nxt);

        // ---- G2 main + shared -------------------------------------------------
        const uint4* ip = (const uint4*)(smem + OFF_INT);
        uint4* oh = (uint4*)outH;
        uint4* ol = (uint4*)outL;
#pragma unroll
        for (int sub = 0; sub < 4; sub++) {
            float acc[2][4] = {};
#pragma unroll
            for (int k0 = 0; k0 < KT; k0++) {
                uint4 a4 = ip[(k0*4 + sub)*32 + lane];
                uint4 b4 = ip[1280 + (k0*4 + sub)*32 + lane];
                uint32_t aH[4] = {a4.x, a4.y, a4.z, a4.w};
                uint32_t aL[4] = {b4.x, b4.y, b4.z, b4.w};
                mma_bf16(acc[0], aH, pbh[k0][0], pbh[k0][1]);
                mma_bf16(acc[0], aH, pbl[k0][0], pbl[k0][1]);
                mma_bf16(acc[0], aL, pbh[k0][0], pbh[k0][1]);
                mma_bf16(acc[1], aH, pbh[k0][2], pbh[k0][3]);
                mma_bf16(acc[1], aH, pbl[k0][2], pbl[k0][3]);
                mma_bf16(acc[1], aL, pbh[k0][2], pbh[k0][3]);
            }
            uint4 hv, lv;
            pack_epi(acc[0], acc[1], wid, tg, hv, lv);
            size_t base = ((size_t)tile * 40 + wid * 4 + sub) * 32 + lane;
            oh[base] = hv;
            ol[base] = lv;
        }
        {
            float acc[2][4] = {};
            const int sc = ss - 8;
#pragma unroll
            for (int k0 = 0; k0 < KT; k0++) {
                uint4 a4 = ip[(k0*4 + su)*32 + lane];
                uint4 b4 = ip[1280 + (k0*4 + su)*32 + lane];
                uint32_t aH[4] = {a4.x, a4.y, a4.z, a4.w};
                uint32_t aL[4] = {b4.x, b4.y, b4.z, b4.w};
                uint4 h4 = sb2[(sc*KT + k0)*32 + lane];
                uint4 l4 = sb2[640 + (sc*KT + k0)*32 + lane];
                mma_bf16(acc[0], aH, h4.x, h4.y);
                mma_bf16(acc[0], aH, l4.x, l4.y);
                mma_bf16(acc[0], aL, h4.x, h4.y);
                mma_bf16(acc[1], aH, h4.z, h4.w);
                mma_bf16(acc[1], aH, l4.z, l4.w);
                mma_bf16(acc[1], aL, h4.z, h4.w);
            }
            uint4 hv, lv;
            pack_epi(acc[0], acc[1], ss, tg, hv, lv);
            size_t base = ((size_t)tile * 40 + ss * 4 + su) * 32 + lane;
            oh[base] = hv;
            ol[base] = lv;
        }
        __syncthreads();
    }
}

// ===================== final layer + fused segment-sum (16 warps) ============
__global__ __launch_bounds__(512, 1)
void layer_atomic(const __nv_bfloat16* __restrict__ inH,
                  const __nv_bfloat16* __restrict__ inL,
                  const __nv_bfloat16* __restrict__ wimg,   // [160][72] hi,lo
                  const int* __restrict__ tgt,
                  float* __restrict__ ep,
                  int M)
{
    constexpr int THREADS = 512, KT = 10, WSTR = 72;
    constexpr int SLOT = 40960;

    extern __shared__ unsigned char smem[];
    const uint32_t sbu = smem_u32(smem);
    const int tid = threadIdx.x, wid = tid >> 5, lane = tid & 31;
    const int g = lane >> 2, tg = lane & 3;
    const int warp_n = wid & 3, sub = wid >> 2;

    uint32_t pbh[KT][4], pbl[KT][4];
    {
        const ushort* WH = (const ushort*)wimg;
        const ushort* WL = WH + 160 * WSTR;
#pragma unroll
        for (int k0 = 0; k0 < KT; k0++)
            wfrag(WH, WL, WSTR, k0, warp_n, g, tg, pbh[k0], pbl[k0]);
    }

    const int ntiles = (M + 63) >> 6;
    const uint4* hp = (const uint4*)inH;
    const uint4* lp = (const uint4*)inL;

    auto stage = [&](int slot, int tile) {
        if (tile < ntiles) {
            for (int i = tid; i < 2560; i += THREADS) {
                int plane = i / 1280, off = i - plane * 1280;
                const uint4* s = (plane ? lp : hp) + (size_t)tile * 1280 + off;
                cpa16(sbu + slot * SLOT + plane * 20480 + off * 16, s);
            }
        }
        CP_COMMIT();
    };

    int t0 = blockIdx.x;
    stage(0, t0);
    stage(1, t0 + gridDim.x);

    int i = 0;
    for (int t = t0; t < ntiles; t += gridDim.x, i++) {
        CP_WAIT1();
        __syncthreads();
        stage((i + 2) % 3, t + 2 * gridDim.x);

        const uint4* ap = (const uint4*)(smem + (i % 3) * SLOT);
        const size_t row0 = (size_t)t << 6;

        float acc[2][4] = {};
#pragma unroll
        for (int k0 = 0; k0 < KT; k0++) {
            uint4 a4 = ap[(k0*4 + sub)*32 + lane];
            uint4 b4 = ap[1280 + (k0*4 + sub)*32 + lane];
            uint32_t aH[4] = {a4.x, a4.y, a4.z, a4.w};
            uint32_t aL[4] = {b4.x, b4.y, b4.z, b4.w};
            mma_bf16(acc[0], aH, pbh[k0][0], pbh[k0][1]);
            mma_bf16(acc[0], aH, pbl[k0][0], pbl[k0][1]);
            mma_bf16(acc[0], aL, pbh[k0][0], pbh[k0][1]);
            mma_bf16(acc[1], aH, pbh[k0][2], pbh[k0][3]);
            mma_bf16(acc[1], aH, pbl[k0][2], pbl[k0][3]);
            mma_bf16(acc[1], aL, pbh[k0][2], pbh[k0][3]);
        }
        size_t gr0 = row0 + sub * 16 + g;
        size_t gr1 = gr0 + 8;
        int t0i = (gr0 < (size_t)M) ? __ldg(tgt + gr0) : -1;
        int t1i = (gr1 < (size_t)M) ? __ldg(tgt + gr1) : -1;
#pragma unroll
        for (int nh = 0; nh < 2; nh++) {
            int gc = warp_n * 16 + nh * 8 + tg * 2;
            if (gc < 50) {
                if (t0i >= 0) red2(ep + (size_t)t0i * 64 + gc, acc[nh][0], acc[nh][1]);
                if (t1i >= 0) red2(ep + (size_t)t1i * 64 + gc, acc[nh][2], acc[nh][3]);
            }
        }
    }
}

// ===================== SIMT GEMM (node MLP) =================================
template <int NS>
__global__ __launch_bounds__(256, 2)
void gemm_kernel(const float* __restrict__ A, int lda,
                 const float* __restrict__ W, const float* __restrict__ B,
                 float* __restrict__ C, int ldc,
                 int M, int din, int dout, int relu, int padstore)
{
    constexpr int PN = NS * 32;
    extern __shared__ float sm[];
    float* Ws = sm;
    float* Bs = Ws + ((din + 3) & ~3) * PN;
    const int tid = threadIdx.x;
    const int din4 = (din + 3) & ~3;
    for (int idx = tid; idx < din4 * PN; idx += 256) {
        int k = idx / PN, j = idx - k * PN;
        Ws[idx] = (k < din && j < dout) ? W[(size_t)k * dout + j] : 0.f;
    }
    for (int j = tid; j < PN; j += 256) Bs[j] = (j < dout) ? B[j] : 0.f;
    __syncthreads();
    const int lane = tid & 31;
    const int gwarp = blockIdx.x * 8 + (tid >> 5);
    const int nwarp = gridDim.x * 8;
    for (int sidx = gwarp; sidx < (M + 7) >> 3; sidx += nwarp) {
        const int row0 = sidx << 3;
        const float* ap[8];
#pragma unroll
        for (int r = 0; r < 8; r++) {
            int rr = row0 + r; if (rr > M - 1) rr = M - 1;
            ap[r] = A + (size_t)rr * lda;
        }
        float acc[8][NS];
#pragma unroll
        for (int r = 0; r < 8; r++)
#pragma unroll
            for (int s = 0; s < NS; s++) acc[r][s] = 0.f;
#pragma unroll 2
        for (int k = 0; k < din4; k += 4) {
            float4 a[8];
#pragma unroll
            for (int r = 0; r < 8; r++) a[r] = *(const float4*)(ap[r] + k);
#pragma unroll
            for (int kk = 0; kk < 4; kk++) {
                float wv[NS];
#pragma unroll
                for (int s = 0; s < NS; s++) wv[s] = Ws[(k + kk) * PN + lane + (s << 5)];
#pragma unroll
                for (int r = 0; r < 8; r++) {
                    float av = (kk == 0) ? a[r].x : (kk == 1) ? a[r].y : (kk == 2) ? a[r].z : a[r].w;
#pragma unroll
                    for (int s = 0; s < NS; s++) acc[r][s] = fmaf(av, wv[s], acc[r][s]);
                }
            }
        }
#pragma unroll
        for (int r = 0; r < 8; r++) {
            int row = row0 + r;
            if (row < M) {
#pragma unroll
                for (int s = 0; s < NS; s++) {
                    int j = lane + (s << 5);
                    float v = acc[r][s] + Bs[j];
                    if (relu) v = fmaxf(v, 0.f);
                    if (padstore || j < dout) C[(size_t)row * ldc + j] = v;
                }
            }
        }
    }
}

// ===================== host ==================================================
static inline size_t smbytes(int din, int PN)
{
    int din4 = (din + 3) & ~3;
    return (size_t)(din4 * PN + PN) * sizeof(float);
}

extern "C" void kernel_launch(void* const* d_in, const int* in_sizes, int n_in,
                              void* d_out, int out_size)
{
    const float* t   = (const float*)d_in[0];
    const float* x   = (const float*)d_in[1];
    const float* ofx = (const float*)d_in[2];
    const int* src   = (const int*)d_in[3];
    const int* tgt   = (const int*)d_in[4];
    const float* RW[5] = {(const float*)d_in[5], (const float*)d_in[7], (const float*)d_in[9],
                          (const float*)d_in[11], (const float*)d_in[13]};
    const float* Rb[5] = {(const float*)d_in[6], (const float*)d_in[8], (const float*)d_in[10],
                          (const float*)d_in[12], (const float*)d_in[14]};
    const float* OW0 = (const float*)d_in[15];
    const float* Ob0 = (const float*)d_in[16];
    const float* OW1 = (const float*)d_in[17];
    const float* Ob1 = (const float*)d_in[18];
    float* out = (float*)d_out;

    const int M = in_sizes[3];
    const int N = in_sizes[1] / 4;

    __nv_bfloat16 *rpH, *rpL, *Xh, *Xl, *Yh, *Yl, *wst;
    float* ep;
    cudaGetSymbolAddress((void**)&rpH, g_rpH);
    cudaGetSymbolAddress((void**)&rpL, g_rpL);
    cudaGetSymbolAddress((void**)&Xh,  g_Xh);
    cudaGetSymbolAddress((void**)&Xl,  g_Xl);
    cudaGetSymbolAddress((void**)&Yh,  g_Yh);
    cudaGetSymbolAddress((void**)&Yl,  g_Yl);
    cudaGetSymbolAddress((void**)&ep,  g_eprime);
    cudaGetSymbolAddress((void**)&wst, g_wstage);

    int nsm = 148;
    cudaDeviceGetAttribute(&nsm, cudaDevAttrMultiProcessorCount, 0);

    const int woff[5] = {0, 5376, 59136, 112896, 166656};
    const int wdin[5]  = {13, 150, 150, 150, 150};
    const int wdout[5] = {150, 150, 150, 150, 50};
    const int wKD[5]   = {16, 160, 160, 160, 160};
    const int wWSTR[5] = {168, 168, 168, 168, 72};
    const int wbrow[5] = {13, 150, 150, 150, 150};
    PrepPack pk;
    int ptotal = 0;
    for (int i = 0; i < 5; i++) {
        pk.c[i] = PrepCfg{RW[i], Rb[i], wdin[i], wdout[i], wKD[i], wWSTR[i], wbrow[i], woff[i]};
        ptotal += wKD[i] * wWSTR[i];
    }
    prep_all<<<(ptotal + 255) / 256, 256>>>(pk, wst, ptotal);

    zero_kernel<<<(N * 64 + 255) / 256, 256>>>(ep, N * 64);
    gather_kernel<<<(M + 255) / 256, 256>>>(x, ofx, src, tgt, t, rpH, rpL, M);

    const int sm01 = 81920 + 20480;                         // 102400
    const int sm23 = 2*51200 + 20480 + 40960 + 40960;       // 204800
    const int sm4  = 3 * 40960;                             // 122880
    cudaFuncSetAttribute(pair1_kernel, cudaFuncAttributeMaxDynamicSharedMemorySize, sm01);
    cudaFuncSetAttribute(pair2_kernel, cudaFuncAttributeMaxDynamicSharedMemorySize, sm23);
    cudaFuncSetAttribute(layer_atomic, cudaFuncAttributeMaxDynamicSharedMemorySize, sm4);

    pair1_kernel<<<nsm, 256, sm01>>>(rpH, rpL, wst + woff[0], wst + woff[1], Xh, Xl, M);
    pair2_kernel<<<nsm, 256, sm23>>>(Xh, Xl, wst + woff[2], wst + woff[3], Yh, Yl, M);
    layer_atomic<<<nsm, 512, sm4>>>(Yh, Yl, wst + woff[4], tgt, ep, M);

    cudaFuncSetAttribute(gemm_kernel<4>, cudaFuncAttributeMaxDynamicSharedMemorySize, 112 * 1024);
    cudaFuncSetAttribute(gemm_kernel<1>, cudaFuncAttributeMaxDynamicSharedMemorySize, 112 * 1024);
    float* nb = (float*)rpH;
    gemm_kernel<4><<<2 * nsm, 256, smbytes(50, 128)>>>(ep, 64, OW0, Ob0, nb, 128, N, 50, 100, 1, 1);
    gemm_kernel<1><<<2 * nsm, 256, smbytes(100, 32)>>>(nb, 128, OW1, Ob1, out, 4, N, 100, 4, 0, 0);
}

// round 14
// speedup vs baseline: 1.6500x; 1.0162x over previous
#include <cuda_runtime.h>
#include <cuda_bf16.h>
#include <cstdint>
#include <cstddef>

// ===================== scratch (no allocations allowed) =====================
#define MAX_EDGES 2000000
#define MAX_NODES 100000
#define SLACK 128

__device__ __align__(128) __nv_bfloat16 g_rpH[(size_t)(MAX_EDGES + SLACK) * 16];
__device__ __align__(128) __nv_bfloat16 g_rpL[(size_t)(MAX_EDGES + SLACK) * 16];
__device__ __align__(128) __nv_bfloat16 g_Xh[(size_t)(MAX_EDGES + SLACK) * 160];
__device__ __align__(128) __nv_bfloat16 g_Xl[(size_t)(MAX_EDGES + SLACK) * 160];
__device__ __align__(128) __nv_bfloat16 g_Yh[(size_t)(MAX_EDGES + SLACK) * 160];
__device__ __align__(128) __nv_bfloat16 g_Yl[(size_t)(MAX_EDGES + SLACK) * 160];
__device__ float g_eprime[(size_t)MAX_NODES * 64];
__device__ __align__(128) __nv_bfloat16 g_wstage[262144];

// ===================== low-level helpers =====================================
__device__ __forceinline__ uint32_t smem_u32(const void* p) {
    uint32_t a;
    asm("{ .reg .u64 t; cvta.to.shared.u64 t, %1; cvt.u32.u64 %0, t; }" : "=r"(a) : "l"(p));
    return a;
}
__device__ __forceinline__ void cpa16(uint32_t dst, const void* src) {
    asm volatile("cp.async.cg.shared.global [%0], [%1], 16;" :: "r"(dst), "l"(src));
}
#define CP_COMMIT() asm volatile("cp.async.commit_group;" ::: "memory")
#define CP_WAIT0()  asm volatile("cp.async.wait_group 0;" ::: "memory")
#define CP_WAIT1()  asm volatile("cp.async.wait_group 1;" ::: "memory")

__device__ __forceinline__ void mma_bf16(float* c, const uint32_t* a, uint32_t b0, uint32_t b1) {
    asm volatile(
        "mma.sync.aligned.m16n8k16.row.col.f32.bf16.bf16.f32 "
        "{%0,%1,%2,%3}, {%4,%5,%6,%7}, {%8,%9}, {%0,%1,%2,%3};"
        : "+f"(c[0]), "+f"(c[1]), "+f"(c[2]), "+f"(c[3])
        : "r"(a[0]), "r"(a[1]), "r"(a[2]), "r"(a[3]), "r"(b0), "r"(b1));
}
__device__ __forceinline__ void red2(float* gp, float v0, float v1) {
    asm volatile("red.global.add.v2.f32 [%0], {%1, %2};" :: "l"(gp), "f"(v0), "f"(v1) : "memory");
}
__device__ __forceinline__ void split2(float v0, float v1, uint32_t& hi, uint32_t& lo) {
    __nv_bfloat16 h0 = __float2bfloat16(v0), h1 = __float2bfloat16(v1);
    __nv_bfloat16 l0 = __float2bfloat16(v0 - __bfloat162float(h0));
    __nv_bfloat16 l1 = __float2bfloat16(v1 - __bfloat162float(h1));
    hi = (uint32_t)__bfloat16_as_ushort(h0) | ((uint32_t)__bfloat16_as_ushort(h1) << 16);
    lo = (uint32_t)__bfloat16_as_ushort(l0) | ((uint32_t)__bfloat16_as_ushort(l1) << 16);
}

// pack acc -> hi/lo uint4 with relu + onecol
__device__ __forceinline__ void pack_epi(const float* a0, const float* a1, int slice, int tg,
                                         uint4& hv, uint4& lv) {
    uint32_t ph[4], pl[4];
#pragma unroll
    for (int nh = 0; nh < 2; nh++) {
        const float* a = nh ? a1 : a0;
        float v0 = fmaxf(a[0], 0.f);
        float v1 = fmaxf(a[1], 0.f);
        float v2 = fmaxf(a[2], 0.f);
        float v3 = fmaxf(a[3], 0.f);
        int gc = slice * 16 + nh * 8 + tg * 2;
        if (gc == 150)     { v0 = 1.f; v2 = 1.f; }
        if (gc + 1 == 150) { v1 = 1.f; v3 = 1.f; }
        split2(v0, v1, ph[nh*2],   pl[nh*2]);
        split2(v2, v3, ph[nh*2+1], pl[nh*2+1]);
    }
    hv = make_uint4(ph[0], ph[1], ph[2], ph[3]);
    lv = make_uint4(pl[0], pl[1], pl[2], pl[3]);
}

// ===================== merged weight prep ====================================
struct PrepCfg {
    const float* W; const float* b;
    int din, dout, KD, WSTR, brow, off;
};
struct PrepPack { PrepCfg c[5]; };

__global__ void prep_all(PrepPack p, __nv_bfloat16* __restrict__ wst, int total)
{
    int idx = blockIdx.x * blockDim.x + threadIdx.x;
    if (idx >= total) return;
#pragma unroll
    for (int L = 0; L < 5; L++) {
        int tot = p.c[L].KD * p.c[L].WSTR;
        if (idx < tot) {
            int k = idx / p.c[L].WSTR, n = idx - k * p.c[L].WSTR;
            float v = 0.f;
            if (n < p.c[L].dout) {
                if (k < p.c[L].din) v = p.c[L].W[(size_t)k * p.c[L].dout + n];
                else if (k == p.c[L].brow) v = p.c[L].b[n];
            }
            __nv_bfloat16 h = __float2bfloat16(v);
            __nv_bfloat16 l = __float2bfloat16(v - __bfloat162float(h));
            wst[p.c[L].off + idx] = h;
            wst[p.c[L].off + tot + idx] = l;
            return;
        }
        idx -= tot;
    }
}

// B fragment gather from weight image (ushort layout [KD][WSTR], hi then lo)
__device__ __forceinline__ void wfrag(const ushort* WH, const ushort* WL, int WSTR,
                                      int k0, int slice, int g, int tg,
                                      uint32_t* bh, uint32_t* bl) {
#pragma unroll
    for (int nh = 0; nh < 2; nh++)
#pragma unroll
        for (int r = 0; r < 2; r++) {
            int k = k0 * 16 + tg * 2 + r * 8;
            int n = slice * 16 + nh * 8 + g;
            bh[nh*2+r] = (uint32_t)WH[k*WSTR+n] | ((uint32_t)WH[(k+1)*WSTR+n] << 16);
            bl[nh*2+r] = (uint32_t)WL[k*WSTR+n] | ((uint32_t)WL[(k+1)*WSTR+n] << 16);
        }
}

// ===================== gather ================================================
__global__ void gather_kernel(const float* __restrict__ x,
                              const float* __restrict__ ofx,
                              const int* __restrict__ src,
                              const int* __restrict__ tgt,
                              const float* __restrict__ t,
                              __nv_bfloat16* __restrict__ oh,
                              __nv_bfloat16* __restrict__ ol, int M)
{
    int e = blockIdx.x * blockDim.x + threadIdx.x;
    if (e >= M) return;
    int s = src[e], g = tgt[e];
    float v[16];
    float4 xs = *(const float4*)(x + (size_t)4 * s);
    float2 os = *(const float2*)(ofx + (size_t)2 * s);
    float4 xt = *(const float4*)(x + (size_t)4 * g);
    float2 ot = *(const float2*)(ofx + (size_t)2 * g);
    v[0]=xs.x; v[1]=xs.y; v[2]=xs.z; v[3]=xs.w; v[4]=os.x; v[5]=os.y;
    v[6]=xt.x; v[7]=xt.y; v[8]=xt.z; v[9]=xt.w; v[10]=ot.x; v[11]=ot.y;
    v[12]=t[0]; v[13]=1.0f; v[14]=0.f; v[15]=0.f;
    uint32_t wh[8], wl[8];
#pragma unroll
    for (int i = 0; i < 8; i++) split2(v[2*i], v[2*i+1], wh[i], wl[i]);
    uint4* ph = (uint4*)(oh + (size_t)e * 16);
    uint4* pl = (uint4*)(ol + (size_t)e * 16);
    ph[0] = make_uint4(wh[0], wh[1], wh[2], wh[3]);
    ph[1] = make_uint4(wh[4], wh[5], wh[6], wh[7]);
    pl[0] = make_uint4(wl[0], wl[1], wl[2], wl[3]);
    pl[1] = make_uint4(wl[4], wl[5], wl[6], wl[7]);
}

__global__ void zero_kernel(float* __restrict__ p, int n)
{
    int i = blockIdx.x * blockDim.x + threadIdx.x;
    if (i < n) p[i] = 0.f;
}

// ===================== pair1: L0+L1 fused, 8 warps, reduced regs =============
// B2 split: k0 0..4 in regs (40), k0 5..9 in smem cache RB2 (all 10 slices).
__global__ __launch_bounds__(256, 1)
void pair1_kernel(const __nv_bfloat16* __restrict__ rpH,
                  const __nv_bfloat16* __restrict__ rpL,
                  const __nv_bfloat16* __restrict__ w1img,   // [16][168] hi,lo
                  const __nv_bfloat16* __restrict__ w2img,   // [160][168] hi,lo
                  __nv_bfloat16* __restrict__ outH,
                  __nv_bfloat16* __restrict__ outL,
                  int M)
{
    constexpr int WSTR = 168;
    extern __shared__ unsigned char smem[];
    uint4* INT = (uint4*)smem;                       // 2 bufs x 2560 uint4
    uint4* RB2 = (uint4*)(smem + 81920);             // [10][5][32] hi(1600), lo(+1600)
    uint4* SB2 = (uint4*)(smem + 133120);            // [2][5][32] hi(320), lo(+320)

    const int tid = threadIdx.x, wid = tid >> 5, lane = tid & 31;
    const int g = lane >> 2, tg = lane & 3;
    const int ss = 8 + (wid >> 2);                   // shared slice (8 or 9)
    const int su = wid & 3;                          // shared sub
    const int sc = ss - 8;

    const ushort* W1H = (const ushort*)w1img;
    const ushort* W1L = W1H + 16 * WSTR;
    const ushort* W2H = (const ushort*)w2img;
    const ushort* W2L = W2H + 160 * WSTR;

    // B1 regs: main slice (wid) + shared slice (ss)
    uint32_t b1hm[4], b1lm[4], b1hs[4], b1ls[4];
    wfrag(W1H, W1L, WSTR, 0, wid, g, tg, b1hm, b1lm);
    wfrag(W1H, W1L, WSTR, 0, ss,  g, tg, b1hs, b1ls);

    // B2 regs: main slice, k0 0..4 only
    uint32_t pbh[5][4], pbl[5][4];
#pragma unroll
    for (int k0 = 0; k0 < 5; k0++)
        wfrag(W2H, W2L, WSTR, k0, wid, g, tg, pbh[k0], pbl[k0]);

    // RB2 cache: all 10 slices, k0 5..9 (warp w builds slices w, w+8)
    for (int s = wid; s < 10; s += 8) {
        for (int k0 = 5; k0 < 10; k0++) {
            uint32_t bh[4], bl[4];
            wfrag(W2H, W2L, WSTR, k0, s, g, tg, bh, bl);
            RB2[(s*5 + k0 - 5)*32 + lane]        = make_uint4(bh[0], bh[1], bh[2], bh[3]);
            RB2[1600 + (s*5 + k0 - 5)*32 + lane] = make_uint4(bl[0], bl[1], bl[2], bl[3]);
        }
    }
    // SB2 cache: slices 8,9 k0 0..4 (warps 0,1)
    if (wid < 2) {
        int slice = 8 + wid;
        for (int k0 = 0; k0 < 5; k0++) {
            uint32_t bh[4], bl[4];
            wfrag(W2H, W2L, WSTR, k0, slice, g, tg, bh, bl);
            SB2[(wid*5 + k0)*32 + lane]       = make_uint4(bh[0], bh[1], bh[2], bh[3]);
            SB2[320 + (wid*5 + k0)*32 + lane] = make_uint4(bl[0], bl[1], bl[2], bl[3]);
        }
    }
    __syncthreads();

    const int ntiles = (M + 63) >> 6;

    uint32_t pAH[4][4], pAL[4][4];   // A frags for all 4 subs
    auto loadA = [&](int tile) {
        const int row0 = tile << 6;
#pragma unroll
        for (int sub = 0; sub < 4; sub++) {
            int r0 = row0 + sub * 16 + g;
            int r1 = r0 + 8;
            if (r0 > M - 1) r0 = M - 1;
            if (r1 > M - 1) r1 = M - 1;
            const __nv_bfloat16* h0p = rpH + (size_t)r0 * 16 + tg * 2;
            const __nv_bfloat16* h1p = rpH + (size_t)r1 * 16 + tg * 2;
            const __nv_bfloat16* l0p = rpL + (size_t)r0 * 16 + tg * 2;
            const __nv_bfloat16* l1p = rpL + (size_t)r1 * 16 + tg * 2;
            pAH[sub][0] = *(const uint32_t*)h0p;
            pAH[sub][1] = *(const uint32_t*)h1p;
            pAH[sub][2] = *(const uint32_t*)(h0p + 8);
            pAH[sub][3] = *(const uint32_t*)(h1p + 8);
            pAL[sub][0] = *(const uint32_t*)l0p;
            pAL[sub][1] = *(const uint32_t*)l1p;
            pAL[sub][2] = *(const uint32_t*)(l0p + 8);
            pAL[sub][3] = *(const uint32_t*)(l1p + 8);
        }
    };

    auto g1 = [&](int buf) {
        uint4* ih = INT + buf * 2560;
#pragma unroll
        for (int sub = 0; sub < 4; sub++) {
            float acc[2][4] = {};
            mma_bf16(acc[0], pAH[sub], b1hm[0], b1hm[1]);
            mma_bf16(acc[0], pAH[sub], b1lm[0], b1lm[1]);
            mma_bf16(acc[0], pAL[sub], b1hm[0], b1hm[1]);
            mma_bf16(acc[1], pAH[sub], b1hm[2], b1hm[3]);
            mma_bf16(acc[1], pAH[sub], b1lm[2], b1lm[3]);
            mma_bf16(acc[1], pAL[sub], b1hm[2], b1hm[3]);
            uint4 hv, lv;
            pack_epi(acc[0], acc[1], wid, tg, hv, lv);
            ih[(wid*4 + sub)*32 + lane]        = hv;
            ih[1280 + (wid*4 + sub)*32 + lane] = lv;
        }
        {   // shared unit (slice ss, sub su)
            float acc[2][4] = {};
            mma_bf16(acc[0], pAH[su], b1hs[0], b1hs[1]);
            mma_bf16(acc[0], pAH[su], b1ls[0], b1ls[1]);
            mma_bf16(acc[0], pAL[su], b1hs[0], b1hs[1]);
            mma_bf16(acc[1], pAH[su], b1hs[2], b1hs[3]);
            mma_bf16(acc[1], pAH[su], b1ls[2], b1ls[3]);
            mma_bf16(acc[1], pAL[su], b1hs[2], b1hs[3]);
            uint4 hv, lv;
            pack_epi(acc[0], acc[1], ss, tg, hv, lv);
            ih[(ss*4 + su)*32 + lane]        = hv;
            ih[1280 + (ss*4 + su)*32 + lane] = lv;
        }
    };

    auto g2 = [&](int tile, int buf) {
        const uint4* ip = INT + buf * 2560;
        uint4* oh = (uint4*)outH;
        uint4* ol = (uint4*)outL;
#pragma unroll
        for (int sub = 0; sub < 4; sub++) {
            float acc[2][4] = {};
#pragma unroll
            for (int k0 = 0; k0 < 5; k0++) {
                uint4 a4 = ip[(k0*4 + sub)*32 + lane];
                uint4 b4 = ip[1280 + (k0*4 + sub)*32 + lane];
                uint32_t aH[4] = {a4.x, a4.y, a4.z, a4.w};
                uint32_t aL[4] = {b4.x, b4.y, b4.z, b4.w};
                mma_bf16(acc[0], aH, pbh[k0][0], pbh[k0][1]);
                mma_bf16(acc[0], aH, pbl[k0][0], pbl[k0][1]);
                mma_bf16(acc[0], aL, pbh[k0][0], pbh[k0][1]);
                mma_bf16(acc[1], aH, pbh[k0][2], pbh[k0][3]);
                mma_bf16(acc[1], aH, pbl[k0][2], pbl[k0][3]);
                mma_bf16(acc[1], aL, pbh[k0][2], pbh[k0][3]);
            }
#pragma unroll
            for (int k0 = 5; k0 < 10; k0++) {
                uint4 a4 = ip[(k0*4 + sub)*32 + lane];
                uint4 b4 = ip[1280 + (k0*4 + sub)*32 + lane];
                uint32_t aH[4] = {a4.x, a4.y, a4.z, a4.w};
                uint32_t aL[4] = {b4.x, b4.y, b4.z, b4.w};
                uint4 h4 = RB2[(wid*5 + k0 - 5)*32 + lane];
                uint4 l4 = RB2[1600 + (wid*5 + k0 - 5)*32 + lane];
                mma_bf16(acc[0], aH, h4.x, h4.y);
                mma_bf16(acc[0], aH, l4.x, l4.y);
                mma_bf16(acc[0], aL, h4.x, h4.y);
                mma_bf16(acc[1], aH, h4.z, h4.w);
                mma_bf16(acc[1], aH, l4.z, l4.w);
                mma_bf16(acc[1], aL, h4.z, h4.w);
            }
            uint4 hv, lv;
            pack_epi(acc[0], acc[1], wid, tg, hv, lv);
            size_t base = ((size_t)tile * 40 + wid * 4 + sub) * 32 + lane;
            oh[base] = hv;
            ol[base] = lv;
        }
        {   // shared unit
            float acc[2][4] = {};
#pragma unroll
            for (int k0 = 0; k0 < 5; k0++) {
                uint4 a4 = ip[(k0*4 + su)*32 + lane];
                uint4 b4 = ip[1280 + (k0*4 + su)*32 + lane];
                uint32_t aH[4] = {a4.x, a4.y, a4.z, a4.w};
                uint32_t aL[4] = {b4.x, b4.y, b4.z, b4.w};
                uint4 h4 = SB2[(sc*5 + k0)*32 + lane];
                uint4 l4 = SB2[320 + (sc*5 + k0)*32 + lane];
                mma_bf16(acc[0], aH, h4.x, h4.y);
                mma_bf16(acc[0], aH, l4.x, l4.y);
                mma_bf16(acc[0], aL, h4.x, h4.y);
                mma_bf16(acc[1], aH, h4.z, h4.w);
                mma_bf16(acc[1], aH, l4.z, l4.w);
                mma_bf16(acc[1], aL, h4.z, h4.w);
            }
#pragma unroll
            for (int k0 = 5; k0 < 10; k0++) {
                uint4 a4 = ip[(k0*4 + su)*32 + lane];
                uint4 b4 = ip[1280 + (k0*4 + su)*32 + lane];
                uint32_t aH[4] = {a4.x, a4.y, a4.z, a4.w};
                uint32_t aL[4] = {b4.x, b4.y, b4.z, b4.w};
                uint4 h4 = RB2[(ss*5 + k0 - 5)*32 + lane];
                uint4 l4 = RB2[1600 + (ss*5 + k0 - 5)*32 + lane];
                mma_bf16(acc[0], aH, h4.x, h4.y);
                mma_bf16(acc[0], aH, l4.x, l4.y);
                mma_bf16(acc[0], aL, h4.x, h4.y);
                mma_bf16(acc[1], aH, h4.z, h4.w);
                mma_bf16(acc[1], aH, l4.z, l4.w);
                mma_bf16(acc[1], aL, h4.z, h4.w);
            }
            uint4 hv, lv;
            pack_epi(acc[0], acc[1], ss, tg, hv, lv);
            size_t base = ((size_t)tile * 40 + ss * 4 + su) * 32 + lane;
            oh[base] = hv;
            ol[base] = lv;
        }
    };

    int t = blockIdx.x;
    if (t < ntiles) { loadA(t); g1(0); }
    int i = 0;
    for (; t < ntiles; t += gridDim.x, i++) {
        int nxt = t + gridDim.x;
        if (nxt < ntiles) loadA(nxt);
        __syncthreads();
        g2(t, i & 1);
        if (nxt < ntiles) g1((i + 1) & 1);
    }
}

// ===================== pair2: L2+L3, 8 warps balanced ========================
__global__ __launch_bounds__(256, 1)
void pair2_kernel(const __nv_bfloat16* __restrict__ inH,
                  const __nv_bfloat16* __restrict__ inL,
                  const __nv_bfloat16* __restrict__ w1img,
                  const __nv_bfloat16* __restrict__ w2img,
                  __nv_bfloat16* __restrict__ outH,
                  __nv_bfloat16* __restrict__ outL,
                  int M)
{
    constexpr int THREADS = 256, KT = 10, WSTR = 168;
    constexpr int S1 = 10 * KT * 512;              // 51200 B per plane
    constexpr int OFF_SB2 = 2 * S1;                // 20480 B
    constexpr int OFF_A = OFF_SB2 + 20480;         // 40960 B
    constexpr int OFF_INT = OFF_A + 40960;         // 40960 B

    extern __shared__ unsigned char smem[];
    const uint32_t sbu = smem_u32(smem);
    const int tid = threadIdx.x, wid = tid >> 5, lane = tid & 31;
    const int g = lane >> 2, tg = lane & 3;
    const int ss = 8 + (wid >> 2), su = wid & 3;

    const ushort* W1H = (const ushort*)w1img;
    const ushort* W1L = W1H + 160 * WSTR;
    const ushort* W2H = (const ushort*)w2img;
    const ushort* W2L = W2H + 160 * WSTR;

    {
        uint4* ch = (uint4*)(smem);
        uint4* cl = (uint4*)(smem + S1);
        for (int s = wid; s < 10; s += 8) {
            for (int k0 = 0; k0 < KT; k0++) {
                uint32_t bh[4], bl[4];
                wfrag(W1H, W1L, WSTR, k0, s, g, tg, bh, bl);
                ch[(s*KT + k0)*32 + lane] = make_uint4(bh[0], bh[1], bh[2], bh[3]);
                cl[(s*KT + k0)*32 + lane] = make_uint4(bl[0], bl[1], bl[2], bl[3]);
            }
        }
    }
    if (wid < 2) {
        uint4* sb = (uint4*)(smem + OFF_SB2);
        int slice = 8 + wid;
        for (int k0 = 0; k0 < KT; k0++) {
            uint32_t bh[4], bl[4];
            wfrag(W2H, W2L, WSTR, k0, slice, g, tg, bh, bl);
            sb[(wid*KT + k0)*32 + lane]       = make_uint4(bh[0], bh[1], bh[2], bh[3]);
            sb[640 + (wid*KT + k0)*32 + lane] = make_uint4(bl[0], bl[1], bl[2], bl[3]);
        }
    }
    uint32_t pbh[KT][4], pbl[KT][4];
#pragma unroll
    for (int k0 = 0; k0 < KT; k0++)
        wfrag(W2H, W2L, WSTR, k0, wid, g, tg, pbh[k0], pbl[k0]);
    __syncthreads();

    const uint4* c1h = (const uint4*)(smem);
    const uint4* c1l = (const uint4*)(smem + S1);
    const uint4* sb2 = (const uint4*)(smem + OFF_SB2);
    const int ntiles = (M + 63) >> 6;

    auto stage = [&](int tile) {
        const uint4* hp = (const uint4*)inH;
        const uint4* lp = (const uint4*)inL;
        for (int i = tid; i < 2560; i += THREADS) {
            int plane = i / 1280, off = i - plane * 1280;
            const uint4* s = (plane ? lp : hp) + (size_t)tile * 1280 + off;
            cpa16(sbu + OFF_A + plane * 20480 + off * 16, s);
        }
        CP_COMMIT();
    };

    int tile = blockIdx.x;
    if (tile < ntiles) stage(tile);

    for (; tile < ntiles; tile += gridDim.x) {
        CP_WAIT0();
        __syncthreads();

        {
            const uint4* ap = (const uint4*)(smem + OFF_A);
            float acc[4][2][4] = {};
#pragma unroll
            for (int k0 = 0; k0 < KT; k0++) {
                uint4 h4 = c1h[(wid*KT + k0)*32 + lane];
                uint4 l4 = c1l[(wid*KT + k0)*32 + lane];
#pragma unroll
                for (int sub = 0; sub < 4; sub++) {
                    uint4 a4 = ap[(k0*4 + sub)*32 + lane];
                    uint4 b4 = ap[1280 + (k0*4 + sub)*32 + lane];
                    uint32_t aH[4] = {a4.x, a4.y, a4.z, a4.w};
                    uint32_t aL[4] = {b4.x, b4.y, b4.z, b4.w};
                    mma_bf16(acc[sub][0], aH, h4.x, h4.y);
                    mma_bf16(acc[sub][0], aH, l4.x, l4.y);
                    mma_bf16(acc[sub][0], aL, h4.x, h4.y);
                    mma_bf16(acc[sub][1], aH, h4.z, h4.w);
                    mma_bf16(acc[sub][1], aH, l4.z, l4.w);
                    mma_bf16(acc[sub][1], aL, h4.z, h4.w);
                }
            }
            uint4* ih = (uint4*)(smem + OFF_INT);
#pragma unroll
            for (int sub = 0; sub < 4; sub++) {
                uint4 hv, lv;
                pack_epi(acc[sub][0], acc[sub][1], wid, tg, hv, lv);
                ih[(wid*4 + sub)*32 + lane]        = hv;
                ih[1280 + (wid*4 + sub)*32 + lane] = lv;
            }
        }
        {
            const uint4* ap = (const uint4*)(smem + OFF_A);
            float acc[2][4] = {};
#pragma unroll
            for (int k0 = 0; k0 < KT; k0++) {
                uint4 h4 = c1h[(ss*KT + k0)*32 + lane];
                uint4 l4 = c1l[(ss*KT + k0)*32 + lane];
                uint4 a4 = ap[(k0*4 + su)*32 + lane];
                uint4 b4 = ap[1280 + (k0*4 + su)*32 + lane];
                uint32_t aH[4] = {a4.x, a4.y, a4.z, a4.w};
                uint32_t aL[4] = {b4.x, b4.y, b4.z, b4.w};
                mma_bf16(acc[0], aH, h4.x, h4.y);
                mma_bf16(acc[0], aH, l4.x, l4.y);
                mma_bf16(acc[0], aL, h4.x, h4.y);
                mma_bf16(acc[1], aH, h4.z, h4.w);
                mma_bf16(acc[1], aH, l4.z, l4.w);
                mma_bf16(acc[1], aL, h4.z, h4.w);
            }
            uint4* ih = (uint4*)(smem + OFF_INT);
            uint4 hv, lv;
            pack_epi(acc[0], acc[1], ss, tg, hv, lv);
            ih[(ss*4 + su)*32 + lane]        = hv;
            ih[1280 + (ss*4 + su)*32 + lane] = lv;
        }
        __syncthreads();

        int nxt = tile + gridDim.x;
        if (nxt < ntiles) stage(nxt);

        const uint4* ip = (const uint4*)(smem + OFF_INT);
        uint4* oh = (uint4*)outH;
        uint4* ol = (uint4*)outL;
#pragma unroll
        for (int sub = 0; sub < 4; sub++) {
            float acc[2][4] = {};
#pragma unroll
            for (int k0 = 0; k0 < KT; k0++) {
                uint4 a4 = ip[(k0*4 + sub)*32 + lane];
                uint4 b4 = ip[1280 + (k0*4 + sub)*32 + lane];
                uint32_t aH[4] = {a4.x, a4.y, a4.z, a4.w};
                uint32_t aL[4] = {b4.x, b4.y, b4.z, b4.w};
                mma_bf16(acc[0], aH, pbh[k0][0], pbh[k0][1]);
                mma_bf16(acc[0], aH, pbl[k0][0], pbl[k0][1]);
                mma_bf16(acc[0], aL, pbh[k0][0], pbh[k0][1]);
                mma_bf16(acc[1], aH, pbh[k0][2], pbh[k0][3]);
                mma_bf16(acc[1], aH, pbl[k0][2], pbl[k0][3]);
                mma_bf16(acc[1], aL, pbh[k0][2], pbh[k0][3]);
            }
            uint4 hv, lv;
            pack_epi(acc[0], acc[1], wid, tg, hv, lv);
            size_t base = ((size_t)tile * 40 + wid * 4 + sub) * 32 + lane;
            oh[base] = hv;
            ol[base] = lv;
        }
        {
            float acc[2][4] = {};
            const int sc = ss - 8;
#pragma unroll
            for (int k0 = 0; k0 < KT; k0++) {
                uint4 a4 = ip[(k0*4 + su)*32 + lane];
                uint4 b4 = ip[1280 + (k0*4 + su)*32 + lane];
                uint32_t aH[4] = {a4.x, a4.y, a4.z, a4.w};
                uint32_t aL[4] = {b4.x, b4.y, b4.z, b4.w};
                uint4 h4 = sb2[(sc*KT + k0)*32 + lane];
                uint4 l4 = sb2[640 + (sc*KT + k0)*32 + lane];
                mma_bf16(acc[0], aH, h4.x, h4.y);
                mma_bf16(acc[0], aH, l4.x, l4.y);
                mma_bf16(acc[0], aL, h4.x, h4.y);
                mma_bf16(acc[1], aH, h4.z, h4.w);
                mma_bf16(acc[1], aH, l4.z, l4.w);
                mma_bf16(acc[1], aL, h4.z, h4.w);
            }
            uint4 hv, lv;
            pack_epi(acc[0], acc[1], ss, tg, hv, lv);
            size_t base = ((size_t)tile * 40 + ss * 4 + su) * 32 + lane;
            oh[base] = hv;
            ol[base] = lv;
        }
        __syncthreads();
    }
}

// ===================== final layer + fused segment-sum (16 warps) ============
__global__ __launch_bounds__(512, 1)
void layer_atomic(const __nv_bfloat16* __restrict__ inH,
                  const __nv_bfloat16* __restrict__ inL,
                  const __nv_bfloat16* __restrict__ wimg,   // [160][72] hi,lo
                  const int* __restrict__ tgt,
                  float* __restrict__ ep,
                  int M)
{
    constexpr int THREADS = 512, KT = 10, WSTR = 72;
    constexpr int SLOT = 40960;

    extern __shared__ unsigned char smem[];
    const uint32_t sbu = smem_u32(smem);
    const int tid = threadIdx.x, wid = tid >> 5, lane = tid & 31;
    const int g = lane >> 2, tg = lane & 3;
    const int warp_n = wid & 3, sub = wid >> 2;

    uint32_t pbh[KT][4], pbl[KT][4];
    {
        const ushort* WH = (const ushort*)wimg;
        const ushort* WL = WH + 160 * WSTR;
#pragma unroll
        for (int k0 = 0; k0 < KT; k0++)
            wfrag(WH, WL, WSTR, k0, warp_n, g, tg, pbh[k0], pbl[k0]);
    }

    const int ntiles = (M + 63) >> 6;
    const uint4* hp = (const uint4*)inH;
    const uint4* lp = (const uint4*)inL;

    auto stage = [&](int slot, int tile) {
        if (tile < ntiles) {
            for (int i = tid; i < 2560; i += THREADS) {
                int plane = i / 1280, off = i - plane * 1280;
                const uint4* s = (plane ? lp : hp) + (size_t)tile * 1280 + off;
                cpa16(sbu + slot * SLOT + plane * 20480 + off * 16, s);
            }
        }
        CP_COMMIT();
    };

    int t0 = blockIdx.x;
    stage(0, t0);
    stage(1, t0 + gridDim.x);

    int i = 0;
    for (int t = t0; t < ntiles; t += gridDim.x, i++) {
        CP_WAIT1();
        __syncthreads();
        stage((i + 2) % 3, t + 2 * gridDim.x);

        const uint4* ap = (const uint4*)(smem + (i % 3) * SLOT);
        const size_t row0 = (size_t)t << 6;

        float acc[2][4] = {};
#pragma unroll
        for (int k0 = 0; k0 < KT; k0++) {
            uint4 a4 = ap[(k0*4 + sub)*32 + lane];
            uint4 b4 = ap[1280 + (k0*4 + sub)*32 + lane];
            uint32_t aH[4] = {a4.x, a4.y, a4.z, a4.w};
            uint32_t aL[4] = {b4.x, b4.y, b4.z, b4.w};
            mma_bf16(acc[0], aH, pbh[k0][0], pbh[k0][1]);
            mma_bf16(acc[0], aH, pbl[k0][0], pbl[k0][1]);
            mma_bf16(acc[0], aL, pbh[k0][0], pbh[k0][1]);
            mma_bf16(acc[1], aH, pbh[k0][2], pbh[k0][3]);
            mma_bf16(acc[1], aH, pbl[k0][2], pbl[k0][3]);
            mma_bf16(acc[1], aL, pbh[k0][2], pbh[k0][3]);
        }
        size_t gr0 = row0 + sub * 16 + g;
        size_t gr1 = gr0 + 8;
        int t0i = (gr0 < (size_t)M) ? __ldg(tgt + gr0) : -1;
        int t1i = (gr1 < (size_t)M) ? __ldg(tgt + gr1) : -1;
#pragma unroll
        for (int nh = 0; nh < 2; nh++) {
            int gc = warp_n * 16 + nh * 8 + tg * 2;
            if (gc < 50) {
                if (t0i >= 0) red2(ep + (size_t)t0i * 64 + gc, acc[nh][0], acc[nh][1]);
                if (t1i >= 0) red2(ep + (size_t)t1i * 64 + gc, acc[nh][2], acc[nh][3]);
            }
        }
    }
}

// ===================== SIMT GEMM (node MLP) =================================
template <int NS>
__global__ __launch_bounds__(256, 2)
void gemm_kernel(const float* __restrict__ A, int lda,
                 const float* __restrict__ W, const float* __restrict__ B,
                 float* __restrict__ C, int ldc,
                 int M, int din, int dout, int relu, int padstore)
{
    constexpr int PN = NS * 32;
    extern __shared__ float sm[];
    float* Ws = sm;
    float* Bs = Ws + ((din + 3) & ~3) * PN;
    const int tid = threadIdx.x;
    const int din4 = (din + 3) & ~3;
    for (int idx = tid; idx < din4 * PN; idx += 256) {
        int k = idx / PN, j = idx - k * PN;
        Ws[idx] = (k < din && j < dout) ? W[(size_t)k * dout + j] : 0.f;
    }
    for (int j = tid; j < PN; j += 256) Bs[j] = (j < dout) ? B[j] : 0.f;
    __syncthreads();
    const int lane = tid & 31;
    const int gwarp = blockIdx.x * 8 + (tid >> 5);
    const int nwarp = gridDim.x * 8;
    for (int sidx = gwarp; sidx < (M + 7) >> 3; sidx += nwarp) {
        const int row0 = sidx << 3;
        const float* ap[8];
#pragma unroll
        for (int r = 0; r < 8; r++) {
            int rr = row0 + r; if (rr > M - 1) rr = M - 1;
            ap[r] = A + (size_t)rr * lda;
        }
        float acc[8][NS];
#pragma unroll
        for (int r = 0; r < 8; r++)
#pragma unroll
            for (int s = 0; s < NS; s++) acc[r][s] = 0.f;
#pragma unroll 2
        for (int k = 0; k < din4; k += 4) {
            float4 a[8];
#pragma unroll
            for (int r = 0; r < 8; r++) a[r] = *(const float4*)(ap[r] + k);
#pragma unroll
            for (int kk = 0; kk < 4; kk++) {
                float wv[NS];
#pragma unroll
                for (int s = 0; s < NS; s++) wv[s] = Ws[(k + kk) * PN + lane + (s << 5)];
#pragma unroll
                for (int r = 0; r < 8; r++) {
                    float av = (kk == 0) ? a[r].x : (kk == 1) ? a[r].y : (kk == 2) ? a[r].z : a[r].w;
#pragma unroll
                    for (int s = 0; s < NS; s++) acc[r][s] = fmaf(av, wv[s], acc[r][s]);
                }
            }
        }
#pragma unroll
        for (int r = 0; r < 8; r++) {
            int row = row0 + r;
            if (row < M) {
#pragma unroll
                for (int s = 0; s < NS; s++) {
                    int j = lane + (s << 5);
                    float v = acc[r][s] + Bs[j];
                    if (relu) v = fmaxf(v, 0.f);
                    if (padstore || j < dout) C[(size_t)row * ldc + j] = v;
                }
            }
        }
    }
}

// ===================== host ==================================================
static inline size_t smbytes(int din, int PN)
{
    int din4 = (din + 3) & ~3;
    return (size_t)(din4 * PN + PN) * sizeof(float);
}

extern "C" void kernel_launch(void* const* d_in, const int* in_sizes, int n_in,
                              void* d_out, int out_size)
{
    const float* t   = (const float*)d_in[0];
    const float* x   = (const float*)d_in[1];
    const float* ofx = (const float*)d_in[2];
    const int* src   = (const int*)d_in[3];
    const int* tgt   = (const int*)d_in[4];
    const float* RW[5] = {(const float*)d_in[5], (const float*)d_in[7], (const float*)d_in[9],
                          (const float*)d_in[11], (const float*)d_in[13]};
    const float* Rb[5] = {(const float*)d_in[6], (const float*)d_in[8], (const float*)d_in[10],
                          (const float*)d_in[12], (const float*)d_in[14]};
    const float* OW0 = (const float*)d_in[15];
    const float* Ob0 = (const float*)d_in[16];
    const float* OW1 = (const float*)d_in[17];
    const float* Ob1 = (const float*)d_in[18];
    float* out = (float*)d_out;

    const int M = in_sizes[3];
    const int N = in_sizes[1] / 4;

    __nv_bfloat16 *rpH, *rpL, *Xh, *Xl, *Yh, *Yl, *wst;
    float* ep;
    cudaGetSymbolAddress((void**)&rpH, g_rpH);
    cudaGetSymbolAddress((void**)&rpL, g_rpL);
    cudaGetSymbolAddress((void**)&Xh,  g_Xh);
    cudaGetSymbolAddress((void**)&Xl,  g_Xl);
    cudaGetSymbolAddress((void**)&Yh,  g_Yh);
    cudaGetSymbolAddress((void**)&Yl,  g_Yl);
    cudaGetSymbolAddress((void**)&ep,  g_eprime);
    cudaGetSymbolAddress((void**)&wst, g_wstage);

    int nsm = 148;
    cudaDeviceGetAttribute(&nsm, cudaDevAttrMultiProcessorCount, 0);

    const int woff[5] = {0, 5376, 59136, 112896, 166656};
    const int wdin[5]  = {13, 150, 150, 150, 150};
    const int wdout[5] = {150, 150, 150, 150, 50};
    const int wKD[5]   = {16, 160, 160, 160, 160};
    const int wWSTR[5] = {168, 168, 168, 168, 72};
    const int wbrow[5] = {13, 150, 150, 150, 150};
    PrepPack pk;
    int ptotal = 0;
    for (int i = 0; i < 5; i++) {
        pk.c[i] = PrepCfg{RW[i], Rb[i], wdin[i], wdout[i], wKD[i], wWSTR[i], wbrow[i], woff[i]};
        ptotal += wKD[i] * wWSTR[i];
    }
    prep_all<<<(ptotal + 255) / 256, 256>>>(pk, wst, ptotal);

    zero_kernel<<<(N * 64 + 255) / 256, 256>>>(ep, N * 64);
    gather_kernel<<<(M + 255) / 256, 256>>>(x, ofx, src, tgt, t, rpH, rpL, M);

    const int sm01 = 81920 + 51200 + 10240;                 // 143360
    const int sm23 = 2*51200 + 20480 + 40960 + 40960;       // 204800
    const int sm4  = 3 * 40960;                             // 122880
    cudaFuncSetAttribute(pair1_kernel, cudaFuncAttributeMaxDynamicSharedMemorySize, sm01);
    cudaFuncSetAttribute(pair2_kernel, cudaFuncAttributeMaxDynamicSharedMemorySize, sm23);
    cudaFuncSetAttribute(layer_atomic, cudaFuncAttributeMaxDynamicSharedMemorySize, sm4);

    pair1_kernel<<<nsm, 256, sm01>>>(rpH, rpL, wst + woff[0], wst + woff[1], Xh, Xl, M);
    pair2_kernel<<<nsm, 256, sm23>>>(Xh, Xl, wst + woff[2], wst + woff[3], Yh, Yl, M);
    layer_atomic<<<nsm, 512, sm4>>>(Yh, Yl, wst + woff[4], tgt, ep, M);

    cudaFuncSetAttribute(gemm_kernel<4>, cudaFuncAttributeMaxDynamicSharedMemorySize, 112 * 1024);
    cudaFuncSetAttribute(gemm_kernel<1>, cudaFuncAttributeMaxDynamicSharedMemorySize, 112 * 1024);
    float* nb = (float*)rpH;
    gemm_kernel<4><<<2 * nsm, 256, smbytes(50, 128)>>>(ep, 64, OW0, Ob0, nb, 128, N, 50, 100, 1, 1);
    gemm_kernel<1><<<2 * nsm, 256, smbytes(100, 32)>>>(nb, 128, OW1, Ob1, out, 4, N, 100, 4, 0, 0);
}